// round 4
// baseline (speedup 1.0000x reference)
#include <cuda_runtime.h>
#include <cuda_bf16.h>
#include <cstdint>
#include <math.h>

// Problem constants
#define TB 32      // batch
#define TS 512     // seq len
#define TE 512     // d_model
#define THD 64     // head dim
#define TNH 8      // heads
#define TL 3       // layers
#define TT (TB*TS) // tokens = 16384
#define QKVW 1536  // 3*E

// Scratch (device globals; allocation-free contract)
__device__ float g_x[(size_t)TT * TE];       // running hidden   32 MB
__device__ float g_qkv[(size_t)TT * QKVW];   // qkv              96 MB
__device__ float g_att[(size_t)TT * TE];     // attn concat out  32 MB
__device__ float g_y[(size_t)TT * TE];       // gemm out         32 MB
__device__ float g_h[(size_t)TT * 4 * TE];   // ffn hidden      128 MB

#define MMA_TF32(d, a, b)                                                     \
    asm volatile(                                                             \
        "mma.sync.aligned.m16n8k8.row.col.f32.tf32.tf32.f32 "                 \
        "{%0,%1,%2,%3}, {%4,%5,%6,%7}, {%8,%9}, {%0,%1,%2,%3};"               \
        : "+f"(d[0]), "+f"(d[1]), "+f"(d[2]), "+f"(d[3])                      \
        : "r"(a[0]), "r"(a[1]), "r"(a[2]), "r"(a[3]), "r"(b[0]), "r"(b[1]))

__device__ __forceinline__ void cpa16(uint32_t s, const void* g) {
    asm volatile("cp.async.cg.shared.global [%0], [%1], 16;" :: "r"(s), "l"(g));
}
__device__ __forceinline__ void cpa_commit() {
    asm volatile("cp.async.commit_group;");
}

// ---------------------------------------------------------------------------
// Embedding: x[t] = emb[ids[t]] + pos[t % S]
// ---------------------------------------------------------------------------
__global__ __launch_bounds__(256) void embed_kernel(
    const int* __restrict__ ids, const float* __restrict__ emb,
    const float* __restrict__ pos, float* __restrict__ x) {
    int idx = blockIdx.x * blockDim.x + threadIdx.x;
    int token = idx >> 7;
    int c = idx & 127;
    float4 e = reinterpret_cast<const float4*>(emb)[(size_t)ids[token] * 128 + c];
    float4 p = reinterpret_cast<const float4*>(pos)[(size_t)(token & (TS - 1)) * 128 + c];
    float4 o;
    o.x = e.x + p.x; o.y = e.y + p.y; o.z = e.z + p.z; o.w = e.w + p.w;
    reinterpret_cast<float4*>(x)[idx] = o;
}

// ---------------------------------------------------------------------------
// TF32 tensor-core GEMM v2: C[M,N] = A[M,K] @ W[N,K]^T + bias[N], opt GELU.
// Block 128x128, ktile 32, 256 threads, warp tile 64x32.
// cp.async double-buffered; raw fp32 bits fed to tf32 mma (rz rounding).
// Dynamic smem: 2 stages x (A+W) x 128x36 words = 73728 B.
// ---------------------------------------------------------------------------
#define SPITCH 36
#define TG_WORDS (128 * SPITCH)
#define TG_SMEM (4 * TG_WORDS * 4)

template <int ACT>
__global__ __launch_bounds__(256, 2) void tgemm_kernel(
    const float* __restrict__ A, const float* __restrict__ W,
    const float* __restrict__ bias, float* __restrict__ C,
    int N, int K) {
    extern __shared__ uint32_t sm[];
    uint32_t* bufA[2] = { sm, sm + 2 * TG_WORDS };
    uint32_t* bufW[2] = { sm + TG_WORDS, sm + 3 * TG_WORDS };
    const uint32_t smBase = (uint32_t)__cvta_generic_to_shared(sm);

    const int t = threadIdx.x;
    const int lane = t & 31;
    const int warp = t >> 5;
    const int wr = (warp >> 2) * 64;
    const int wc = (warp & 3) * 32;
    const int qr = lane >> 2;
    const int qc = lane & 3;

    const int m0 = blockIdx.y * 128;
    const int n0 = blockIdx.x * 128;
    const int KT = K >> 5;

    // per-thread copy coordinates (4 16B segments per matrix per tile)
    const int crow = t >> 1;              // rows covered with i-stride: f4 = t+256i
    (void)crow;

    float acc[4][4][4];
#pragma unroll
    for (int i = 0; i < 4; i++)
#pragma unroll
        for (int j = 0; j < 4; j++)
#pragma unroll
            for (int r = 0; r < 4; r++) acc[i][j][r] = 0.f;

    // prologue: issue tiles 0 and 1
#pragma unroll
    for (int s = 0; s < 2; s++) {
        if (s < KT) {
            uint32_t aoff = smBase + (uint32_t)((2 * s) * TG_WORDS) * 4;
            uint32_t woff = smBase + (uint32_t)((2 * s + 1) * TG_WORDS) * 4;
#pragma unroll
            for (int i = 0; i < 4; i++) {
                int f4 = t + 256 * i;
                int row = f4 >> 3, kq = (f4 & 7) * 4;
                cpa16(aoff + (uint32_t)(row * SPITCH + kq) * 4,
                      A + (size_t)(m0 + row) * K + s * 32 + kq);
                cpa16(woff + (uint32_t)(row * SPITCH + kq) * 4,
                      W + (size_t)(n0 + row) * K + s * 32 + kq);
            }
        }
        cpa_commit();
    }

    for (int kt = 0; kt < KT; kt++) {
        if (kt + 1 < KT)
            asm volatile("cp.async.wait_group 1;");
        else
            asm volatile("cp.async.wait_group 0;");
        __syncthreads();

        const uint32_t* As = bufA[kt & 1];
        const uint32_t* Ws = bufW[kt & 1];
#pragma unroll
        for (int kk = 0; kk < 32; kk += 8) {
            uint32_t a[4][4], b[4][2];
#pragma unroll
            for (int mi = 0; mi < 4; mi++) {
                const uint32_t* base = &As[(wr + mi * 16 + qr) * SPITCH + kk + qc];
                a[mi][0] = base[0];
                a[mi][1] = base[8 * SPITCH];
                a[mi][2] = base[4];
                a[mi][3] = base[8 * SPITCH + 4];
            }
#pragma unroll
            for (int ni = 0; ni < 4; ni++) {
                const uint32_t* base = &Ws[(wc + ni * 8 + qr) * SPITCH + kk + qc];
                b[ni][0] = base[0];
                b[ni][1] = base[4];
            }
#pragma unroll
            for (int mi = 0; mi < 4; mi++)
#pragma unroll
                for (int ni = 0; ni < 4; ni++) MMA_TF32(acc[mi][ni], a[mi], b[ni]);
        }
        __syncthreads();

        if (kt + 2 < KT) {
            int s = kt + 2;
            uint32_t aoff = smBase + (uint32_t)((2 * (s & 1)) * TG_WORDS) * 4;
            uint32_t woff = smBase + (uint32_t)((2 * (s & 1) + 1) * TG_WORDS) * 4;
#pragma unroll
            for (int i = 0; i < 4; i++) {
                int f4 = t + 256 * i;
                int row = f4 >> 3, kq = (f4 & 7) * 4;
                cpa16(aoff + (uint32_t)(row * SPITCH + kq) * 4,
                      A + (size_t)(m0 + row) * K + s * 32 + kq);
                cpa16(woff + (uint32_t)(row * SPITCH + kq) * 4,
                      W + (size_t)(n0 + row) * K + s * 32 + kq);
            }
            cpa_commit();
        } else {
            cpa_commit();
        }
    }

#pragma unroll
    for (int mi = 0; mi < 4; mi++) {
#pragma unroll
        for (int ni = 0; ni < 4; ni++) {
            int col = n0 + wc + ni * 8 + qc * 2;
            float b0 = bias[col], b1 = bias[col + 1];
#pragma unroll
            for (int half = 0; half < 2; half++) {
                int row = m0 + wr + mi * 16 + qr + half * 8;
                float v0 = acc[mi][ni][half * 2 + 0] + b0;
                float v1 = acc[mi][ni][half * 2 + 1] + b1;
                if (ACT == 1) {
                    v0 = 0.5f * v0 * (1.f + erff(v0 * 0.70710678118654752f));
                    v1 = 0.5f * v1 * (1.f + erff(v1 * 0.70710678118654752f));
                }
                float2 o; o.x = v0; o.y = v1;
                *reinterpret_cast<float2*>(C + (size_t)row * N + col) = o;
            }
        }
    }
}

// ---------------------------------------------------------------------------
// Fused attention scores + softmax (TF32 tensor cores, raw-bit operands).
// Per block: 64 query rows x all 512 keys for one (b,h).
// ---------------------------------------------------------------------------
#define APITCH 68

__global__ __launch_bounds__(256) void attn_fused_kernel(
    const float* __restrict__ qkv, const int* __restrict__ mask,
    float* __restrict__ attn) {
    __shared__ uint32_t Qs[64 * APITCH];
    __shared__ uint32_t Ks[64 * APITCH];
    __shared__ float biasS[512];
    __shared__ float red[64 * 9];

    const int t = threadIdx.x, lane = t & 31, warp = t >> 5;
    const int qr = lane >> 2, qc = lane & 3;
    const int bh = blockIdx.y, b = bh >> 3, h = bh & 7;
    const int m0 = blockIdx.x * 64;
    const float* qb = qkv + (size_t)b * TS * QKVW + h * THD;
    const float* kb = qb + TE;

    for (int i = t; i < 512; i += 256)
        biasS[i] = (mask[b * TS + i] == 0) ? -1e30f : 0.f;

    // Load Q tile 64x64 (raw fp32 bits)
#pragma unroll
    for (int i = 0; i < 4; i++) {
        int f4 = t + 256 * i;
        int row = f4 >> 4, kq = (f4 & 15) * 4;
        float4 q4 = *reinterpret_cast<const float4*>(qb + (size_t)(m0 + row) * QKVW + kq);
        uint32_t* s = &Qs[row * APITCH + kq];
        s[0] = __float_as_uint(q4.x); s[1] = __float_as_uint(q4.y);
        s[2] = __float_as_uint(q4.z); s[3] = __float_as_uint(q4.w);
    }

    float acc[8][4][4];
#pragma unroll
    for (int c = 0; c < 8; c++)
#pragma unroll
        for (int mi = 0; mi < 4; mi++)
#pragma unroll
            for (int r = 0; r < 4; r++) acc[c][mi][r] = 0.f;

    float4 kv[4];
#pragma unroll
    for (int i = 0; i < 4; i++) {
        int f4 = t + 256 * i;
        int row = f4 >> 4, kq = (f4 & 15) * 4;
        kv[i] = *reinterpret_cast<const float4*>(kb + (size_t)row * QKVW + kq);
    }

    for (int c = 0; c < 8; c++) {
        __syncthreads();
#pragma unroll
        for (int i = 0; i < 4; i++) {
            int f4 = t + 256 * i;
            int row = f4 >> 4, kq = (f4 & 15) * 4;
            uint32_t* s = &Ks[row * APITCH + kq];
            s[0] = __float_as_uint(kv[i].x); s[1] = __float_as_uint(kv[i].y);
            s[2] = __float_as_uint(kv[i].z); s[3] = __float_as_uint(kv[i].w);
        }
        __syncthreads();
        if (c < 7) {
#pragma unroll
            for (int i = 0; i < 4; i++) {
                int f4 = t + 256 * i;
                int row = f4 >> 4, kq = (f4 & 15) * 4;
                kv[i] = *reinterpret_cast<const float4*>(kb + (size_t)((c + 1) * 64 + row) * QKVW + kq);
            }
        }
#pragma unroll
        for (int kk = 0; kk < 64; kk += 8) {
            uint32_t a[4][4], bf[2];
#pragma unroll
            for (int mi = 0; mi < 4; mi++) {
                const uint32_t* base = &Qs[(mi * 16 + qr) * APITCH + kk + qc];
                a[mi][0] = base[0];
                a[mi][1] = base[8 * APITCH];
                a[mi][2] = base[4];
                a[mi][3] = base[8 * APITCH + 4];
            }
            {
                const uint32_t* base = &Ks[(warp * 8 + qr) * APITCH + kk + qc];
                bf[0] = base[0];
                bf[1] = base[4];
            }
#pragma unroll
            for (int mi = 0; mi < 4; mi++) MMA_TF32(acc[c][mi], a[mi], bf);
        }
    }

    // ---- softmax over 512 keys per row ----
    float bm[4][2], bs[4][2];
    const float scale = 0.125f;
#pragma unroll
    for (int mi = 0; mi < 4; mi++) {
#pragma unroll
        for (int h2 = 0; h2 < 2; h2++) {
            float m = -3.4e38f;
#pragma unroll
            for (int c = 0; c < 8; c++) {
                int col = c * 64 + warp * 8 + qc * 2;
                float v0 = acc[c][mi][2 * h2 + 0] * scale + biasS[col];
                float v1 = acc[c][mi][2 * h2 + 1] * scale + biasS[col + 1];
                acc[c][mi][2 * h2 + 0] = v0;
                acc[c][mi][2 * h2 + 1] = v1;
                m = fmaxf(m, fmaxf(v0, v1));
            }
            m = fmaxf(m, __shfl_xor_sync(0xFFFFFFFFu, m, 1));
            m = fmaxf(m, __shfl_xor_sync(0xFFFFFFFFu, m, 2));
            bm[mi][h2] = m;
        }
    }
    if (qc == 0) {
#pragma unroll
        for (int mi = 0; mi < 4; mi++)
#pragma unroll
            for (int h2 = 0; h2 < 2; h2++)
                red[(mi * 16 + qr + h2 * 8) * 9 + warp] = bm[mi][h2];
    }
    __syncthreads();
#pragma unroll
    for (int mi = 0; mi < 4; mi++)
#pragma unroll
        for (int h2 = 0; h2 < 2; h2++) {
            int row = mi * 16 + qr + h2 * 8;
            float m = red[row * 9 + 0];
#pragma unroll
            for (int w2 = 1; w2 < 8; w2++) m = fmaxf(m, red[row * 9 + w2]);
            bm[mi][h2] = m;
        }
    __syncthreads();
#pragma unroll
    for (int mi = 0; mi < 4; mi++) {
#pragma unroll
        for (int h2 = 0; h2 < 2; h2++) {
            float m = bm[mi][h2];
            float s = 0.f;
#pragma unroll
            for (int c = 0; c < 8; c++) {
                float e0 = __expf(acc[c][mi][2 * h2 + 0] - m);
                float e1 = __expf(acc[c][mi][2 * h2 + 1] - m);
                acc[c][mi][2 * h2 + 0] = e0;
                acc[c][mi][2 * h2 + 1] = e1;
                s += e0 + e1;
            }
            s += __shfl_xor_sync(0xFFFFFFFFu, s, 1);
            s += __shfl_xor_sync(0xFFFFFFFFu, s, 2);
            bs[mi][h2] = s;
        }
    }
    if (qc == 0) {
#pragma unroll
        for (int mi = 0; mi < 4; mi++)
#pragma unroll
            for (int h2 = 0; h2 < 2; h2++)
                red[(mi * 16 + qr + h2 * 8) * 9 + warp] = bs[mi][h2];
    }
    __syncthreads();
#pragma unroll
    for (int mi = 0; mi < 4; mi++)
#pragma unroll
        for (int h2 = 0; h2 < 2; h2++) {
            int row = mi * 16 + qr + h2 * 8;
            float s = 0.f;
#pragma unroll
            for (int w2 = 0; w2 < 8; w2++) s += red[row * 9 + w2];
            float inv = 1.f / s;
            float* orow = attn + ((size_t)bh * TS + m0 + row) * TS;
#pragma unroll
            for (int c = 0; c < 8; c++) {
                int col = c * 64 + warp * 8 + qc * 2;
                float2 o;
                o.x = acc[c][mi][2 * h2 + 0] * inv;
                o.y = acc[c][mi][2 * h2 + 1] * inv;
                *reinterpret_cast<float2*>(orow + col) = o;
            }
        }
}

// ---------------------------------------------------------------------------
// AV v2: O[64,64] = P[64,512] @ V[512,64] per (b,h) tile.
// P double-buffered via cp.async; V transposed at STS so B-frag loads are
// conflict-free. Raw fp32 bits into tf32 mma.
// Dynamic smem: 2*64*68*4 (P) + 64*68*4 (VT) = 52224 B.
// ---------------------------------------------------------------------------
#define AV_PWORDS (64 * APITCH)
#define AV_SMEM ((2 * AV_PWORDS + AV_PWORDS) * 4)

__global__ __launch_bounds__(256) void attn_av_tc_kernel(
    const float* __restrict__ attn, const float* __restrict__ qkv,
    float* __restrict__ outx) {
    extern __shared__ uint32_t sm[];
    uint32_t* Ps[2] = { sm, sm + AV_PWORDS };
    uint32_t* VT = sm + 2 * AV_PWORDS;
    const uint32_t smBase = (uint32_t)__cvta_generic_to_shared(sm);

    const int t = threadIdx.x, lane = t & 31, warp = t >> 5;
    const int qr = lane >> 2, qc = lane & 3;
    const int bh = blockIdx.y, b = bh >> 3, h = bh & 7;
    const int m0 = blockIdx.x * 64;
    const int wr = (warp & 3) * 16;
    const int wc = (warp >> 2) * 32;
    const float* P = attn + (size_t)bh * TS * TS;
    const float* vb = qkv + (size_t)b * TS * QKVW + 2 * TE + h * THD;

    float acc[4][4] = {};

    // prologue: cp.async P chunk 0; LDG V chunk 0
#pragma unroll
    for (int i = 0; i < 4; i++) {
        int f4 = t + 256 * i;
        int row = f4 >> 4, kq = (f4 & 15) * 4;
        cpa16(smBase + (uint32_t)(row * APITCH + kq) * 4,
              P + (size_t)(m0 + row) * TS + kq);
    }
    cpa_commit();

    float4 vv[4];
#pragma unroll
    for (int i = 0; i < 4; i++) {
        int f4 = t + 256 * i;
        int row = f4 >> 4, kq = (f4 & 15) * 4;
        vv[i] = *reinterpret_cast<const float4*>(vb + (size_t)row * QKVW + kq);
    }

    for (int kc = 0; kc < 8; kc++) {
        __syncthreads();   // prior VT consumers done
        // store V chunk transposed: VT[dim][key]
#pragma unroll
        for (int i = 0; i < 4; i++) {
            int f4 = t + 256 * i;
            int row = f4 >> 4, kq = (f4 & 15) * 4;
            VT[(kq + 0) * APITCH + row] = __float_as_uint(vv[i].x);
            VT[(kq + 1) * APITCH + row] = __float_as_uint(vv[i].y);
            VT[(kq + 2) * APITCH + row] = __float_as_uint(vv[i].z);
            VT[(kq + 3) * APITCH + row] = __float_as_uint(vv[i].w);
        }
        // issue next P chunk
        if (kc + 1 < 8) {
            uint32_t poff = smBase + (uint32_t)(((kc + 1) & 1) * AV_PWORDS) * 4;
#pragma unroll
            for (int i = 0; i < 4; i++) {
                int f4 = t + 256 * i;
                int row = f4 >> 4, kq = (f4 & 15) * 4;
                cpa16(poff + (uint32_t)(row * APITCH + kq) * 4,
                      P + (size_t)(m0 + row) * TS + (kc + 1) * 64 + kq);
            }
            cpa_commit();
            asm volatile("cp.async.wait_group 1;");
        } else {
            cpa_commit();
            asm volatile("cp.async.wait_group 0;");
        }
        __syncthreads();
        // prefetch next V chunk
        if (kc + 1 < 8) {
#pragma unroll
            for (int i = 0; i < 4; i++) {
                int f4 = t + 256 * i;
                int row = f4 >> 4, kq = (f4 & 15) * 4;
                vv[i] = *reinterpret_cast<const float4*>(vb + (size_t)((kc + 1) * 64 + row) * QKVW + kq);
            }
        }

        const uint32_t* Pc = Ps[kc & 1];
#pragma unroll
        for (int kk = 0; kk < 64; kk += 8) {
            uint32_t a[4], bf[4][2];
            {
                const uint32_t* base = &Pc[(wr + qr) * APITCH + kk + qc];
                a[0] = base[0];
                a[1] = base[8 * APITCH];
                a[2] = base[4];
                a[3] = base[8 * APITCH + 4];
            }
#pragma unroll
            for (int ni = 0; ni < 4; ni++) {
                const uint32_t* base = &VT[(wc + ni * 8 + qr) * APITCH + kk + qc];
                bf[ni][0] = base[0];
                bf[ni][1] = base[4];
            }
#pragma unroll
            for (int ni = 0; ni < 4; ni++) MMA_TF32(acc[ni], a, bf[ni]);
        }
    }

#pragma unroll
    for (int ni = 0; ni < 4; ni++) {
#pragma unroll
        for (int h2 = 0; h2 < 2; h2++) {
            int row = m0 + wr + qr + h2 * 8;
            int col = wc + ni * 8 + qc * 2;
            float2 o;
            o.x = acc[ni][2 * h2 + 0];
            o.y = acc[ni][2 * h2 + 1];
            *reinterpret_cast<float2*>(outx + ((size_t)b * TS + row) * TE + h * THD + col) = o;
        }
    }
}

// ---------------------------------------------------------------------------
// Fused residual + LayerNorm: x = LN(x + y) * g + b. 1 block/token, 128 thr.
// ---------------------------------------------------------------------------
__global__ __launch_bounds__(128) void add_ln_kernel(
    float* __restrict__ x, const float* __restrict__ y,
    const float* __restrict__ g, const float* __restrict__ bb) {
    const size_t row = blockIdx.x;
    const int t = threadIdx.x;
    float4 xv = reinterpret_cast<float4*>(x + row * TE)[t];
    float4 yv = reinterpret_cast<const float4*>(y + row * TE)[t];
    float4 s;
    s.x = xv.x + yv.x; s.y = xv.y + yv.y; s.z = xv.z + yv.z; s.w = xv.w + yv.w;
    float sum = s.x + s.y + s.z + s.w;
    float sq = s.x * s.x + s.y * s.y + s.z * s.z + s.w * s.w;
#pragma unroll
    for (int o = 16; o; o >>= 1) {
        sum += __shfl_xor_sync(0xFFFFFFFFu, sum, o);
        sq  += __shfl_xor_sync(0xFFFFFFFFu, sq, o);
    }
    __shared__ float s1[4], s2[4];
    if ((t & 31) == 0) { s1[t >> 5] = sum; s2[t >> 5] = sq; }
    __syncthreads();
    sum = s1[0] + s1[1] + s1[2] + s1[3];
    sq  = s2[0] + s2[1] + s2[2] + s2[3];
    const float mean = sum * (1.f / TE);
    const float var = sq * (1.f / TE) - mean * mean;
    const float rstd = rsqrtf(var + 1e-5f);
    float4 gv = reinterpret_cast<const float4*>(g)[t];
    float4 bv = reinterpret_cast<const float4*>(bb)[t];
    float4 o;
    o.x = (s.x - mean) * rstd * gv.x + bv.x;
    o.y = (s.y - mean) * rstd * gv.y + bv.y;
    o.z = (s.z - mean) * rstd * gv.z + bv.z;
    o.w = (s.w - mean) * rstd * gv.w + bv.w;
    reinterpret_cast<float4*>(x + row * TE)[t] = o;
}

// ---------------------------------------------------------------------------
// CLS head
// ---------------------------------------------------------------------------
__global__ void cls_kernel(const float* __restrict__ x, const float* __restrict__ w,
                           const float* __restrict__ cb, float* __restrict__ out) {
    int t = threadIdx.x;
    if (t >= TB * 2) return;
    int b = t >> 1, c = t & 1;
    const float* xr = x + (size_t)b * TS * TE;
    const float* wr = w + c * TE;
    float s = cb[c];
    for (int e = 0; e < TE; e++) s = fmaf(xr[e], wr[e], s);
    out[b * 2 + c] = s;
}

// ---------------------------------------------------------------------------
extern "C" void kernel_launch(void* const* d_in, const int* in_sizes, int n_in,
                              void* d_out, int out_size) {
    const int*   ids  = (const int*)d_in[0];
    const int*   mask = (const int*)d_in[1];
    const float* emb  = (const float*)d_in[2];
    const float* pos  = (const float*)d_in[3];
    const float* ipw  = (const float*)d_in[4];
    const float* ipb  = (const float*)d_in[5];
    const float* opw  = (const float*)d_in[6];
    const float* opb  = (const float*)d_in[7];
    const float* l1g  = (const float*)d_in[8];
    const float* l1b  = (const float*)d_in[9];
    const float* l2g  = (const float*)d_in[10];
    const float* l2b  = (const float*)d_in[11];
    const float* f1w  = (const float*)d_in[12];
    const float* f1b  = (const float*)d_in[13];
    const float* f2w  = (const float*)d_in[14];
    const float* f2b  = (const float*)d_in[15];
    const float* cw   = (const float*)d_in[16];
    const float* cb   = (const float*)d_in[17];
    float* out = (float*)d_out;
    float* attn_base = out + TB * 2;  // logits first, then [L,B,NH,S,S] attn

    float *x, *qkv, *att, *y, *hb;
    cudaGetSymbolAddress((void**)&x,   g_x);
    cudaGetSymbolAddress((void**)&qkv, g_qkv);
    cudaGetSymbolAddress((void**)&att, g_att);
    cudaGetSymbolAddress((void**)&y,   g_y);
    cudaGetSymbolAddress((void**)&hb,  g_h);

    cudaFuncSetAttribute(tgemm_kernel<0>, cudaFuncAttributeMaxDynamicSharedMemorySize, TG_SMEM);
    cudaFuncSetAttribute(tgemm_kernel<1>, cudaFuncAttributeMaxDynamicSharedMemorySize, TG_SMEM);
    cudaFuncSetAttribute(attn_av_tc_kernel, cudaFuncAttributeMaxDynamicSharedMemorySize, AV_SMEM);

    embed_kernel<<<(TT * 128) / 256, 256>>>(ids, emb, pos, x);

    for (int l = 0; l < TL; l++) {
        tgemm_kernel<0><<<dim3(QKVW / 128, TT / 128), 256, TG_SMEM>>>(
            x, ipw + (size_t)l * QKVW * TE, ipb + l * QKVW, qkv, QKVW, TE);

        float* attn_l = attn_base + (size_t)l * TB * TNH * TS * TS;
        attn_fused_kernel<<<dim3(8, TB * TNH), 256>>>(qkv, mask, attn_l);
        attn_av_tc_kernel<<<dim3(8, TB * TNH), 256, AV_SMEM>>>(attn_l, qkv, att);

        tgemm_kernel<0><<<dim3(TE / 128, TT / 128), 256, TG_SMEM>>>(
            att, opw + (size_t)l * TE * TE, opb + l * TE, y, TE, TE);
        add_ln_kernel<<<TT, 128>>>(x, y, l1g + l * TE, l1b + l * TE);

        tgemm_kernel<1><<<dim3(4 * TE / 128, TT / 128), 256, TG_SMEM>>>(
            x, f1w + (size_t)l * 4 * TE * TE, f1b + l * 4 * TE, hb, 4 * TE, TE);
        tgemm_kernel<0><<<dim3(TE / 128, TT / 128), 256, TG_SMEM>>>(
            hb, f2w + (size_t)l * TE * 4 * TE, f2b + l * TE, y, TE, 4 * TE);
        add_ln_kernel<<<TT, 128>>>(x, y, l2g + l * TE, l2b + l * TE);
    }

    cls_kernel<<<1, 64>>>(x, cw, cb, out);
}

// round 5
// speedup vs baseline: 1.1628x; 1.1628x over previous
#include <cuda_runtime.h>
#include <cuda_bf16.h>
#include <cstdint>
#include <math.h>

// Problem constants
#define TB 32      // batch
#define TS 512     // seq len
#define TE 512     // d_model
#define THD 64     // head dim
#define TNH 8      // heads
#define TL 3       // layers
#define TT (TB*TS) // tokens = 16384
#define QKVW 1536  // 3*E

// Scratch (device globals; allocation-free contract)
__device__ float g_x[(size_t)TT * TE];       // running hidden   32 MB
__device__ float g_qkv[(size_t)TT * QKVW];   // qkv              96 MB
__device__ float g_att[(size_t)TT * TE];     // attn concat out  32 MB
__device__ float g_y[(size_t)TT * TE];       // gemm out         32 MB
__device__ float g_h[(size_t)TT * 4 * TE];   // ffn hidden      128 MB

#define MMA_TF32(d, a, b)                                                     \
    asm volatile(                                                             \
        "mma.sync.aligned.m16n8k8.row.col.f32.tf32.tf32.f32 "                 \
        "{%0,%1,%2,%3}, {%4,%5,%6,%7}, {%8,%9}, {%0,%1,%2,%3};"               \
        : "+f"(d[0]), "+f"(d[1]), "+f"(d[2]), "+f"(d[3])                      \
        : "r"(a[0]), "r"(a[1]), "r"(a[2]), "r"(a[3]), "r"(b[0]), "r"(b[1]))

__device__ __forceinline__ void cpa16(uint32_t s, const void* g) {
    asm volatile("cp.async.cg.shared.global [%0], [%1], 16;" :: "r"(s), "l"(g));
}
__device__ __forceinline__ void cpa_commit() {
    asm volatile("cp.async.commit_group;");
}

// ---------------------------------------------------------------------------
// Embedding: x[t] = emb[ids[t]] + pos[t % S]
// ---------------------------------------------------------------------------
__global__ __launch_bounds__(256) void embed_kernel(
    const int* __restrict__ ids, const float* __restrict__ emb,
    const float* __restrict__ pos, float* __restrict__ x) {
    int idx = blockIdx.x * blockDim.x + threadIdx.x;
    int token = idx >> 7;
    int c = idx & 127;
    float4 e = reinterpret_cast<const float4*>(emb)[(size_t)ids[token] * 128 + c];
    float4 p = reinterpret_cast<const float4*>(pos)[(size_t)(token & (TS - 1)) * 128 + c];
    float4 o;
    o.x = e.x + p.x; o.y = e.y + p.y; o.z = e.z + p.z; o.w = e.w + p.w;
    reinterpret_cast<float4*>(x)[idx] = o;
}

// ---------------------------------------------------------------------------
// TF32 GEMM v3: C[M,N] = A[M,K] @ W[N,K]^T + bias[N], opt GELU.
// Block 128x128, 128 threads = 4 warps, warp tile 64x64 (high LDS intensity).
// 3-stage cp.async pipeline; raw fp32 bits into tf32 mma.
// Dynamic smem: 3 stages x (A+W) x 128x36 words = 110592 B; 2 blocks/SM.
// ---------------------------------------------------------------------------
#define SPITCH 36
#define STG_WORDS (2 * 128 * SPITCH)   // one stage: A tile + W tile
#define TG_SMEM (3 * STG_WORDS * 4)

template <int ACT>
__global__ __launch_bounds__(128, 2) void tgemm_kernel(
    const float* __restrict__ A, const float* __restrict__ W,
    const float* __restrict__ bias, float* __restrict__ C,
    int N, int K) {
    extern __shared__ uint32_t sm[];
    const uint32_t smBase = (uint32_t)__cvta_generic_to_shared(sm);

    const int t = threadIdx.x;
    const int lane = t & 31;
    const int warp = t >> 5;
    const int wr = (warp >> 1) * 64;
    const int wc = (warp & 1) * 64;
    const int qr = lane >> 2;
    const int qc = lane & 3;

    const int m0 = blockIdx.y * 128;
    const int n0 = blockIdx.x * 128;
    const int KT = K >> 5;

    float acc[4][8][4];
#pragma unroll
    for (int i = 0; i < 4; i++)
#pragma unroll
        for (int j = 0; j < 8; j++)
#pragma unroll
            for (int r = 0; r < 4; r++) acc[i][j][r] = 0.f;

    // prologue: issue stages 0,1,2
#pragma unroll
    for (int s = 0; s < 3; s++) {
        if (s < KT) {
            uint32_t base = smBase + (uint32_t)(s * STG_WORDS) * 4;
#pragma unroll
            for (int i = 0; i < 8; i++) {
                int f4 = t + 128 * i;
                int row = f4 >> 3, kq = (f4 & 7) * 4;
                cpa16(base + (uint32_t)(row * SPITCH + kq) * 4,
                      A + (size_t)(m0 + row) * K + s * 32 + kq);
                cpa16(base + (uint32_t)(128 * SPITCH + row * SPITCH + kq) * 4,
                      W + (size_t)(n0 + row) * K + s * 32 + kq);
            }
        }
        cpa_commit();
    }

    for (int kt = 0; kt < KT; kt++) {
        if (kt + 2 < KT)
            asm volatile("cp.async.wait_group 2;");
        else if (kt + 1 < KT)
            asm volatile("cp.async.wait_group 1;");
        else
            asm volatile("cp.async.wait_group 0;");
        __syncthreads();

        const uint32_t* As = sm + (kt % 3) * STG_WORDS;
        const uint32_t* Ws = As + 128 * SPITCH;
#pragma unroll
        for (int kk = 0; kk < 32; kk += 8) {
            uint32_t a[4][4], b[8][2];
#pragma unroll
            for (int mi = 0; mi < 4; mi++) {
                const uint32_t* base = &As[(wr + mi * 16 + qr) * SPITCH + kk + qc];
                a[mi][0] = base[0];
                a[mi][1] = base[8 * SPITCH];
                a[mi][2] = base[4];
                a[mi][3] = base[8 * SPITCH + 4];
            }
#pragma unroll
            for (int ni = 0; ni < 8; ni++) {
                const uint32_t* base = &Ws[(wc + ni * 8 + qr) * SPITCH + kk + qc];
                b[ni][0] = base[0];
                b[ni][1] = base[4];
            }
#pragma unroll
            for (int mi = 0; mi < 4; mi++)
#pragma unroll
                for (int ni = 0; ni < 8; ni++) MMA_TF32(acc[mi][ni], a[mi], b[ni]);
        }
        __syncthreads();

        if (kt + 3 < KT) {
            int s = kt + 3;
            uint32_t base = smBase + (uint32_t)((s % 3) * STG_WORDS) * 4;
#pragma unroll
            for (int i = 0; i < 8; i++) {
                int f4 = t + 128 * i;
                int row = f4 >> 3, kq = (f4 & 7) * 4;
                cpa16(base + (uint32_t)(row * SPITCH + kq) * 4,
                      A + (size_t)(m0 + row) * K + s * 32 + kq);
                cpa16(base + (uint32_t)(128 * SPITCH + row * SPITCH + kq) * 4,
                      W + (size_t)(n0 + row) * K + s * 32 + kq);
            }
        }
        cpa_commit();
    }

#pragma unroll
    for (int mi = 0; mi < 4; mi++) {
#pragma unroll
        for (int ni = 0; ni < 8; ni++) {
            int col = n0 + wc + ni * 8 + qc * 2;
            float b0 = bias[col], b1 = bias[col + 1];
#pragma unroll
            for (int half = 0; half < 2; half++) {
                int row = m0 + wr + mi * 16 + qr + half * 8;
                float v0 = acc[mi][ni][half * 2 + 0] + b0;
                float v1 = acc[mi][ni][half * 2 + 1] + b1;
                if (ACT == 1) {
                    v0 = 0.5f * v0 * (1.f + erff(v0 * 0.70710678118654752f));
                    v1 = 0.5f * v1 * (1.f + erff(v1 * 0.70710678118654752f));
                }
                float2 o; o.x = v0; o.y = v1;
                *reinterpret_cast<float2*>(C + (size_t)row * N + col) = o;
            }
        }
    }
}

// ---------------------------------------------------------------------------
// Fused attention scores + softmax (TF32 tensor cores, raw-bit operands).
// Per block: 64 query rows x all 512 keys for one (b,h).
// ---------------------------------------------------------------------------
#define APITCH 68

__global__ __launch_bounds__(256) void attn_fused_kernel(
    const float* __restrict__ qkv, const int* __restrict__ mask,
    float* __restrict__ attn) {
    __shared__ uint32_t Qs[64 * APITCH];
    __shared__ uint32_t Ks[64 * APITCH];
    __shared__ float biasS[512];
    __shared__ float red[64 * 9];

    const int t = threadIdx.x, lane = t & 31, warp = t >> 5;
    const int qr = lane >> 2, qc = lane & 3;
    const int bh = blockIdx.y, b = bh >> 3, h = bh & 7;
    const int m0 = blockIdx.x * 64;
    const float* qb = qkv + (size_t)b * TS * QKVW + h * THD;
    const float* kb = qb + TE;

    for (int i = t; i < 512; i += 256)
        biasS[i] = (mask[b * TS + i] == 0) ? -1e30f : 0.f;

#pragma unroll
    for (int i = 0; i < 4; i++) {
        int f4 = t + 256 * i;
        int row = f4 >> 4, kq = (f4 & 15) * 4;
        float4 q4 = *reinterpret_cast<const float4*>(qb + (size_t)(m0 + row) * QKVW + kq);
        uint32_t* s = &Qs[row * APITCH + kq];
        s[0] = __float_as_uint(q4.x); s[1] = __float_as_uint(q4.y);
        s[2] = __float_as_uint(q4.z); s[3] = __float_as_uint(q4.w);
    }

    float acc[8][4][4];
#pragma unroll
    for (int c = 0; c < 8; c++)
#pragma unroll
        for (int mi = 0; mi < 4; mi++)
#pragma unroll
            for (int r = 0; r < 4; r++) acc[c][mi][r] = 0.f;

    float4 kv[4];
#pragma unroll
    for (int i = 0; i < 4; i++) {
        int f4 = t + 256 * i;
        int row = f4 >> 4, kq = (f4 & 15) * 4;
        kv[i] = *reinterpret_cast<const float4*>(kb + (size_t)row * QKVW + kq);
    }

    for (int c = 0; c < 8; c++) {
        __syncthreads();
#pragma unroll
        for (int i = 0; i < 4; i++) {
            int f4 = t + 256 * i;
            int row = f4 >> 4, kq = (f4 & 15) * 4;
            uint32_t* s = &Ks[row * APITCH + kq];
            s[0] = __float_as_uint(kv[i].x); s[1] = __float_as_uint(kv[i].y);
            s[2] = __float_as_uint(kv[i].z); s[3] = __float_as_uint(kv[i].w);
        }
        __syncthreads();
        if (c < 7) {
#pragma unroll
            for (int i = 0; i < 4; i++) {
                int f4 = t + 256 * i;
                int row = f4 >> 4, kq = (f4 & 15) * 4;
                kv[i] = *reinterpret_cast<const float4*>(kb + (size_t)((c + 1) * 64 + row) * QKVW + kq);
            }
        }
#pragma unroll
        for (int kk = 0; kk < 64; kk += 8) {
            uint32_t a[4][4], bf[2];
#pragma unroll
            for (int mi = 0; mi < 4; mi++) {
                const uint32_t* base = &Qs[(mi * 16 + qr) * APITCH + kk + qc];
                a[mi][0] = base[0];
                a[mi][1] = base[8 * APITCH];
                a[mi][2] = base[4];
                a[mi][3] = base[8 * APITCH + 4];
            }
            {
                const uint32_t* base = &Ks[(warp * 8 + qr) * APITCH + kk + qc];
                bf[0] = base[0];
                bf[1] = base[4];
            }
#pragma unroll
            for (int mi = 0; mi < 4; mi++) MMA_TF32(acc[c][mi], a[mi], bf);
        }
    }

    // ---- softmax over 512 keys per row ----
    float bm[4][2], bs[4][2];
    const float scale = 0.125f;
#pragma unroll
    for (int mi = 0; mi < 4; mi++) {
#pragma unroll
        for (int h2 = 0; h2 < 2; h2++) {
            float m = -3.4e38f;
#pragma unroll
            for (int c = 0; c < 8; c++) {
                int col = c * 64 + warp * 8 + qc * 2;
                float v0 = acc[c][mi][2 * h2 + 0] * scale + biasS[col];
                float v1 = acc[c][mi][2 * h2 + 1] * scale + biasS[col + 1];
                acc[c][mi][2 * h2 + 0] = v0;
                acc[c][mi][2 * h2 + 1] = v1;
                m = fmaxf(m, fmaxf(v0, v1));
            }
            m = fmaxf(m, __shfl_xor_sync(0xFFFFFFFFu, m, 1));
            m = fmaxf(m, __shfl_xor_sync(0xFFFFFFFFu, m, 2));
            bm[mi][h2] = m;
        }
    }
    if (qc == 0) {
#pragma unroll
        for (int mi = 0; mi < 4; mi++)
#pragma unroll
            for (int h2 = 0; h2 < 2; h2++)
                red[(mi * 16 + qr + h2 * 8) * 9 + warp] = bm[mi][h2];
    }
    __syncthreads();
#pragma unroll
    for (int mi = 0; mi < 4; mi++)
#pragma unroll
        for (int h2 = 0; h2 < 2; h2++) {
            int row = mi * 16 + qr + h2 * 8;
            float m = red[row * 9 + 0];
#pragma unroll
            for (int w2 = 1; w2 < 8; w2++) m = fmaxf(m, red[row * 9 + w2]);
            bm[mi][h2] = m;
        }
    __syncthreads();
#pragma unroll
    for (int mi = 0; mi < 4; mi++) {
#pragma unroll
        for (int h2 = 0; h2 < 2; h2++) {
            float m = bm[mi][h2];
            float s = 0.f;
#pragma unroll
            for (int c = 0; c < 8; c++) {
                float e0 = __expf(acc[c][mi][2 * h2 + 0] - m);
                float e1 = __expf(acc[c][mi][2 * h2 + 1] - m);
                acc[c][mi][2 * h2 + 0] = e0;
                acc[c][mi][2 * h2 + 1] = e1;
                s += e0 + e1;
            }
            s += __shfl_xor_sync(0xFFFFFFFFu, s, 1);
            s += __shfl_xor_sync(0xFFFFFFFFu, s, 2);
            bs[mi][h2] = s;
        }
    }
    if (qc == 0) {
#pragma unroll
        for (int mi = 0; mi < 4; mi++)
#pragma unroll
            for (int h2 = 0; h2 < 2; h2++)
                red[(mi * 16 + qr + h2 * 8) * 9 + warp] = bs[mi][h2];
    }
    __syncthreads();
#pragma unroll
    for (int mi = 0; mi < 4; mi++)
#pragma unroll
        for (int h2 = 0; h2 < 2; h2++) {
            int row = mi * 16 + qr + h2 * 8;
            float s = 0.f;
#pragma unroll
            for (int w2 = 0; w2 < 8; w2++) s += red[row * 9 + w2];
            float inv = 1.f / s;
            float* orow = attn + ((size_t)bh * TS + m0 + row) * TS;
#pragma unroll
            for (int c = 0; c < 8; c++) {
                int col = c * 64 + warp * 8 + qc * 2;
                float2 o;
                o.x = acc[c][mi][2 * h2 + 0] * inv;
                o.y = acc[c][mi][2 * h2 + 1] * inv;
                *reinterpret_cast<float2*>(orow + col) = o;
            }
        }
}

// ---------------------------------------------------------------------------
// AV (round-3 structure, raw-bit operands): O[64,64] = P[64,512] @ V[512,64].
// grid (8 mtiles, B*NH), block 256 = 8 warps; warp (w&3) owns 16 rows,
// (w>>2) owns 32 of the 64 head dims. V indexed as natural B layout.
// ---------------------------------------------------------------------------
__global__ __launch_bounds__(256) void attn_av_tc_kernel(
    const float* __restrict__ attn, const float* __restrict__ qkv,
    float* __restrict__ outx) {
    __shared__ uint32_t Ps[64 * APITCH];
    __shared__ uint32_t Vs[64 * APITCH];

    const int t = threadIdx.x, lane = t & 31, warp = t >> 5;
    const int qr = lane >> 2, qc = lane & 3;
    const int bh = blockIdx.y, b = bh >> 3, h = bh & 7;
    const int m0 = blockIdx.x * 64;
    const int wr = (warp & 3) * 16;
    const int wc = (warp >> 2) * 32;
    const float* P = attn + (size_t)bh * TS * TS;
    const float* vb = qkv + (size_t)b * TS * QKVW + 2 * TE + h * THD;

    float acc[4][4] = {};

    float4 pv[4], vv[4];
#pragma unroll
    for (int i = 0; i < 4; i++) {
        int f4 = t + 256 * i;
        int row = f4 >> 4, kq = (f4 & 15) * 4;
        pv[i] = *reinterpret_cast<const float4*>(P + (size_t)(m0 + row) * TS + kq);
        vv[i] = *reinterpret_cast<const float4*>(vb + (size_t)row * QKVW + kq);
    }

    for (int kc = 0; kc < 8; kc++) {
        __syncthreads();
#pragma unroll
        for (int i = 0; i < 4; i++) {
            int f4 = t + 256 * i;
            int row = f4 >> 4, kq = (f4 & 15) * 4;
            uint32_t* sp = &Ps[row * APITCH + kq];
            sp[0] = __float_as_uint(pv[i].x); sp[1] = __float_as_uint(pv[i].y);
            sp[2] = __float_as_uint(pv[i].z); sp[3] = __float_as_uint(pv[i].w);
            uint32_t* sv = &Vs[row * APITCH + kq];
            sv[0] = __float_as_uint(vv[i].x); sv[1] = __float_as_uint(vv[i].y);
            sv[2] = __float_as_uint(vv[i].z); sv[3] = __float_as_uint(vv[i].w);
        }
        __syncthreads();
        if (kc < 7) {
#pragma unroll
            for (int i = 0; i < 4; i++) {
                int f4 = t + 256 * i;
                int row = f4 >> 4, kq = (f4 & 15) * 4;
                pv[i] = *reinterpret_cast<const float4*>(P + (size_t)(m0 + row) * TS + (kc + 1) * 64 + kq);
                vv[i] = *reinterpret_cast<const float4*>(vb + (size_t)((kc + 1) * 64 + row) * QKVW + kq);
            }
        }
#pragma unroll
        for (int kk = 0; kk < 64; kk += 8) {
            uint32_t a[4], bf[4][2];
            {
                const uint32_t* base = &Ps[(wr + qr) * APITCH + kk + qc];
                a[0] = base[0];
                a[1] = base[8 * APITCH];
                a[2] = base[4];
                a[3] = base[8 * APITCH + 4];
            }
#pragma unroll
            for (int ni = 0; ni < 4; ni++) {
                bf[ni][0] = Vs[(kk + qc) * APITCH + wc + ni * 8 + qr];
                bf[ni][1] = Vs[(kk + qc + 4) * APITCH + wc + ni * 8 + qr];
            }
#pragma unroll
            for (int ni = 0; ni < 4; ni++) MMA_TF32(acc[ni], a, bf[ni]);
        }
    }

#pragma unroll
    for (int ni = 0; ni < 4; ni++) {
#pragma unroll
        for (int h2 = 0; h2 < 2; h2++) {
            int row = m0 + wr + qr + h2 * 8;
            int col = wc + ni * 8 + qc * 2;
            float2 o;
            o.x = acc[ni][2 * h2 + 0];
            o.y = acc[ni][2 * h2 + 1];
            *reinterpret_cast<float2*>(outx + ((size_t)b * TS + row) * TE + h * THD + col) = o;
        }
    }
}

// ---------------------------------------------------------------------------
// Fused residual + LayerNorm: x = LN(x + y) * g + b. 1 block/token, 128 thr.
// ---------------------------------------------------------------------------
__global__ __launch_bounds__(128) void add_ln_kernel(
    float* __restrict__ x, const float* __restrict__ y,
    const float* __restrict__ g, const float* __restrict__ bb) {
    const size_t row = blockIdx.x;
    const int t = threadIdx.x;
    float4 xv = reinterpret_cast<float4*>(x + row * TE)[t];
    float4 yv = reinterpret_cast<const float4*>(y + row * TE)[t];
    float4 s;
    s.x = xv.x + yv.x; s.y = xv.y + yv.y; s.z = xv.z + yv.z; s.w = xv.w + yv.w;
    float sum = s.x + s.y + s.z + s.w;
    float sq = s.x * s.x + s.y * s.y + s.z * s.z + s.w * s.w;
#pragma unroll
    for (int o = 16; o; o >>= 1) {
        sum += __shfl_xor_sync(0xFFFFFFFFu, sum, o);
        sq  += __shfl_xor_sync(0xFFFFFFFFu, sq, o);
    }
    __shared__ float s1[4], s2[4];
    if ((t & 31) == 0) { s1[t >> 5] = sum; s2[t >> 5] = sq; }
    __syncthreads();
    sum = s1[0] + s1[1] + s1[2] + s1[3];
    sq  = s2[0] + s2[1] + s2[2] + s2[3];
    const float mean = sum * (1.f / TE);
    const float var = sq * (1.f / TE) - mean * mean;
    const float rstd = rsqrtf(var + 1e-5f);
    float4 gv = reinterpret_cast<const float4*>(g)[t];
    float4 bv = reinterpret_cast<const float4*>(bb)[t];
    float4 o;
    o.x = (s.x - mean) * rstd * gv.x + bv.x;
    o.y = (s.y - mean) * rstd * gv.y + bv.y;
    o.z = (s.z - mean) * rstd * gv.z + bv.z;
    o.w = (s.w - mean) * rstd * gv.w + bv.w;
    reinterpret_cast<float4*>(x + row * TE)[t] = o;
}

// ---------------------------------------------------------------------------
// CLS head
// ---------------------------------------------------------------------------
__global__ void cls_kernel(const float* __restrict__ x, const float* __restrict__ w,
                           const float* __restrict__ cb, float* __restrict__ out) {
    int t = threadIdx.x;
    if (t >= TB * 2) return;
    int b = t >> 1, c = t & 1;
    const float* xr = x + (size_t)b * TS * TE;
    const float* wr = w + c * TE;
    float s = cb[c];
    for (int e = 0; e < TE; e++) s = fmaf(xr[e], wr[e], s);
    out[b * 2 + c] = s;
}

// ---------------------------------------------------------------------------
extern "C" void kernel_launch(void* const* d_in, const int* in_sizes, int n_in,
                              void* d_out, int out_size) {
    const int*   ids  = (const int*)d_in[0];
    const int*   mask = (const int*)d_in[1];
    const float* emb  = (const float*)d_in[2];
    const float* pos  = (const float*)d_in[3];
    const float* ipw  = (const float*)d_in[4];
    const float* ipb  = (const float*)d_in[5];
    const float* opw  = (const float*)d_in[6];
    const float* opb  = (const float*)d_in[7];
    const float* l1g  = (const float*)d_in[8];
    const float* l1b  = (const float*)d_in[9];
    const float* l2g  = (const float*)d_in[10];
    const float* l2b  = (const float*)d_in[11];
    const float* f1w  = (const float*)d_in[12];
    const float* f1b  = (const float*)d_in[13];
    const float* f2w  = (const float*)d_in[14];
    const float* f2b  = (const float*)d_in[15];
    const float* cw   = (const float*)d_in[16];
    const float* cb   = (const float*)d_in[17];
    float* out = (float*)d_out;
    float* attn_base = out + TB * 2;  // logits first, then [L,B,NH,S,S] attn

    float *x, *qkv, *att, *y, *hb;
    cudaGetSymbolAddress((void**)&x,   g_x);
    cudaGetSymbolAddress((void**)&qkv, g_qkv);
    cudaGetSymbolAddress((void**)&att, g_att);
    cudaGetSymbolAddress((void**)&y,   g_y);
    cudaGetSymbolAddress((void**)&hb,  g_h);

    cudaFuncSetAttribute(tgemm_kernel<0>, cudaFuncAttributeMaxDynamicSharedMemorySize, TG_SMEM);
    cudaFuncSetAttribute(tgemm_kernel<1>, cudaFuncAttributeMaxDynamicSharedMemorySize, TG_SMEM);

    embed_kernel<<<(TT * 128) / 256, 256>>>(ids, emb, pos, x);

    for (int l = 0; l < TL; l++) {
        tgemm_kernel<0><<<dim3(QKVW / 128, TT / 128), 128, TG_SMEM>>>(
            x, ipw + (size_t)l * QKVW * TE, ipb + l * QKVW, qkv, QKVW, TE);

        float* attn_l = attn_base + (size_t)l * TB * TNH * TS * TS;
        attn_fused_kernel<<<dim3(8, TB * TNH), 256>>>(qkv, mask, attn_l);
        attn_av_tc_kernel<<<dim3(8, TB * TNH), 256>>>(attn_l, qkv, att);

        tgemm_kernel<0><<<dim3(TE / 128, TT / 128), 128, TG_SMEM>>>(
            att, opw + (size_t)l * TE * TE, opb + l * TE, y, TE, TE);
        add_ln_kernel<<<TT, 128>>>(x, y, l1g + l * TE, l1b + l * TE);

        tgemm_kernel<1><<<dim3(4 * TE / 128, TT / 128), 128, TG_SMEM>>>(
            x, f1w + (size_t)l * 4 * TE * TE, f1b + l * 4 * TE, hb, 4 * TE, TE);
        tgemm_kernel<0><<<dim3(TE / 128, TT / 128), 128, TG_SMEM>>>(
            hb, f2w + (size_t)l * TE * 4 * TE, f2b + l * TE, y, TE, 4 * TE);
        add_ln_kernel<<<TT, 128>>>(x, y, l2g + l * TE, l2b + l * TE);
    }

    cls_kernel<<<1, 64>>>(x, cw, cb, out);
}

// round 7
// speedup vs baseline: 1.6250x; 1.3974x over previous
#include <cuda_runtime.h>
#include <cuda_fp16.h>
#include <cstdint>
#include <math.h>

// Problem constants
#define TB 32      // batch
#define TS 512     // seq len
#define TE 512     // d_model
#define THD 64     // head dim
#define TNH 8      // heads
#define TL 3       // layers
#define TT (TB*TS) // tokens = 16384
#define QKVW 1536  // 3*E

// Scratch (device globals; allocation-free contract)
__device__ float  g_x[(size_t)TT * TE];        // running hidden fp32   32 MB
__device__ float  g_qkv[(size_t)TT * QKVW];    // qkv fp32              96 MB
__device__ float  g_y[(size_t)TT * TE];        // gemm out fp32         32 MB
__device__ __half g_x16[(size_t)TT * TE];      // hidden fp16           16 MB
__device__ __half g_att16[(size_t)TT * TE];    // attn concat fp16      16 MB
__device__ __half g_h16[(size_t)TT * 4 * TE];  // ffn hidden fp16       64 MB
#define W16_TOTAL 9437184
__device__ __half g_w16[W16_TOTAL];            // all weights fp16      18 MB
// w16 layout offsets (halfs)
#define W16_IPW(l) ((size_t)(l) * 786432)
#define W16_OPW(l) (2359296 + (size_t)(l) * 262144)
#define W16_F1W(l) (3145728 + (size_t)(l) * 1048576)
#define W16_F2W(l) (6291456 + (size_t)(l) * 1048576)

#define MMA_TF32(d, a, b)                                                     \
    asm volatile(                                                             \
        "mma.sync.aligned.m16n8k8.row.col.f32.tf32.tf32.f32 "                 \
        "{%0,%1,%2,%3}, {%4,%5,%6,%7}, {%8,%9}, {%0,%1,%2,%3};"               \
        : "+f"(d[0]), "+f"(d[1]), "+f"(d[2]), "+f"(d[3])                      \
        : "r"(a[0]), "r"(a[1]), "r"(a[2]), "r"(a[3]), "r"(b[0]), "r"(b[1]))

#define MMA_F16(d, a, b)                                                      \
    asm volatile(                                                             \
        "mma.sync.aligned.m16n8k16.row.col.f32.f16.f16.f32 "                  \
        "{%0,%1,%2,%3}, {%4,%5,%6,%7}, {%8,%9}, {%0,%1,%2,%3};"               \
        : "+f"(d[0]), "+f"(d[1]), "+f"(d[2]), "+f"(d[3])                      \
        : "r"(a[0]), "r"(a[1]), "r"(a[2]), "r"(a[3]), "r"(b[0]), "r"(b[1]))

#define LDSM4(r0, r1, r2, r3, addr)                                           \
    asm volatile("ldmatrix.sync.aligned.m8n8.x4.shared.b16 {%0,%1,%2,%3}, [%4];" \
        : "=r"(r0), "=r"(r1), "=r"(r2), "=r"(r3) : "r"(addr))

#define LDSM2(r0, r1, addr)                                                   \
    asm volatile("ldmatrix.sync.aligned.m8n8.x2.shared.b16 {%0,%1}, [%2];"    \
        : "=r"(r0), "=r"(r1) : "r"(addr))

__device__ __forceinline__ void cpa16(uint32_t s, const void* g) {
    asm volatile("cp.async.cg.shared.global [%0], [%1], 16;" :: "r"(s), "l"(g));
}
__device__ __forceinline__ void cpa_commit() {
    asm volatile("cp.async.commit_group;");
}

// fp16 tile swizzle: row pitch 64B (32 halfs), chunk = 16B unit
__device__ __forceinline__ uint32_t hswz(int row, int chunk) {
    return (uint32_t)(row * 64 + (((chunk + (row >> 1)) & 3) << 4));
}

// ---------------------------------------------------------------------------
// Weight conversion fp32 -> fp16 (runs once per launch; memory-bound ~40us)
// ---------------------------------------------------------------------------
__global__ __launch_bounds__(256) void cvtw_kernel(
    const float* __restrict__ ipw, const float* __restrict__ opw,
    const float* __restrict__ f1w, const float* __restrict__ f2w,
    __half* __restrict__ w16) {
    size_t i = ((size_t)blockIdx.x * 256 + threadIdx.x) * 4;
    const float* src; size_t off;
    if (i < 2359296)      { src = ipw; off = i; }
    else if (i < 3145728) { src = opw; off = i - 2359296; }
    else if (i < 6291456) { src = f1w; off = i - 3145728; }
    else                  { src = f2w; off = i - 6291456; }
    float4 v = *reinterpret_cast<const float4*>(src + off);
    __half2* dst = reinterpret_cast<__half2*>(w16 + i);
    dst[0] = __floats2half2_rn(v.x, v.y);
    dst[1] = __floats2half2_rn(v.z, v.w);
}

// ---------------------------------------------------------------------------
// Embedding: x fp32 + fp16 twin
// ---------------------------------------------------------------------------
__global__ __launch_bounds__(256) void embed_kernel(
    const int* __restrict__ ids, const float* __restrict__ emb,
    const float* __restrict__ pos, float* __restrict__ x, __half* __restrict__ x16) {
    int idx = blockIdx.x * blockDim.x + threadIdx.x;
    int token = idx >> 7;
    int c = idx & 127;
    float4 e = reinterpret_cast<const float4*>(emb)[(size_t)ids[token] * 128 + c];
    float4 p = reinterpret_cast<const float4*>(pos)[(size_t)(token & (TS - 1)) * 128 + c];
    float4 o;
    o.x = e.x + p.x; o.y = e.y + p.y; o.z = e.z + p.z; o.w = e.w + p.w;
    reinterpret_cast<float4*>(x)[idx] = o;
    __half2* h = reinterpret_cast<__half2*>(x16) + idx * 2;
    h[0] = __floats2half2_rn(o.x, o.y);
    h[1] = __floats2half2_rn(o.z, o.w);
}

// ---------------------------------------------------------------------------
// FP16 tensor-core GEMM: C[M,N] = A[M,K] @ W[N,K]^T + bias, opt GELU,
// output fp32 or fp16. Block 128x128, 128 thr = 4 warps, warp tile 64x64.
// 4-stage cp.async ring (16KB/stage), ldmatrix fragment loads.
// ---------------------------------------------------------------------------
#define HSTG 16384
#define HG_SMEM (4 * HSTG)

template <int ACT, int OUT16>
__global__ __launch_bounds__(128, 2) void hgemm_kernel(
    const __half* __restrict__ A, const __half* __restrict__ W,
    const float* __restrict__ bias, float* __restrict__ C,
    __half* __restrict__ C16, int N, int K) {
    extern __shared__ char smraw[];
    uint32_t base;
    asm("{ .reg .u64 t; cvta.to.shared.u64 t, %1; cvt.u32.u64 %0, t; }"
        : "=r"(base) : "l"(smraw));

    const int t = threadIdx.x;
    const int lane = t & 31;
    const int warp = t >> 5;
    const int wr = (warp >> 1) * 64;
    const int wc = (warp & 1) * 64;
    const int qr = lane >> 2;
    const int qc = lane & 3;

    const int m0 = blockIdx.y * 128;
    const int n0 = blockIdx.x * 128;
    const int KT = K >> 5;

    // ldmatrix per-lane offsets
    const int arow = lane & 15;          // tile row within 16-row block
    const int achk = lane >> 4;          // 0/1 -> k chunk within k16 step
    const int brow = lane & 7;
    const int bchk = (lane >> 3) & 1;

    float acc[4][8][4];
#pragma unroll
    for (int i = 0; i < 4; i++)
#pragma unroll
        for (int j = 0; j < 8; j++)
#pragma unroll
            for (int r = 0; r < 4; r++) acc[i][j][r] = 0.f;

    // prologue: issue tiles 0..2
#pragma unroll
    for (int s = 0; s < 3; s++) {
        uint32_t sb = base + s * HSTG;
#pragma unroll
        for (int i = 0; i < 4; i++) {
            int idx = t + 128 * i;
            int row = idx >> 2, c = idx & 3;
            cpa16(sb + hswz(row, c), A + (size_t)(m0 + row) * K + s * 32 + c * 8);
            cpa16(sb + 8192 + hswz(row, c), W + (size_t)(n0 + row) * K + s * 32 + c * 8);
        }
        cpa_commit();
    }

    for (int kt = 0; kt < KT; kt++) {
        int pend = KT - 1 - kt; if (pend > 2) pend = 2;
        if (pend == 2)      asm volatile("cp.async.wait_group 2;");
        else if (pend == 1) asm volatile("cp.async.wait_group 1;");
        else                asm volatile("cp.async.wait_group 0;");
        __syncthreads();

        // issue tile kt+3 into stage (kt+3)&3 (its last reader was iter kt-1)
        if (kt + 3 < KT) {
            int j = kt + 3;
            uint32_t sb = base + (j & 3) * HSTG;
#pragma unroll
            for (int i = 0; i < 4; i++) {
                int idx = t + 128 * i;
                int row = idx >> 2, c = idx & 3;
                cpa16(sb + hswz(row, c), A + (size_t)(m0 + row) * K + j * 32 + c * 8);
                cpa16(sb + 8192 + hswz(row, c), W + (size_t)(n0 + row) * K + j * 32 + c * 8);
            }
            cpa_commit();
        } else {
            cpa_commit();
        }

        const uint32_t sb = base + (kt & 3) * HSTG;
#pragma unroll
        for (int s2 = 0; s2 < 2; s2++) {
            uint32_t a[4][4], bw[8][2];
#pragma unroll
            for (int mi = 0; mi < 4; mi++) {
                uint32_t ad = sb + hswz(wr + mi * 16 + arow, 2 * s2 + achk);
                LDSM4(a[mi][0], a[mi][1], a[mi][2], a[mi][3], ad);
            }
#pragma unroll
            for (int ni = 0; ni < 8; ni++) {
                uint32_t bd = sb + 8192 + hswz(wc + ni * 8 + brow, 2 * s2 + bchk);
                LDSM2(bw[ni][0], bw[ni][1], bd);
            }
#pragma unroll
            for (int mi = 0; mi < 4; mi++)
#pragma unroll
                for (int ni = 0; ni < 8; ni++) MMA_F16(acc[mi][ni], a[mi], bw[ni]);
        }
    }

#pragma unroll
    for (int mi = 0; mi < 4; mi++) {
#pragma unroll
        for (int ni = 0; ni < 8; ni++) {
            int col = n0 + wc + ni * 8 + qc * 2;
            float b0 = bias[col], b1 = bias[col + 1];
#pragma unroll
            for (int half = 0; half < 2; half++) {
                int row = m0 + wr + mi * 16 + qr + half * 8;
                float v0 = acc[mi][ni][half * 2 + 0] + b0;
                float v1 = acc[mi][ni][half * 2 + 1] + b1;
                if (ACT == 1) {
                    v0 = 0.5f * v0 * (1.f + erff(v0 * 0.70710678118654752f));
                    v1 = 0.5f * v1 * (1.f + erff(v1 * 0.70710678118654752f));
                }
                if (OUT16) {
                    *reinterpret_cast<__half2*>(C16 + (size_t)row * N + col) =
                        __floats2half2_rn(v0, v1);
                } else {
                    float2 o; o.x = v0; o.y = v1;
                    *reinterpret_cast<float2*>(C + (size_t)row * N + col) = o;
                }
            }
        }
    }
}

// ---------------------------------------------------------------------------
// Fused attention scores + softmax (TF32 mma.sync, raw-bit fp32 operands).
// ---------------------------------------------------------------------------
#define APITCH 68

__global__ __launch_bounds__(256) void attn_fused_kernel(
    const float* __restrict__ qkv, const int* __restrict__ mask,
    float* __restrict__ attn) {
    __shared__ uint32_t Qs[64 * APITCH];
    __shared__ uint32_t Ks[64 * APITCH];
    __shared__ float biasS[512];
    __shared__ float red[64 * 9];

    const int t = threadIdx.x, lane = t & 31, warp = t >> 5;
    const int qr = lane >> 2, qc = lane & 3;
    const int bh = blockIdx.y, b = bh >> 3, h = bh & 7;
    const int m0 = blockIdx.x * 64;
    const float* qb = qkv + (size_t)b * TS * QKVW + h * THD;
    const float* kb = qb + TE;

    for (int i = t; i < 512; i += 256)
        biasS[i] = (mask[b * TS + i] == 0) ? -1e30f : 0.f;

#pragma unroll
    for (int i = 0; i < 4; i++) {
        int f4 = t + 256 * i;
        int row = f4 >> 4, kq = (f4 & 15) * 4;
        float4 q4 = *reinterpret_cast<const float4*>(qb + (size_t)(m0 + row) * QKVW + kq);
        uint32_t* s = &Qs[row * APITCH + kq];
        s[0] = __float_as_uint(q4.x); s[1] = __float_as_uint(q4.y);
        s[2] = __float_as_uint(q4.z); s[3] = __float_as_uint(q4.w);
    }

    float acc[8][4][4];
#pragma unroll
    for (int c = 0; c < 8; c++)
#pragma unroll
        for (int mi = 0; mi < 4; mi++)
#pragma unroll
            for (int r = 0; r < 4; r++) acc[c][mi][r] = 0.f;

    float4 kv[4];
#pragma unroll
    for (int i = 0; i < 4; i++) {
        int f4 = t + 256 * i;
        int row = f4 >> 4, kq = (f4 & 15) * 4;
        kv[i] = *reinterpret_cast<const float4*>(kb + (size_t)row * QKVW + kq);
    }

    for (int c = 0; c < 8; c++) {
        __syncthreads();
#pragma unroll
        for (int i = 0; i < 4; i++) {
            int f4 = t + 256 * i;
            int row = f4 >> 4, kq = (f4 & 15) * 4;
            uint32_t* s = &Ks[row * APITCH + kq];
            s[0] = __float_as_uint(kv[i].x); s[1] = __float_as_uint(kv[i].y);
            s[2] = __float_as_uint(kv[i].z); s[3] = __float_as_uint(kv[i].w);
        }
        __syncthreads();
        if (c < 7) {
#pragma unroll
            for (int i = 0; i < 4; i++) {
                int f4 = t + 256 * i;
                int row = f4 >> 4, kq = (f4 & 15) * 4;
                kv[i] = *reinterpret_cast<const float4*>(kb + (size_t)((c + 1) * 64 + row) * QKVW + kq);
            }
        }
#pragma unroll
        for (int kk = 0; kk < 64; kk += 8) {
            uint32_t a[4][4], bf[2];
#pragma unroll
            for (int mi = 0; mi < 4; mi++) {
                const uint32_t* base = &Qs[(mi * 16 + qr) * APITCH + kk + qc];
                a[mi][0] = base[0];
                a[mi][1] = base[8 * APITCH];
                a[mi][2] = base[4];
                a[mi][3] = base[8 * APITCH + 4];
            }
            {
                const uint32_t* base = &Ks[(warp * 8 + qr) * APITCH + kk + qc];
                bf[0] = base[0];
                bf[1] = base[4];
            }
#pragma unroll
            for (int mi = 0; mi < 4; mi++) MMA_TF32(acc[c][mi], a[mi], bf);
        }
    }

    float bm[4][2], bs[4][2];
    const float scale = 0.125f;
#pragma unroll
    for (int mi = 0; mi < 4; mi++) {
#pragma unroll
        for (int h2 = 0; h2 < 2; h2++) {
            float m = -3.4e38f;
#pragma unroll
            for (int c = 0; c < 8; c++) {
                int col = c * 64 + warp * 8 + qc * 2;
                float v0 = acc[c][mi][2 * h2 + 0] * scale + biasS[col];
                float v1 = acc[c][mi][2 * h2 + 1] * scale + biasS[col + 1];
                acc[c][mi][2 * h2 + 0] = v0;
                acc[c][mi][2 * h2 + 1] = v1;
                m = fmaxf(m, fmaxf(v0, v1));
            }
            m = fmaxf(m, __shfl_xor_sync(0xFFFFFFFFu, m, 1));
            m = fmaxf(m, __shfl_xor_sync(0xFFFFFFFFu, m, 2));
            bm[mi][h2] = m;
        }
    }
    if (qc == 0) {
#pragma unroll
        for (int mi = 0; mi < 4; mi++)
#pragma unroll
            for (int h2 = 0; h2 < 2; h2++)
                red[(mi * 16 + qr + h2 * 8) * 9 + warp] = bm[mi][h2];
    }
    __syncthreads();
#pragma unroll
    for (int mi = 0; mi < 4; mi++)
#pragma unroll
        for (int h2 = 0; h2 < 2; h2++) {
            int row = mi * 16 + qr + h2 * 8;
            float m = red[row * 9 + 0];
#pragma unroll
            for (int w2 = 1; w2 < 8; w2++) m = fmaxf(m, red[row * 9 + w2]);
            bm[mi][h2] = m;
        }
    __syncthreads();
#pragma unroll
    for (int mi = 0; mi < 4; mi++) {
#pragma unroll
        for (int h2 = 0; h2 < 2; h2++) {
            float m = bm[mi][h2];
            float s = 0.f;
#pragma unroll
            for (int c = 0; c < 8; c++) {
                float e0 = __expf(acc[c][mi][2 * h2 + 0] - m);
                float e1 = __expf(acc[c][mi][2 * h2 + 1] - m);
                acc[c][mi][2 * h2 + 0] = e0;
                acc[c][mi][2 * h2 + 1] = e1;
                s += e0 + e1;
            }
            s += __shfl_xor_sync(0xFFFFFFFFu, s, 1);
            s += __shfl_xor_sync(0xFFFFFFFFu, s, 2);
            bs[mi][h2] = s;
        }
    }
    if (qc == 0) {
#pragma unroll
        for (int mi = 0; mi < 4; mi++)
#pragma unroll
            for (int h2 = 0; h2 < 2; h2++)
                red[(mi * 16 + qr + h2 * 8) * 9 + warp] = bs[mi][h2];
    }
    __syncthreads();
#pragma unroll
    for (int mi = 0; mi < 4; mi++)
#pragma unroll
        for (int h2 = 0; h2 < 2; h2++) {
            int row = mi * 16 + qr + h2 * 8;
            float s = 0.f;
#pragma unroll
            for (int w2 = 0; w2 < 8; w2++) s += red[row * 9 + w2];
            float inv = 1.f / s;
            float* orow = attn + ((size_t)bh * TS + m0 + row) * TS;
#pragma unroll
            for (int c = 0; c < 8; c++) {
                int col = c * 64 + warp * 8 + qc * 2;
                float2 o;
                o.x = acc[c][mi][2 * h2 + 0] * inv;
                o.y = acc[c][mi][2 * h2 + 1] * inv;
                *reinterpret_cast<float2*>(orow + col) = o;
            }
        }
}

// ---------------------------------------------------------------------------
// AV (tf32, raw-bit operands); epilogue now emits fp16 att concat.
// ---------------------------------------------------------------------------
__global__ __launch_bounds__(256) void attn_av_tc_kernel(
    const float* __restrict__ attn, const float* __restrict__ qkv,
    __half* __restrict__ outx) {
    __shared__ uint32_t Ps[64 * APITCH];
    __shared__ uint32_t Vs[64 * APITCH];

    const int t = threadIdx.x, lane = t & 31, warp = t >> 5;
    const int qr = lane >> 2, qc = lane & 3;
    const int bh = blockIdx.y, b = bh >> 3, h = bh & 7;
    const int m0 = blockIdx.x * 64;
    const int wr = (warp & 3) * 16;
    const int wc = (warp >> 2) * 32;
    const float* P = attn + (size_t)bh * TS * TS;
    const float* vb = qkv + (size_t)b * TS * QKVW + 2 * TE + h * THD;

    float acc[4][4] = {};

    float4 pv[4], vv[4];
#pragma unroll
    for (int i = 0; i < 4; i++) {
        int f4 = t + 256 * i;
        int row = f4 >> 4, kq = (f4 & 15) * 4;
        pv[i] = *reinterpret_cast<const float4*>(P + (size_t)(m0 + row) * TS + kq);
        vv[i] = *reinterpret_cast<const float4*>(vb + (size_t)row * QKVW + kq);
    }

    for (int kc = 0; kc < 8; kc++) {
        __syncthreads();
#pragma unroll
        for (int i = 0; i < 4; i++) {
            int f4 = t + 256 * i;
            int row = f4 >> 4, kq = (f4 & 15) * 4;
            uint32_t* sp = &Ps[row * APITCH + kq];
            sp[0] = __float_as_uint(pv[i].x); sp[1] = __float_as_uint(pv[i].y);
            sp[2] = __float_as_uint(pv[i].z); sp[3] = __float_as_uint(pv[i].w);
            uint32_t* sv = &Vs[row * APITCH + kq];
            sv[0] = __float_as_uint(vv[i].x); sv[1] = __float_as_uint(vv[i].y);
            sv[2] = __float_as_uint(vv[i].z); sv[3] = __float_as_uint(vv[i].w);
        }
        __syncthreads();
        if (kc < 7) {
#pragma unroll
            for (int i = 0; i < 4; i++) {
                int f4 = t + 256 * i;
                int row = f4 >> 4, kq = (f4 & 15) * 4;
                pv[i] = *reinterpret_cast<const float4*>(P + (size_t)(m0 + row) * TS + (kc + 1) * 64 + kq);
                vv[i] = *reinterpret_cast<const float4*>(vb + (size_t)((kc + 1) * 64 + row) * QKVW + kq);
            }
        }
#pragma unroll
        for (int kk = 0; kk < 64; kk += 8) {
            uint32_t a[4], bf[4][2];
            {
                const uint32_t* base = &Ps[(wr + qr) * APITCH + kk + qc];
                a[0] = base[0];
                a[1] = base[8 * APITCH];
                a[2] = base[4];
                a[3] = base[8 * APITCH + 4];
            }
#pragma unroll
            for (int ni = 0; ni < 4; ni++) {
                bf[ni][0] = Vs[(kk + qc) * APITCH + wc + ni * 8 + qr];
                bf[ni][1] = Vs[(kk + qc + 4) * APITCH + wc + ni * 8 + qr];
            }
#pragma unroll
            for (int ni = 0; ni < 4; ni++) MMA_TF32(acc[ni], a, bf[ni]);
        }
    }

#pragma unroll
    for (int ni = 0; ni < 4; ni++) {
#pragma unroll
        for (int h2 = 0; h2 < 2; h2++) {
            int row = m0 + wr + qr + h2 * 8;
            int col = wc + ni * 8 + qc * 2;
            *reinterpret_cast<__half2*>(outx + ((size_t)b * TS + row) * TE + h * THD + col) =
                __floats2half2_rn(acc[ni][2 * h2 + 0], acc[ni][2 * h2 + 1]);
        }
    }
}

// ---------------------------------------------------------------------------
// Fused residual + LayerNorm; writes fp32 x and fp16 twin.
// ---------------------------------------------------------------------------
__global__ __launch_bounds__(128) void add_ln_kernel(
    float* __restrict__ x, const float* __restrict__ y,
    const float* __restrict__ g, const float* __restrict__ bb,
    __half* __restrict__ x16) {
    const size_t row = blockIdx.x;
    const int t = threadIdx.x;
    float4 xv = reinterpret_cast<float4*>(x + row * TE)[t];
    float4 yv = reinterpret_cast<const float4*>(y + row * TE)[t];
    float4 s;
    s.x = xv.x + yv.x; s.y = xv.y + yv.y; s.z = xv.z + yv.z; s.w = xv.w + yv.w;
    float sum = s.x + s.y + s.z + s.w;
    float sq = s.x * s.x + s.y * s.y + s.z * s.z + s.w * s.w;
#pragma unroll
    for (int o = 16; o; o >>= 1) {
        sum += __shfl_xor_sync(0xFFFFFFFFu, sum, o);
        sq  += __shfl_xor_sync(0xFFFFFFFFu, sq, o);
    }
    __shared__ float s1[4], s2[4];
    if ((t & 31) == 0) { s1[t >> 5] = sum; s2[t >> 5] = sq; }
    __syncthreads();
    sum = s1[0] + s1[1] + s1[2] + s1[3];
    sq  = s2[0] + s2[1] + s2[2] + s2[3];
    const float mean = sum * (1.f / TE);
    const float var = sq * (1.f / TE) - mean * mean;
    const float rstd = rsqrtf(var + 1e-5f);
    float4 gv = reinterpret_cast<const float4*>(g)[t];
    float4 bv = reinterpret_cast<const float4*>(bb)[t];
    float4 o;
    o.x = (s.x - mean) * rstd * gv.x + bv.x;
    o.y = (s.y - mean) * rstd * gv.y + bv.y;
    o.z = (s.z - mean) * rstd * gv.z + bv.z;
    o.w = (s.w - mean) * rstd * gv.w + bv.w;
    reinterpret_cast<float4*>(x + row * TE)[t] = o;
    __half2* hx = reinterpret_cast<__half2*>(x16 + row * TE) + t * 2;
    hx[0] = __floats2half2_rn(o.x, o.y);
    hx[1] = __floats2half2_rn(o.z, o.w);
}

// ---------------------------------------------------------------------------
// CLS head
// ---------------------------------------------------------------------------
__global__ void cls_kernel(const float* __restrict__ x, const float* __restrict__ w,
                           const float* __restrict__ cb, float* __restrict__ out) {
    int t = threadIdx.x;
    if (t >= TB * 2) return;
    int b = t >> 1, c = t & 1;
    const float* xr = x + (size_t)b * TS * TE;
    const float* wr = w + c * TE;
    float s = cb[c];
    for (int e = 0; e < TE; e++) s = fmaf(xr[e], wr[e], s);
    out[b * 2 + c] = s;
}

// ---------------------------------------------------------------------------
extern "C" void kernel_launch(void* const* d_in, const int* in_sizes, int n_in,
                              void* d_out, int out_size) {
    const int*   ids  = (const int*)d_in[0];
    const int*   mask = (const int*)d_in[1];
    const float* emb  = (const float*)d_in[2];
    const float* pos  = (const float*)d_in[3];
    const float* ipw  = (const float*)d_in[4];
    const float* ipb  = (const float*)d_in[5];
    const float* opw  = (const float*)d_in[6];
    const float* opb  = (const float*)d_in[7];
    const float* l1g  = (const float*)d_in[8];
    const float* l1b  = (const float*)d_in[9];
    const float* l2g  = (const float*)d_in[10];
    const float* l2b  = (const float*)d_in[11];
    const float* f1w  = (const float*)d_in[12];
    const float* f1b  = (const float*)d_in[13];
    const float* f2w  = (const float*)d_in[14];
    const float* f2b  = (const float*)d_in[15];
    const float* cw   = (const float*)d_in[16];
    const float* cb   = (const float*)d_in[17];
    float* out = (float*)d_out;
    float* attn_base = out + TB * 2;

    float *x, *qkv, *y;
    __half *x16, *att16, *h16, *w16;
    cudaGetSymbolAddress((void**)&x,     g_x);
    cudaGetSymbolAddress((void**)&qkv,   g_qkv);
    cudaGetSymbolAddress((void**)&y,     g_y);
    cudaGetSymbolAddress((void**)&x16,   g_x16);
    cudaGetSymbolAddress((void**)&att16, g_att16);
    cudaGetSymbolAddress((void**)&h16,   g_h16);
    cudaGetSymbolAddress((void**)&w16,   g_w16);

    cudaFuncSetAttribute(hgemm_kernel<0, 0>, cudaFuncAttributeMaxDynamicSharedMemorySize, HG_SMEM);
    cudaFuncSetAttribute(hgemm_kernel<1, 1>, cudaFuncAttributeMaxDynamicSharedMemorySize, HG_SMEM);

    cvtw_kernel<<<W16_TOTAL / 4 / 256, 256>>>(ipw, opw, f1w, f2w, w16);
    embed_kernel<<<(TT * 128) / 256, 256>>>(ids, emb, pos, x, x16);

    for (int l = 0; l < TL; l++) {
        hgemm_kernel<0, 0><<<dim3(QKVW / 128, TT / 128), 128, HG_SMEM>>>(
            x16, w16 + W16_IPW(l), ipb + l * QKVW, qkv, nullptr, QKVW, TE);

        float* attn_l = attn_base + (size_t)l * TB * TNH * TS * TS;
        attn_fused_kernel<<<dim3(8, TB * TNH), 256>>>(qkv, mask, attn_l);
        attn_av_tc_kernel<<<dim3(8, TB * TNH), 256>>>(attn_l, qkv, att16);

        hgemm_kernel<0, 0><<<dim3(TE / 128, TT / 128), 128, HG_SMEM>>>(
            att16, w16 + W16_OPW(l), opb + l * TE, y, nullptr, TE, TE);
        add_ln_kernel<<<TT, 128>>>(x, y, l1g + l * TE, l1b + l * TE, x16);

        hgemm_kernel<1, 1><<<dim3(4 * TE / 128, TT / 128), 128, HG_SMEM>>>(
            x16, w16 + W16_F1W(l), f1b + l * 4 * TE, nullptr, h16, 4 * TE, TE);
        hgemm_kernel<0, 0><<<dim3(TE / 128, TT / 128), 128, HG_SMEM>>>(
            h16, w16 + W16_F2W(l), f2b + l * TE, y, nullptr, TE, 4 * TE);
        add_ln_kernel<<<TT, 128>>>(x, y, l2g + l * TE, l2b + l * TE, x16);
    }

    cls_kernel<<<1, 64>>>(x, cw, cb, out);
}

// round 8
// speedup vs baseline: 2.0440x; 1.2579x over previous
#include <cuda_runtime.h>
#include <cuda_fp16.h>
#include <cstdint>
#include <math.h>

// Problem constants
#define TB 32      // batch
#define TS 512     // seq len
#define TE 512     // d_model
#define THD 64     // head dim
#define TNH 8      // heads
#define TL 3       // layers
#define TT (TB*TS) // tokens = 16384
#define QKVW 1536  // 3*E

// Scratch (device globals; allocation-free contract)
__device__ float  g_x[(size_t)TT * TE];        // running hidden fp32   32 MB
__device__ float  g_y[(size_t)TT * TE];        // gemm out fp32         32 MB
__device__ __half g_qkv16[(size_t)TT * QKVW];  // qkv fp16              48 MB
__device__ __half g_x16[(size_t)TT * TE];      // hidden fp16           16 MB
__device__ __half g_att16[(size_t)TT * TE];    // attn concat fp16      16 MB
__device__ __half g_h16[(size_t)TT * 4 * TE];  // ffn hidden fp16       64 MB
#define W16_TOTAL 9437184
__device__ __half g_w16[W16_TOTAL];            // all weights fp16      18 MB
#define W16_IPW(l) ((size_t)(l) * 786432)
#define W16_OPW(l) (2359296 + (size_t)(l) * 262144)
#define W16_F1W(l) (3145728 + (size_t)(l) * 1048576)
#define W16_F2W(l) (6291456 + (size_t)(l) * 1048576)

#define MMA_TF32(d, a, b)                                                     \
    asm volatile(                                                             \
        "mma.sync.aligned.m16n8k8.row.col.f32.tf32.tf32.f32 "                 \
        "{%0,%1,%2,%3}, {%4,%5,%6,%7}, {%8,%9}, {%0,%1,%2,%3};"               \
        : "+f"(d[0]), "+f"(d[1]), "+f"(d[2]), "+f"(d[3])                      \
        : "r"(a[0]), "r"(a[1]), "r"(a[2]), "r"(a[3]), "r"(b[0]), "r"(b[1]))

#define MMA_F16(d, a, b)                                                      \
    asm volatile(                                                             \
        "mma.sync.aligned.m16n8k16.row.col.f32.f16.f16.f32 "                  \
        "{%0,%1,%2,%3}, {%4,%5,%6,%7}, {%8,%9}, {%0,%1,%2,%3};"               \
        : "+f"(d[0]), "+f"(d[1]), "+f"(d[2]), "+f"(d[3])                      \
        : "r"(a[0]), "r"(a[1]), "r"(a[2]), "r"(a[3]), "r"(b[0]), "r"(b[1]))

#define LDSM4(r0, r1, r2, r3, addr)                                           \
    asm volatile("ldmatrix.sync.aligned.m8n8.x4.shared.b16 {%0,%1,%2,%3}, [%4];" \
        : "=r"(r0), "=r"(r1), "=r"(r2), "=r"(r3) : "r"(addr))

#define LDSM2(r0, r1, addr)                                                   \
    asm volatile("ldmatrix.sync.aligned.m8n8.x2.shared.b16 {%0,%1}, [%2];"    \
        : "=r"(r0), "=r"(r1) : "r"(addr))

__device__ __forceinline__ void cpa16(uint32_t s, const void* g) {
    asm volatile("cp.async.cg.shared.global [%0], [%1], 16;" :: "r"(s), "l"(g));
}
__device__ __forceinline__ void cpa_commit() {
    asm volatile("cp.async.commit_group;");
}

// fp16 tile swizzles: chunk = 16B unit
// 64B-pitch rows (32 halfs) for hgemm
__device__ __forceinline__ uint32_t hswz(int row, int chunk) {
    return (uint32_t)(row * 64 + (((chunk + (row >> 1)) & 3) << 4));
}
// 128B-pitch rows (64 halfs) for attention tiles
#define ASWZ(row, c8) ((uint32_t)(((row) << 7) | ((((c8) ^ ((row) & 7))) << 4)))

// ---------------------------------------------------------------------------
// Weight conversion fp32 -> fp16 (once per launch, ~40us)
// ---------------------------------------------------------------------------
__global__ __launch_bounds__(256) void cvtw_kernel(
    const float* __restrict__ ipw, const float* __restrict__ opw,
    const float* __restrict__ f1w, const float* __restrict__ f2w,
    __half* __restrict__ w16) {
    size_t i = ((size_t)blockIdx.x * 256 + threadIdx.x) * 4;
    const float* src; size_t off;
    if (i < 2359296)      { src = ipw; off = i; }
    else if (i < 3145728) { src = opw; off = i - 2359296; }
    else if (i < 6291456) { src = f1w; off = i - 3145728; }
    else                  { src = f2w; off = i - 6291456; }
    float4 v = *reinterpret_cast<const float4*>(src + off);
    __half2* dst = reinterpret_cast<__half2*>(w16 + i);
    dst[0] = __floats2half2_rn(v.x, v.y);
    dst[1] = __floats2half2_rn(v.z, v.w);
}

// ---------------------------------------------------------------------------
// Embedding: x fp32 + fp16 twin
// ---------------------------------------------------------------------------
__global__ __launch_bounds__(256) void embed_kernel(
    const int* __restrict__ ids, const float* __restrict__ emb,
    const float* __restrict__ pos, float* __restrict__ x, __half* __restrict__ x16) {
    int idx = blockIdx.x * blockDim.x + threadIdx.x;
    int token = idx >> 7;
    int c = idx & 127;
    float4 e = reinterpret_cast<const float4*>(emb)[(size_t)ids[token] * 128 + c];
    float4 p = reinterpret_cast<const float4*>(pos)[(size_t)(token & (TS - 1)) * 128 + c];
    float4 o;
    o.x = e.x + p.x; o.y = e.y + p.y; o.z = e.z + p.z; o.w = e.w + p.w;
    reinterpret_cast<float4*>(x)[idx] = o;
    __half2* h = reinterpret_cast<__half2*>(x16) + idx * 2;
    h[0] = __floats2half2_rn(o.x, o.y);
    h[1] = __floats2half2_rn(o.z, o.w);
}

// ---------------------------------------------------------------------------
// FP16 tensor-core GEMM (proven round-7): C = A @ W^T + bias, opt GELU,
// fp32 or fp16 output. Block 128x128, 128 thr, warp tile 64x64, 4-stage ring.
// ---------------------------------------------------------------------------
#define HSTG 16384
#define HG_SMEM (4 * HSTG)

template <int ACT, int OUT16>
__global__ __launch_bounds__(128, 2) void hgemm_kernel(
    const __half* __restrict__ A, const __half* __restrict__ W,
    const float* __restrict__ bias, float* __restrict__ C,
    __half* __restrict__ C16, int N, int K) {
    extern __shared__ char smraw[];
    uint32_t base;
    asm("{ .reg .u64 t; cvta.to.shared.u64 t, %1; cvt.u32.u64 %0, t; }"
        : "=r"(base) : "l"(smraw));

    const int t = threadIdx.x;
    const int lane = t & 31;
    const int warp = t >> 5;
    const int wr = (warp >> 1) * 64;
    const int wc = (warp & 1) * 64;
    const int qr = lane >> 2;
    const int qc = lane & 3;

    const int m0 = blockIdx.y * 128;
    const int n0 = blockIdx.x * 128;
    const int KT = K >> 5;

    const int arow = lane & 15;
    const int achk = lane >> 4;
    const int brow = lane & 7;
    const int bchk = (lane >> 3) & 1;

    float acc[4][8][4];
#pragma unroll
    for (int i = 0; i < 4; i++)
#pragma unroll
        for (int j = 0; j < 8; j++)
#pragma unroll
            for (int r = 0; r < 4; r++) acc[i][j][r] = 0.f;

#pragma unroll
    for (int s = 0; s < 3; s++) {
        uint32_t sb = base + s * HSTG;
#pragma unroll
        for (int i = 0; i < 4; i++) {
            int idx = t + 128 * i;
            int row = idx >> 2, c = idx & 3;
            cpa16(sb + hswz(row, c), A + (size_t)(m0 + row) * K + s * 32 + c * 8);
            cpa16(sb + 8192 + hswz(row, c), W + (size_t)(n0 + row) * K + s * 32 + c * 8);
        }
        cpa_commit();
    }

    for (int kt = 0; kt < KT; kt++) {
        int pend = KT - 1 - kt; if (pend > 2) pend = 2;
        if (pend == 2)      asm volatile("cp.async.wait_group 2;");
        else if (pend == 1) asm volatile("cp.async.wait_group 1;");
        else                asm volatile("cp.async.wait_group 0;");
        __syncthreads();

        if (kt + 3 < KT) {
            int j = kt + 3;
            uint32_t sb = base + (j & 3) * HSTG;
#pragma unroll
            for (int i = 0; i < 4; i++) {
                int idx = t + 128 * i;
                int row = idx >> 2, c = idx & 3;
                cpa16(sb + hswz(row, c), A + (size_t)(m0 + row) * K + j * 32 + c * 8);
                cpa16(sb + 8192 + hswz(row, c), W + (size_t)(n0 + row) * K + j * 32 + c * 8);
            }
            cpa_commit();
        } else {
            cpa_commit();
        }

        const uint32_t sb = base + (kt & 3) * HSTG;
#pragma unroll
        for (int s2 = 0; s2 < 2; s2++) {
            uint32_t a[4][4], bw[8][2];
#pragma unroll
            for (int mi = 0; mi < 4; mi++) {
                uint32_t ad = sb + hswz(wr + mi * 16 + arow, 2 * s2 + achk);
                LDSM4(a[mi][0], a[mi][1], a[mi][2], a[mi][3], ad);
            }
#pragma unroll
            for (int ni = 0; ni < 8; ni++) {
                uint32_t bd = sb + 8192 + hswz(wc + ni * 8 + brow, 2 * s2 + bchk);
                LDSM2(bw[ni][0], bw[ni][1], bd);
            }
#pragma unroll
            for (int mi = 0; mi < 4; mi++)
#pragma unroll
                for (int ni = 0; ni < 8; ni++) MMA_F16(acc[mi][ni], a[mi], bw[ni]);
        }
    }

#pragma unroll
    for (int mi = 0; mi < 4; mi++) {
#pragma unroll
        for (int ni = 0; ni < 8; ni++) {
            int col = n0 + wc + ni * 8 + qc * 2;
            float b0 = bias[col], b1 = bias[col + 1];
#pragma unroll
            for (int half = 0; half < 2; half++) {
                int row = m0 + wr + mi * 16 + qr + half * 8;
                float v0 = acc[mi][ni][half * 2 + 0] + b0;
                float v1 = acc[mi][ni][half * 2 + 1] + b1;
                if (ACT == 1) {
                    v0 = 0.5f * v0 * (1.f + erff(v0 * 0.70710678118654752f));
                    v1 = 0.5f * v1 * (1.f + erff(v1 * 0.70710678118654752f));
                }
                if (OUT16) {
                    *reinterpret_cast<__half2*>(C16 + (size_t)row * N + col) =
                        __floats2half2_rn(v0, v1);
                } else {
                    float2 o; o.x = v0; o.y = v1;
                    *reinterpret_cast<float2*>(C + (size_t)row * N + col) = o;
                }
            }
        }
    }
}

// ---------------------------------------------------------------------------
// Fused attention scores + softmax, fp16 tensor cores.
// Block: 32 q-rows x 512 keys for one (b,h); 256 thr; warp w owns key cols
// {chunk*64 + w*8} over 8 chunks. K triple-buffered via cp.async.
// Writes normalized fp32 probabilities directly.
// ---------------------------------------------------------------------------
__global__ __launch_bounds__(256, 2) void attn_fused16_kernel(
    const __half* __restrict__ qkv16, const int* __restrict__ mask,
    float* __restrict__ attn) {
    __shared__ __align__(128) char smQ[32 * 128];     // 4 KB
    __shared__ __align__(128) char smK[3 * 64 * 128]; // 24 KB
    __shared__ float biasS[512];
    __shared__ float red[32 * 9];

    const int t = threadIdx.x, lane = t & 31, warp = t >> 5;
    const int qr = lane >> 2, qc = lane & 3;
    const int bh = blockIdx.y, b = bh >> 3, h = bh & 7;
    const int m0 = blockIdx.x * 32;
    const __half* qb = qkv16 + (size_t)b * TS * QKVW + h * THD;
    const __half* kb = qb + TE;

    uint32_t qbase = (uint32_t)__cvta_generic_to_shared(smQ);
    uint32_t kbase = (uint32_t)__cvta_generic_to_shared(smK);

    for (int i = t; i < 512; i += 256)
        biasS[i] = (mask[b * TS + i] == 0) ? -1e30f : 0.f;

    // Q tile (32x64 fp16) + K chunk 0 -> group 0
    {
        int row = t >> 3, c8 = t & 7;
        cpa16(qbase + ASWZ(row, c8), qb + (size_t)(m0 + row) * QKVW + c8 * 8);
#pragma unroll
        for (int i = 0; i < 2; i++) {
            int u = t + 256 * i;
            int kr = u >> 3, kc = u & 7;
            cpa16(kbase + ASWZ(kr, kc), kb + (size_t)kr * QKVW + kc * 8);
        }
    }
    cpa_commit();
    // K chunk 1 -> group 1
    {
#pragma unroll
        for (int i = 0; i < 2; i++) {
            int u = t + 256 * i;
            int kr = u >> 3, kc = u & 7;
            cpa16(kbase + 8192 + ASWZ(kr, kc), kb + (size_t)(64 + kr) * QKVW + kc * 8);
        }
    }
    cpa_commit();

    float acc[8][2][4];
#pragma unroll
    for (int c = 0; c < 8; c++)
#pragma unroll
        for (int mi = 0; mi < 2; mi++)
#pragma unroll
            for (int r = 0; r < 4; r++) acc[c][mi][r] = 0.f;

    const int arow = lane & 15, achk = lane >> 4;
    const int brow = lane & 7, bchk = (lane >> 3) & 1;

    for (int c = 0; c < 8; c++) {
        if (c < 7) asm volatile("cp.async.wait_group 1;");
        else       asm volatile("cp.async.wait_group 0;");
        __syncthreads();

        if (c + 2 < 8) {
            uint32_t kbn = kbase + ((c + 2) % 3) * 8192;
#pragma unroll
            for (int i = 0; i < 2; i++) {
                int u = t + 256 * i;
                int kr = u >> 3, kc = u & 7;
                cpa16(kbn + ASWZ(kr, kc), kb + (size_t)((c + 2) * 64 + kr) * QKVW + kc * 8);
            }
            cpa_commit();
        }

        const uint32_t kbc = kbase + (c % 3) * 8192;
#pragma unroll
        for (int s = 0; s < 4; s++) {
            uint32_t a[2][4], bw[2];
#pragma unroll
            for (int mi = 0; mi < 2; mi++)
                LDSM4(a[mi][0], a[mi][1], a[mi][2], a[mi][3],
                      qbase + ASWZ(mi * 16 + arow, 2 * s + achk));
            LDSM2(bw[0], bw[1], kbc + ASWZ(warp * 8 + brow, 2 * s + bchk));
#pragma unroll
            for (int mi = 0; mi < 2; mi++) MMA_F16(acc[c][mi], a[mi], bw);
        }
    }

    // ---- softmax over 512 keys per row (32 rows) ----
    float bm[2][2], bs[2][2];
    const float scale = 0.125f;
#pragma unroll
    for (int mi = 0; mi < 2; mi++) {
#pragma unroll
        for (int h2 = 0; h2 < 2; h2++) {
            float m = -3.4e38f;
#pragma unroll
            for (int c = 0; c < 8; c++) {
                int col = c * 64 + warp * 8 + qc * 2;
                float v0 = acc[c][mi][2 * h2 + 0] * scale + biasS[col];
                float v1 = acc[c][mi][2 * h2 + 1] * scale + biasS[col + 1];
                acc[c][mi][2 * h2 + 0] = v0;
                acc[c][mi][2 * h2 + 1] = v1;
                m = fmaxf(m, fmaxf(v0, v1));
            }
            m = fmaxf(m, __shfl_xor_sync(0xFFFFFFFFu, m, 1));
            m = fmaxf(m, __shfl_xor_sync(0xFFFFFFFFu, m, 2));
            bm[mi][h2] = m;
        }
    }
    if (qc == 0) {
#pragma unroll
        for (int mi = 0; mi < 2; mi++)
#pragma unroll
            for (int h2 = 0; h2 < 2; h2++)
                red[(mi * 16 + qr + h2 * 8) * 9 + warp] = bm[mi][h2];
    }
    __syncthreads();
#pragma unroll
    for (int mi = 0; mi < 2; mi++)
#pragma unroll
        for (int h2 = 0; h2 < 2; h2++) {
            int row = mi * 16 + qr + h2 * 8;
            float m = red[row * 9 + 0];
#pragma unroll
            for (int w2 = 1; w2 < 8; w2++) m = fmaxf(m, red[row * 9 + w2]);
            bm[mi][h2] = m;
        }
    __syncthreads();
#pragma unroll
    for (int mi = 0; mi < 2; mi++) {
#pragma unroll
        for (int h2 = 0; h2 < 2; h2++) {
            float m = bm[mi][h2];
            float s = 0.f;
#pragma unroll
            for (int c = 0; c < 8; c++) {
                float e0 = __expf(acc[c][mi][2 * h2 + 0] - m);
                float e1 = __expf(acc[c][mi][2 * h2 + 1] - m);
                acc[c][mi][2 * h2 + 0] = e0;
                acc[c][mi][2 * h2 + 1] = e1;
                s += e0 + e1;
            }
            s += __shfl_xor_sync(0xFFFFFFFFu, s, 1);
            s += __shfl_xor_sync(0xFFFFFFFFu, s, 2);
            bs[mi][h2] = s;
        }
    }
    if (qc == 0) {
#pragma unroll
        for (int mi = 0; mi < 2; mi++)
#pragma unroll
            for (int h2 = 0; h2 < 2; h2++)
                red[(mi * 16 + qr + h2 * 8) * 9 + warp] = bs[mi][h2];
    }
    __syncthreads();
#pragma unroll
    for (int mi = 0; mi < 2; mi++)
#pragma unroll
        for (int h2 = 0; h2 < 2; h2++) {
            int row = mi * 16 + qr + h2 * 8;
            float s = 0.f;
#pragma unroll
            for (int w2 = 0; w2 < 8; w2++) s += red[row * 9 + w2];
            float inv = 1.f / s;
            float* orow = attn + ((size_t)bh * TS + m0 + row) * TS;
#pragma unroll
            for (int c = 0; c < 8; c++) {
                int col = c * 64 + warp * 8 + qc * 2;
                float2 o;
                o.x = acc[c][mi][2 * h2 + 0] * inv;
                o.y = acc[c][mi][2 * h2 + 1] * inv;
                *reinterpret_cast<float2*>(orow + col) = o;
            }
        }
}

// ---------------------------------------------------------------------------
// AV (tf32, proven structure); V now sourced from fp16 qkv16.
// ---------------------------------------------------------------------------
#define APITCH 68

__global__ __launch_bounds__(256) void attn_av_tc_kernel(
    const float* __restrict__ attn, const __half* __restrict__ qkv16,
    __half* __restrict__ outx) {
    __shared__ uint32_t Ps[64 * APITCH];
    __shared__ uint32_t Vs[64 * APITCH];

    const int t = threadIdx.x, lane = t & 31, warp = t >> 5;
    const int qr = lane >> 2, qc = lane & 3;
    const int bh = blockIdx.y, b = bh >> 3, h = bh & 7;
    const int m0 = blockIdx.x * 64;
    const int wr = (warp & 3) * 16;
    const int wc = (warp >> 2) * 32;
    const float* P = attn + (size_t)bh * TS * TS;
    const __half* vb = qkv16 + (size_t)b * TS * QKVW + 2 * TE + h * THD;

    float acc[4][4] = {};

    float4 pv[4];
    uint4 vv[2];
#pragma unroll
    for (int i = 0; i < 4; i++) {
        int f4 = t + 256 * i;
        int row = f4 >> 4, kq = (f4 & 15) * 4;
        pv[i] = *reinterpret_cast<const float4*>(P + (size_t)(m0 + row) * TS + kq);
    }
#pragma unroll
    for (int i = 0; i < 2; i++) {
        int u = t + 256 * i;
        int row = u >> 3, c8 = u & 7;
        vv[i] = *reinterpret_cast<const uint4*>(vb + (size_t)row * QKVW + c8 * 8);
    }

    for (int kc = 0; kc < 8; kc++) {
        __syncthreads();
#pragma unroll
        for (int i = 0; i < 4; i++) {
            int f4 = t + 256 * i;
            int row = f4 >> 4, kq = (f4 & 15) * 4;
            uint32_t* sp = &Ps[row * APITCH + kq];
            sp[0] = __float_as_uint(pv[i].x); sp[1] = __float_as_uint(pv[i].y);
            sp[2] = __float_as_uint(pv[i].z); sp[3] = __float_as_uint(pv[i].w);
        }
#pragma unroll
        for (int i = 0; i < 2; i++) {
            int u = t + 256 * i;
            int row = u >> 3, c8 = u & 7;
            const __half2* hp = reinterpret_cast<const __half2*>(&vv[i]);
            uint32_t* sv = &Vs[row * APITCH + c8 * 8];
#pragma unroll
            for (int j = 0; j < 4; j++) {
                float2 f = __half22float2(hp[j]);
                sv[2 * j + 0] = __float_as_uint(f.x);
                sv[2 * j + 1] = __float_as_uint(f.y);
            }
        }
        __syncthreads();
        if (kc < 7) {
#pragma unroll
            for (int i = 0; i < 4; i++) {
                int f4 = t + 256 * i;
                int row = f4 >> 4, kq = (f4 & 15) * 4;
                pv[i] = *reinterpret_cast<const float4*>(P + (size_t)(m0 + row) * TS + (kc + 1) * 64 + kq);
            }
#pragma unroll
            for (int i = 0; i < 2; i++) {
                int u = t + 256 * i;
                int row = u >> 3, c8 = u & 7;
                vv[i] = *reinterpret_cast<const uint4*>(vb + (size_t)((kc + 1) * 64 + row) * QKVW + c8 * 8);
            }
        }
#pragma unroll
        for (int kk = 0; kk < 64; kk += 8) {
            uint32_t a[4], bf[4][2];
            {
                const uint32_t* base = &Ps[(wr + qr) * APITCH + kk + qc];
                a[0] = base[0];
                a[1] = base[8 * APITCH];
                a[2] = base[4];
                a[3] = base[8 * APITCH + 4];
            }
#pragma unroll
            for (int ni = 0; ni < 4; ni++) {
                bf[ni][0] = Vs[(kk + qc) * APITCH + wc + ni * 8 + qr];
                bf[ni][1] = Vs[(kk + qc + 4) * APITCH + wc + ni * 8 + qr];
            }
#pragma unroll
            for (int ni = 0; ni < 4; ni++) MMA_TF32(acc[ni], a, bf[ni]);
        }
    }

#pragma unroll
    for (int ni = 0; ni < 4; ni++) {
#pragma unroll
        for (int h2 = 0; h2 < 2; h2++) {
            int row = m0 + wr + qr + h2 * 8;
            int col = wc + ni * 8 + qc * 2;
            *reinterpret_cast<__half2*>(outx + ((size_t)b * TS + row) * TE + h * THD + col) =
                __floats2half2_rn(acc[ni][2 * h2 + 0], acc[ni][2 * h2 + 1]);
        }
    }
}

// ---------------------------------------------------------------------------
// Fused residual + LayerNorm; writes fp32 x and fp16 twin.
// ---------------------------------------------------------------------------
__global__ __launch_bounds__(128) void add_ln_kernel(
    float* __restrict__ x, const float* __restrict__ y,
    const float* __restrict__ g, const float* __restrict__ bb,
    __half* __restrict__ x16) {
    const size_t row = blockIdx.x;
    const int t = threadIdx.x;
    float4 xv = reinterpret_cast<float4*>(x + row * TE)[t];
    float4 yv = reinterpret_cast<const float4*>(y + row * TE)[t];
    float4 s;
    s.x = xv.x + yv.x; s.y = xv.y + yv.y; s.z = xv.z + yv.z; s.w = xv.w + yv.w;
    float sum = s.x + s.y + s.z + s.w;
    float sq = s.x * s.x + s.y * s.y + s.z * s.z + s.w * s.w;
#pragma unroll
    for (int o = 16; o; o >>= 1) {
        sum += __shfl_xor_sync(0xFFFFFFFFu, sum, o);
        sq  += __shfl_xor_sync(0xFFFFFFFFu, sq, o);
    }
    __shared__ float s1[4], s2[4];
    if ((t & 31) == 0) { s1[t >> 5] = sum; s2[t >> 5] = sq; }
    __syncthreads();
    sum = s1[0] + s1[1] + s1[2] + s1[3];
    sq  = s2[0] + s2[1] + s2[2] + s2[3];
    const float mean = sum * (1.f / TE);
    const float var = sq * (1.f / TE) - mean * mean;
    const float rstd = rsqrtf(var + 1e-5f);
    float4 gv = reinterpret_cast<const float4*>(g)[t];
    float4 bv = reinterpret_cast<const float4*>(bb)[t];
    float4 o;
    o.x = (s.x - mean) * rstd * gv.x + bv.x;
    o.y = (s.y - mean) * rstd * gv.y + bv.y;
    o.z = (s.z - mean) * rstd * gv.z + bv.z;
    o.w = (s.w - mean) * rstd * gv.w + bv.w;
    reinterpret_cast<float4*>(x + row * TE)[t] = o;
    __half2* hx = reinterpret_cast<__half2*>(x16 + row * TE) + t * 2;
    hx[0] = __floats2half2_rn(o.x, o.y);
    hx[1] = __floats2half2_rn(o.z, o.w);
}

// ---------------------------------------------------------------------------
// CLS head
// ---------------------------------------------------------------------------
__global__ void cls_kernel(const float* __restrict__ x, const float* __restrict__ w,
                           const float* __restrict__ cb, float* __restrict__ out) {
    int t = threadIdx.x;
    if (t >= TB * 2) return;
    int b = t >> 1, c = t & 1;
    const float* xr = x + (size_t)b * TS * TE;
    const float* wr = w + c * TE;
    float s = cb[c];
    for (int e = 0; e < TE; e++) s = fmaf(xr[e], wr[e], s);
    out[b * 2 + c] = s;
}

// ---------------------------------------------------------------------------
extern "C" void kernel_launch(void* const* d_in, const int* in_sizes, int n_in,
                              void* d_out, int out_size) {
    const int*   ids  = (const int*)d_in[0];
    const int*   mask = (const int*)d_in[1];
    const float* emb  = (const float*)d_in[2];
    const float* pos  = (const float*)d_in[3];
    const float* ipw  = (const float*)d_in[4];
    const float* ipb  = (const float*)d_in[5];
    const float* opw  = (const float*)d_in[6];
    const float* opb  = (const float*)d_in[7];
    const float* l1g  = (const float*)d_in[8];
    const float* l1b  = (const float*)d_in[9];
    const float* l2g  = (const float*)d_in[10];
    const float* l2b  = (const float*)d_in[11];
    const float* f1w  = (const float*)d_in[12];
    const float* f1b  = (const float*)d_in[13];
    const float* f2w  = (const float*)d_in[14];
    const float* f2b  = (const float*)d_in[15];
    const float* cw   = (const float*)d_in[16];
    const float* cb   = (const float*)d_in[17];
    float* out = (float*)d_out;
    float* attn_base = out + TB * 2;

    float *x, *y;
    __half *qkv16, *x16, *att16, *h16, *w16;
    cudaGetSymbolAddress((void**)&x,      g_x);
    cudaGetSymbolAddress((void**)&y,      g_y);
    cudaGetSymbolAddress((void**)&qkv16,  g_qkv16);
    cudaGetSymbolAddress((void**)&x16,    g_x16);
    cudaGetSymbolAddress((void**)&att16,  g_att16);
    cudaGetSymbolAddress((void**)&h16,    g_h16);
    cudaGetSymbolAddress((void**)&w16,    g_w16);

    cudaFuncSetAttribute(hgemm_kernel<0, 0>, cudaFuncAttributeMaxDynamicSharedMemorySize, HG_SMEM);
    cudaFuncSetAttribute(hgemm_kernel<0, 1>, cudaFuncAttributeMaxDynamicSharedMemorySize, HG_SMEM);
    cudaFuncSetAttribute(hgemm_kernel<1, 1>, cudaFuncAttributeMaxDynamicSharedMemorySize, HG_SMEM);

    cvtw_kernel<<<W16_TOTAL / 4 / 256, 256>>>(ipw, opw, f1w, f2w, w16);
    embed_kernel<<<(TT * 128) / 256, 256>>>(ids, emb, pos, x, x16);

    for (int l = 0; l < TL; l++) {
        hgemm_kernel<0, 1><<<dim3(QKVW / 128, TT / 128), 128, HG_SMEM>>>(
            x16, w16 + W16_IPW(l), ipb + l * QKVW, nullptr, qkv16, QKVW, TE);

        float* attn_l = attn_base + (size_t)l * TB * TNH * TS * TS;
        attn_fused16_kernel<<<dim3(16, TB * TNH), 256>>>(qkv16, mask, attn_l);
        attn_av_tc_kernel<<<dim3(8, TB * TNH), 256>>>(attn_l, qkv16, att16);

        hgemm_kernel<0, 0><<<dim3(TE / 128, TT / 128), 128, HG_SMEM>>>(
            att16, w16 + W16_OPW(l), opb + l * TE, y, nullptr, TE, TE);
        add_ln_kernel<<<TT, 128>>>(x, y, l1g + l * TE, l1b + l * TE, x16);

        hgemm_kernel<1, 1><<<dim3(4 * TE / 128, TT / 128), 128, HG_SMEM>>>(
            x16, w16 + W16_F1W(l), f1b + l * 4 * TE, nullptr, h16, 4 * TE, TE);
        hgemm_kernel<0, 0><<<dim3(TE / 128, TT / 128), 128, HG_SMEM>>>(
            h16, w16 + W16_F2W(l), f2b + l * TE, y, nullptr, TE, 4 * TE);
        add_ln_kernel<<<TT, 128>>>(x, y, l2g + l * TE, l2b + l * TE, x16);
    }

    cls_kernel<<<1, 64>>>(x, cw, cb, out);
}

// round 9
// speedup vs baseline: 2.2143x; 1.0833x over previous
#include <cuda_runtime.h>
#include <cuda_fp16.h>
#include <cstdint>
#include <math.h>

// Problem constants
#define TB 32      // batch
#define TS 512     // seq len
#define TE 512     // d_model
#define THD 64     // head dim
#define TNH 8      // heads
#define TL 3       // layers
#define TT (TB*TS) // tokens = 16384
#define QKVW 1536  // 3*E

// Scratch (device globals; allocation-free contract)
__device__ float  g_x[(size_t)TT * TE];        // running hidden fp32   32 MB
__device__ float  g_y[(size_t)TT * TE];        // gemm out fp32         32 MB
__device__ __half g_qkv16[(size_t)TT * QKVW];  // qkv fp16              48 MB
__device__ __half g_x16[(size_t)TT * TE];      // hidden fp16           16 MB
__device__ __half g_att16[(size_t)TT * TE];    // attn concat fp16      16 MB
__device__ __half g_h16[(size_t)TT * 4 * TE];  // ffn hidden fp16       64 MB
__device__ __half g_p16[(size_t)TB * TNH * TS * TS];  // probs fp16    134 MB
#define W16_TOTAL 9437184
__device__ __half g_w16[W16_TOTAL];            // all weights fp16      18 MB
#define W16_IPW(l) ((size_t)(l) * 786432)
#define W16_OPW(l) (2359296 + (size_t)(l) * 262144)
#define W16_F1W(l) (3145728 + (size_t)(l) * 1048576)
#define W16_F2W(l) (6291456 + (size_t)(l) * 1048576)

#define MMA_F16(d, a, b)                                                      \
    asm volatile(                                                             \
        "mma.sync.aligned.m16n8k16.row.col.f32.f16.f16.f32 "                  \
        "{%0,%1,%2,%3}, {%4,%5,%6,%7}, {%8,%9}, {%0,%1,%2,%3};"               \
        : "+f"(d[0]), "+f"(d[1]), "+f"(d[2]), "+f"(d[3])                      \
        : "r"(a[0]), "r"(a[1]), "r"(a[2]), "r"(a[3]), "r"(b[0]), "r"(b[1]))

#define LDSM4(r0, r1, r2, r3, addr)                                           \
    asm volatile("ldmatrix.sync.aligned.m8n8.x4.shared.b16 {%0,%1,%2,%3}, [%4];" \
        : "=r"(r0), "=r"(r1), "=r"(r2), "=r"(r3) : "r"(addr))

#define LDSM2(r0, r1, addr)                                                   \
    asm volatile("ldmatrix.sync.aligned.m8n8.x2.shared.b16 {%0,%1}, [%2];"    \
        : "=r"(r0), "=r"(r1) : "r"(addr))

#define LDSM2T(r0, r1, addr)                                                  \
    asm volatile("ldmatrix.sync.aligned.m8n8.x2.trans.shared.b16 {%0,%1}, [%2];" \
        : "=r"(r0), "=r"(r1) : "r"(addr))

__device__ __forceinline__ void cpa16(uint32_t s, const void* g) {
    asm volatile("cp.async.cg.shared.global [%0], [%1], 16;" :: "r"(s), "l"(g));
}
__device__ __forceinline__ void cpa_commit() {
    asm volatile("cp.async.commit_group;");
}

// fp16 tile swizzles: chunk = 16B unit
// 64B-pitch rows (32 halfs) for hgemm
__device__ __forceinline__ uint32_t hswz(int row, int chunk) {
    return (uint32_t)(row * 64 + (((chunk + (row >> 1)) & 3) << 4));
}
// 128B-pitch rows (64 halfs) for attention tiles
#define ASWZ(row, c8) ((uint32_t)(((row) << 7) | ((((c8) ^ ((row) & 7))) << 4)))

// ---------------------------------------------------------------------------
// Weight conversion fp32 -> fp16 (once per launch, ~40us)
// ---------------------------------------------------------------------------
__global__ __launch_bounds__(256) void cvtw_kernel(
    const float* __restrict__ ipw, const float* __restrict__ opw,
    const float* __restrict__ f1w, const float* __restrict__ f2w,
    __half* __restrict__ w16) {
    size_t i = ((size_t)blockIdx.x * 256 + threadIdx.x) * 4;
    const float* src; size_t off;
    if (i < 2359296)      { src = ipw; off = i; }
    else if (i < 3145728) { src = opw; off = i - 2359296; }
    else if (i < 6291456) { src = f1w; off = i - 3145728; }
    else                  { src = f2w; off = i - 6291456; }
    float4 v = *reinterpret_cast<const float4*>(src + off);
    __half2* dst = reinterpret_cast<__half2*>(w16 + i);
    dst[0] = __floats2half2_rn(v.x, v.y);
    dst[1] = __floats2half2_rn(v.z, v.w);
}

// ---------------------------------------------------------------------------
// Embedding: x fp32 + fp16 twin
// ---------------------------------------------------------------------------
__global__ __launch_bounds__(256) void embed_kernel(
    const int* __restrict__ ids, const float* __restrict__ emb,
    const float* __restrict__ pos, float* __restrict__ x, __half* __restrict__ x16) {
    int idx = blockIdx.x * blockDim.x + threadIdx.x;
    int token = idx >> 7;
    int c = idx & 127;
    float4 e = reinterpret_cast<const float4*>(emb)[(size_t)ids[token] * 128 + c];
    float4 p = reinterpret_cast<const float4*>(pos)[(size_t)(token & (TS - 1)) * 128 + c];
    float4 o;
    o.x = e.x + p.x; o.y = e.y + p.y; o.z = e.z + p.z; o.w = e.w + p.w;
    reinterpret_cast<float4*>(x)[idx] = o;
    __half2* h = reinterpret_cast<__half2*>(x16) + idx * 2;
    h[0] = __floats2half2_rn(o.x, o.y);
    h[1] = __floats2half2_rn(o.z, o.w);
}

// ---------------------------------------------------------------------------
// FP16 tensor-core GEMM (proven): C = A @ W^T + bias, opt GELU,
// fp32 or fp16 output. Block 128x128, 128 thr, warp tile 64x64, 4-stage ring.
// ---------------------------------------------------------------------------
#define HSTG 16384
#define HG_SMEM (4 * HSTG)

template <int ACT, int OUT16>
__global__ __launch_bounds__(128, 2) void hgemm_kernel(
    const __half* __restrict__ A, const __half* __restrict__ W,
    const float* __restrict__ bias, float* __restrict__ C,
    __half* __restrict__ C16, int N, int K) {
    extern __shared__ char smraw[];
    uint32_t base;
    asm("{ .reg .u64 t; cvta.to.shared.u64 t, %1; cvt.u32.u64 %0, t; }"
        : "=r"(base) : "l"(smraw));

    const int t = threadIdx.x;
    const int lane = t & 31;
    const int warp = t >> 5;
    const int wr = (warp >> 1) * 64;
    const int wc = (warp & 1) * 64;
    const int qr = lane >> 2;
    const int qc = lane & 3;

    const int m0 = blockIdx.y * 128;
    const int n0 = blockIdx.x * 128;
    const int KT = K >> 5;

    const int arow = lane & 15;
    const int achk = lane >> 4;
    const int brow = lane & 7;
    const int bchk = (lane >> 3) & 1;

    float acc[4][8][4];
#pragma unroll
    for (int i = 0; i < 4; i++)
#pragma unroll
        for (int j = 0; j < 8; j++)
#pragma unroll
            for (int r = 0; r < 4; r++) acc[i][j][r] = 0.f;

#pragma unroll
    for (int s = 0; s < 3; s++) {
        uint32_t sb = base + s * HSTG;
#pragma unroll
        for (int i = 0; i < 4; i++) {
            int idx = t + 128 * i;
            int row = idx >> 2, c = idx & 3;
            cpa16(sb + hswz(row, c), A + (size_t)(m0 + row) * K + s * 32 + c * 8);
            cpa16(sb + 8192 + hswz(row, c), W + (size_t)(n0 + row) * K + s * 32 + c * 8);
        }
        cpa_commit();
    }

    for (int kt = 0; kt < KT; kt++) {
        int pend = KT - 1 - kt; if (pend > 2) pend = 2;
        if (pend == 2)      asm volatile("cp.async.wait_group 2;");
        else if (pend == 1) asm volatile("cp.async.wait_group 1;");
        else                asm volatile("cp.async.wait_group 0;");
        __syncthreads();

        if (kt + 3 < KT) {
            int j = kt + 3;
            uint32_t sb = base + (j & 3) * HSTG;
#pragma unroll
            for (int i = 0; i < 4; i++) {
                int idx = t + 128 * i;
                int row = idx >> 2, c = idx & 3;
                cpa16(sb + hswz(row, c), A + (size_t)(m0 + row) * K + j * 32 + c * 8);
                cpa16(sb + 8192 + hswz(row, c), W + (size_t)(n0 + row) * K + j * 32 + c * 8);
            }
            cpa_commit();
        } else {
            cpa_commit();
        }

        const uint32_t sb = base + (kt & 3) * HSTG;
#pragma unroll
        for (int s2 = 0; s2 < 2; s2++) {
            uint32_t a[4][4], bw[8][2];
#pragma unroll
            for (int mi = 0; mi < 4; mi++) {
                uint32_t ad = sb + hswz(wr + mi * 16 + arow, 2 * s2 + achk);
                LDSM4(a[mi][0], a[mi][1], a[mi][2], a[mi][3], ad);
            }
#pragma unroll
            for (int ni = 0; ni < 8; ni++) {
                uint32_t bd = sb + 8192 + hswz(wc + ni * 8 + brow, 2 * s2 + bchk);
                LDSM2(bw[ni][0], bw[ni][1], bd);
            }
#pragma unroll
            for (int mi = 0; mi < 4; mi++)
#pragma unroll
                for (int ni = 0; ni < 8; ni++) MMA_F16(acc[mi][ni], a[mi], bw[ni]);
        }
    }

#pragma unroll
    for (int mi = 0; mi < 4; mi++) {
#pragma unroll
        for (int ni = 0; ni < 8; ni++) {
            int col = n0 + wc + ni * 8 + qc * 2;
            float b0 = bias[col], b1 = bias[col + 1];
#pragma unroll
            for (int half = 0; half < 2; half++) {
                int row = m0 + wr + mi * 16 + qr + half * 8;
                float v0 = acc[mi][ni][half * 2 + 0] + b0;
                float v1 = acc[mi][ni][half * 2 + 1] + b1;
                if (ACT == 1) {
                    v0 = 0.5f * v0 * (1.f + erff(v0 * 0.70710678118654752f));
                    v1 = 0.5f * v1 * (1.f + erff(v1 * 0.70710678118654752f));
                }
                if (OUT16) {
                    *reinterpret_cast<__half2*>(C16 + (size_t)row * N + col) =
                        __floats2half2_rn(v0, v1);
                } else {
                    float2 o; o.x = v0; o.y = v1;
                    *reinterpret_cast<float2*>(C + (size_t)row * N + col) = o;
                }
            }
        }
    }
}

// ---------------------------------------------------------------------------
// Fused attention scores + softmax, fp16 tensor cores.
// Block: 32 q-rows x 512 keys for one (b,h). Writes normalized fp32 probs
// (required output) AND an fp16 copy for the AV kernel.
// ---------------------------------------------------------------------------
__global__ __launch_bounds__(256, 2) void attn_fused16_kernel(
    const __half* __restrict__ qkv16, const int* __restrict__ mask,
    float* __restrict__ attn, __half* __restrict__ p16) {
    __shared__ __align__(128) char smQ[32 * 128];     // 4 KB
    __shared__ __align__(128) char smK[3 * 64 * 128]; // 24 KB
    __shared__ float biasS[512];
    __shared__ float red[32 * 9];

    const int t = threadIdx.x, lane = t & 31, warp = t >> 5;
    const int qr = lane >> 2, qc = lane & 3;
    const int bh = blockIdx.y, b = bh >> 3, h = bh & 7;
    const int m0 = blockIdx.x * 32;
    const __half* qb = qkv16 + (size_t)b * TS * QKVW + h * THD;
    const __half* kb = qb + TE;

    uint32_t qbase = (uint32_t)__cvta_generic_to_shared(smQ);
    uint32_t kbase = (uint32_t)__cvta_generic_to_shared(smK);

    for (int i = t; i < 512; i += 256)
        biasS[i] = (mask[b * TS + i] == 0) ? -1e30f : 0.f;

    {
        int row = t >> 3, c8 = t & 7;
        cpa16(qbase + ASWZ(row, c8), qb + (size_t)(m0 + row) * QKVW + c8 * 8);
#pragma unroll
        for (int i = 0; i < 2; i++) {
            int u = t + 256 * i;
            int kr = u >> 3, kc = u & 7;
            cpa16(kbase + ASWZ(kr, kc), kb + (size_t)kr * QKVW + kc * 8);
        }
    }
    cpa_commit();
    {
#pragma unroll
        for (int i = 0; i < 2; i++) {
            int u = t + 256 * i;
            int kr = u >> 3, kc = u & 7;
            cpa16(kbase + 8192 + ASWZ(kr, kc), kb + (size_t)(64 + kr) * QKVW + kc * 8);
        }
    }
    cpa_commit();

    float acc[8][2][4];
#pragma unroll
    for (int c = 0; c < 8; c++)
#pragma unroll
        for (int mi = 0; mi < 2; mi++)
#pragma unroll
            for (int r = 0; r < 4; r++) acc[c][mi][r] = 0.f;

    const int arow = lane & 15, achk = lane >> 4;
    const int brow = lane & 7, bchk = (lane >> 3) & 1;

    for (int c = 0; c < 8; c++) {
        if (c < 7) asm volatile("cp.async.wait_group 1;");
        else       asm volatile("cp.async.wait_group 0;");
        __syncthreads();

        if (c + 2 < 8) {
            uint32_t kbn = kbase + ((c + 2) % 3) * 8192;
#pragma unroll
            for (int i = 0; i < 2; i++) {
                int u = t + 256 * i;
                int kr = u >> 3, kc = u & 7;
                cpa16(kbn + ASWZ(kr, kc), kb + (size_t)((c + 2) * 64 + kr) * QKVW + kc * 8);
            }
            cpa_commit();
        }

        const uint32_t kbc = kbase + (c % 3) * 8192;
#pragma unroll
        for (int s = 0; s < 4; s++) {
            uint32_t a[2][4], bw[2];
#pragma unroll
            for (int mi = 0; mi < 2; mi++)
                LDSM4(a[mi][0], a[mi][1], a[mi][2], a[mi][3],
                      qbase + ASWZ(mi * 16 + arow, 2 * s + achk));
            LDSM2(bw[0], bw[1], kbc + ASWZ(warp * 8 + brow, 2 * s + bchk));
#pragma unroll
            for (int mi = 0; mi < 2; mi++) MMA_F16(acc[c][mi], a[mi], bw);
        }
    }

    // ---- softmax over 512 keys per row (32 rows) ----
    float bm[2][2], bs[2][2];
    const float scale = 0.125f;
#pragma unroll
    for (int mi = 0; mi < 2; mi++) {
#pragma unroll
        for (int h2 = 0; h2 < 2; h2++) {
            float m = -3.4e38f;
#pragma unroll
            for (int c = 0; c < 8; c++) {
                int col = c * 64 + warp * 8 + qc * 2;
                float v0 = acc[c][mi][2 * h2 + 0] * scale + biasS[col];
                float v1 = acc[c][mi][2 * h2 + 1] * scale + biasS[col + 1];
                acc[c][mi][2 * h2 + 0] = v0;
                acc[c][mi][2 * h2 + 1] = v1;
                m = fmaxf(m, fmaxf(v0, v1));
            }
            m = fmaxf(m, __shfl_xor_sync(0xFFFFFFFFu, m, 1));
            m = fmaxf(m, __shfl_xor_sync(0xFFFFFFFFu, m, 2));
            bm[mi][h2] = m;
        }
    }
    if (qc == 0) {
#pragma unroll
        for (int mi = 0; mi < 2; mi++)
#pragma unroll
            for (int h2 = 0; h2 < 2; h2++)
                red[(mi * 16 + qr + h2 * 8) * 9 + warp] = bm[mi][h2];
    }
    __syncthreads();
#pragma unroll
    for (int mi = 0; mi < 2; mi++)
#pragma unroll
        for (int h2 = 0; h2 < 2; h2++) {
            int row = mi * 16 + qr + h2 * 8;
            float m = red[row * 9 + 0];
#pragma unroll
            for (int w2 = 1; w2 < 8; w2++) m = fmaxf(m, red[row * 9 + w2]);
            bm[mi][h2] = m;
        }
    __syncthreads();
#pragma unroll
    for (int mi = 0; mi < 2; mi++) {
#pragma unroll
        for (int h2 = 0; h2 < 2; h2++) {
            float m = bm[mi][h2];
            float s = 0.f;
#pragma unroll
            for (int c = 0; c < 8; c++) {
                float e0 = __expf(acc[c][mi][2 * h2 + 0] - m);
                float e1 = __expf(acc[c][mi][2 * h2 + 1] - m);
                acc[c][mi][2 * h2 + 0] = e0;
                acc[c][mi][2 * h2 + 1] = e1;
                s += e0 + e1;
            }
            s += __shfl_xor_sync(0xFFFFFFFFu, s, 1);
            s += __shfl_xor_sync(0xFFFFFFFFu, s, 2);
            bs[mi][h2] = s;
        }
    }
    if (qc == 0) {
#pragma unroll
        for (int mi = 0; mi < 2; mi++)
#pragma unroll
            for (int h2 = 0; h2 < 2; h2++)
                red[(mi * 16 + qr + h2 * 8) * 9 + warp] = bs[mi][h2];
    }
    __syncthreads();
#pragma unroll
    for (int mi = 0; mi < 2; mi++)
#pragma unroll
        for (int h2 = 0; h2 < 2; h2++) {
            int row = mi * 16 + qr + h2 * 8;
            float s = 0.f;
#pragma unroll
            for (int w2 = 0; w2 < 8; w2++) s += red[row * 9 + w2];
            float inv = 1.f / s;
            float* orow = attn + ((size_t)bh * TS + m0 + row) * TS;
            __half* prow = p16 + ((size_t)bh * TS + m0 + row) * TS;
#pragma unroll
            for (int c = 0; c < 8; c++) {
                int col = c * 64 + warp * 8 + qc * 2;
                float2 o;
                o.x = acc[c][mi][2 * h2 + 0] * inv;
                o.y = acc[c][mi][2 * h2 + 1] * inv;
                *reinterpret_cast<float2*>(orow + col) = o;
                *reinterpret_cast<__half2*>(prow + col) = __floats2half2_rn(o.x, o.y);
            }
        }
}

// ---------------------------------------------------------------------------
// AV fp16: per (b,h) O[64,64] tile = P16[64,512] @ V[512,64].
// 3-stage cp.async ring over 64-key chunks. A-frags via LDSM4 (P rows),
// B-frags via ldmatrix.trans on V's natural [key][dim] layout.
// Warp w: rows (w&3)*16, dims (w>>2)*32.
// ---------------------------------------------------------------------------
#define AV_STG 16384
#define AV_SMEM (3 * AV_STG)

__global__ __launch_bounds__(256, 2) void attn_av16_kernel(
    const __half* __restrict__ p16, const __half* __restrict__ qkv16,
    __half* __restrict__ outx) {
    extern __shared__ char smraw[];
    uint32_t base;
    asm("{ .reg .u64 t; cvta.to.shared.u64 t, %1; cvt.u32.u64 %0, t; }"
        : "=r"(base) : "l"(smraw));

    const int t = threadIdx.x, lane = t & 31, warp = t >> 5;
    const int qr = lane >> 2, qc = lane & 3;
    const int bh = blockIdx.y, b = bh >> 3, h = bh & 7;
    const int m0 = blockIdx.x * 64;
    const int wr = (warp & 3) * 16;
    const int wc = (warp >> 2) * 32;
    const __half* Pb = p16 + ((size_t)bh * TS + m0) * TS;
    const __half* vb = qkv16 + (size_t)b * TS * QKVW + 2 * TE + h * THD;

    const int arow = lane & 15, achk = lane >> 4;
    const int trow = lane & 15;

    float acc[4][4];
#pragma unroll
    for (int ni = 0; ni < 4; ni++)
#pragma unroll
        for (int r = 0; r < 4; r++) acc[ni][r] = 0.f;

    // prologue: chunks 0,1
#pragma unroll
    for (int s = 0; s < 2; s++) {
        uint32_t sb = base + s * AV_STG;
#pragma unroll
        for (int i = 0; i < 2; i++) {
            int u = t + 256 * i;
            int row = u >> 3, c8 = u & 7;
            cpa16(sb + ASWZ(row, c8), Pb + (size_t)row * TS + s * 64 + c8 * 8);
            cpa16(sb + 8192 + ASWZ(row, c8), vb + (size_t)(s * 64 + row) * QKVW + c8 * 8);
        }
        cpa_commit();
    }

    for (int kc = 0; kc < 8; kc++) {
        if (kc < 7) asm volatile("cp.async.wait_group 1;");
        else        asm volatile("cp.async.wait_group 0;");
        __syncthreads();

        if (kc + 2 < 8) {
            uint32_t sb = base + ((kc + 2) % 3) * AV_STG;
#pragma unroll
            for (int i = 0; i < 2; i++) {
                int u = t + 256 * i;
                int row = u >> 3, c8 = u & 7;
                cpa16(sb + ASWZ(row, c8), Pb + (size_t)row * TS + (kc + 2) * 64 + c8 * 8);
                cpa16(sb + 8192 + ASWZ(row, c8),
                      vb + (size_t)((kc + 2) * 64 + row) * QKVW + c8 * 8);
            }
            cpa_commit();
        }

        const uint32_t sb = base + (kc % 3) * AV_STG;
#pragma unroll
        for (int s = 0; s < 4; s++) {
            uint32_t a[4];
            LDSM4(a[0], a[1], a[2], a[3], sb + ASWZ(wr + arow, 2 * s + achk));
#pragma unroll
            for (int ni = 0; ni < 4; ni++) {
                uint32_t bw[2];
                LDSM2T(bw[0], bw[1],
                       sb + 8192 + ASWZ(s * 16 + trow, (warp >> 2) * 4 + ni));
                MMA_F16(acc[ni], a, bw);
            }
        }
    }

#pragma unroll
    for (int ni = 0; ni < 4; ni++) {
#pragma unroll
        for (int h2 = 0; h2 < 2; h2++) {
            int row = m0 + wr + qr + h2 * 8;
            int col = wc + ni * 8 + qc * 2;
            *reinterpret_cast<__half2*>(outx + ((size_t)b * TS + row) * TE + h * THD + col) =
                __floats2half2_rn(acc[ni][2 * h2 + 0], acc[ni][2 * h2 + 1]);
        }
    }
}

// ---------------------------------------------------------------------------
// Fused residual + LayerNorm; writes fp32 x and fp16 twin.
// ---------------------------------------------------------------------------
__global__ __launch_bounds__(128) void add_ln_kernel(
    float* __restrict__ x, const float* __restrict__ y,
    const float* __restrict__ g, const float* __restrict__ bb,
    __half* __restrict__ x16) {
    const size_t row = blockIdx.x;
    const int t = threadIdx.x;
    float4 xv = reinterpret_cast<float4*>(x + row * TE)[t];
    float4 yv = reinterpret_cast<const float4*>(y + row * TE)[t];
    float4 s;
    s.x = xv.x + yv.x; s.y = xv.y + yv.y; s.z = xv.z + yv.z; s.w = xv.w + yv.w;
    float sum = s.x + s.y + s.z + s.w;
    float sq = s.x * s.x + s.y * s.y + s.z * s.z + s.w * s.w;
#pragma unroll
    for (int o = 16; o; o >>= 1) {
        sum += __shfl_xor_sync(0xFFFFFFFFu, sum, o);
        sq  += __shfl_xor_sync(0xFFFFFFFFu, sq, o);
    }
    __shared__ float s1[4], s2[4];
    if ((t & 31) == 0) { s1[t >> 5] = sum; s2[t >> 5] = sq; }
    __syncthreads();
    sum = s1[0] + s1[1] + s1[2] + s1[3];
    sq  = s2[0] + s2[1] + s2[2] + s2[3];
    const float mean = sum * (1.f / TE);
    const float var = sq * (1.f / TE) - mean * mean;
    const float rstd = rsqrtf(var + 1e-5f);
    float4 gv = reinterpret_cast<const float4*>(g)[t];
    float4 bv = reinterpret_cast<const float4*>(bb)[t];
    float4 o;
    o.x = (s.x - mean) * rstd * gv.x + bv.x;
    o.y = (s.y - mean) * rstd * gv.y + bv.y;
    o.z = (s.z - mean) * rstd * gv.z + bv.z;
    o.w = (s.w - mean) * rstd * gv.w + bv.w;
    reinterpret_cast<float4*>(x + row * TE)[t] = o;
    __half2* hx = reinterpret_cast<__half2*>(x16 + row * TE) + t * 2;
    hx[0] = __floats2half2_rn(o.x, o.y);
    hx[1] = __floats2half2_rn(o.z, o.w);
}

// ---------------------------------------------------------------------------
// CLS head
// ---------------------------------------------------------------------------
__global__ void cls_kernel(const float* __restrict__ x, const float* __restrict__ w,
                           const float* __restrict__ cb, float* __restrict__ out) {
    int t = threadIdx.x;
    if (t >= TB * 2) return;
    int b = t >> 1, c = t & 1;
    const float* xr = x + (size_t)b * TS * TE;
    const float* wr = w + c * TE;
    float s = cb[c];
    for (int e = 0; e < TE; e++) s = fmaf(xr[e], wr[e], s);
    out[b * 2 + c] = s;
}

// ---------------------------------------------------------------------------
extern "C" void kernel_launch(void* const* d_in, const int* in_sizes, int n_in,
                              void* d_out, int out_size) {
    const int*   ids  = (const int*)d_in[0];
    const int*   mask = (const int*)d_in[1];
    const float* emb  = (const float*)d_in[2];
    const float* pos  = (const float*)d_in[3];
    const float* ipw  = (const float*)d_in[4];
    const float* ipb  = (const float*)d_in[5];
    const float* opw  = (const float*)d_in[6];
    const float* opb  = (const float*)d_in[7];
    const float* l1g  = (const float*)d_in[8];
    const float* l1b  = (const float*)d_in[9];
    const float* l2g  = (const float*)d_in[10];
    const float* l2b  = (const float*)d_in[11];
    const float* f1w  = (const float*)d_in[12];
    const float* f1b  = (const float*)d_in[13];
    const float* f2w  = (const float*)d_in[14];
    const float* f2b  = (const float*)d_in[15];
    const float* cw   = (const float*)d_in[16];
    const float* cb   = (const float*)d_in[17];
    float* out = (float*)d_out;
    float* attn_base = out + TB * 2;

    float *x, *y;
    __half *qkv16, *x16, *att16, *h16, *w16, *p16;
    cudaGetSymbolAddress((void**)&x,      g_x);
    cudaGetSymbolAddress((void**)&y,      g_y);
    cudaGetSymbolAddress((void**)&qkv16,  g_qkv16);
    cudaGetSymbolAddress((void**)&x16,    g_x16);
    cudaGetSymbolAddress((void**)&att16,  g_att16);
    cudaGetSymbolAddress((void**)&h16,    g_h16);
    cudaGetSymbolAddress((void**)&w16,    g_w16);
    cudaGetSymbolAddress((void**)&p16,    g_p16);

    cudaFuncSetAttribute(hgemm_kernel<0, 0>, cudaFuncAttributeMaxDynamicSharedMemorySize, HG_SMEM);
    cudaFuncSetAttribute(hgemm_kernel<0, 1>, cudaFuncAttributeMaxDynamicSharedMemorySize, HG_SMEM);
    cudaFuncSetAttribute(hgemm_kernel<1, 1>, cudaFuncAttributeMaxDynamicSharedMemorySize, HG_SMEM);
    cudaFuncSetAttribute(attn_av16_kernel, cudaFuncAttributeMaxDynamicSharedMemorySize, AV_SMEM);

    cvtw_kernel<<<W16_TOTAL / 4 / 256, 256>>>(ipw, opw, f1w, f2w, w16);
    embed_kernel<<<(TT * 128) / 256, 256>>>(ids, emb, pos, x, x16);

    for (int l = 0; l < TL; l++) {
        hgemm_kernel<0, 1><<<dim3(QKVW / 128, TT / 128), 128, HG_SMEM>>>(
            x16, w16 + W16_IPW(l), ipb + l * QKVW, nullptr, qkv16, QKVW, TE);

        float* attn_l = attn_base + (size_t)l * TB * TNH * TS * TS;
        attn_fused16_kernel<<<dim3(16, TB * TNH), 256>>>(qkv16, mask, attn_l, p16);
        attn_av16_kernel<<<dim3(8, TB * TNH), 256, AV_SMEM>>>(p16, qkv16, att16);

        hgemm_kernel<0, 0><<<dim3(TE / 128, TT / 128), 128, HG_SMEM>>>(
            att16, w16 + W16_OPW(l), opb + l * TE, y, nullptr, TE, TE);
        add_ln_kernel<<<TT, 128>>>(x, y, l1g + l * TE, l1b + l * TE, x16);

        hgemm_kernel<1, 1><<<dim3(4 * TE / 128, TT / 128), 128, HG_SMEM>>>(
            x16, w16 + W16_F1W(l), f1b + l * 4 * TE, nullptr, h16, 4 * TE, TE);
        hgemm_kernel<0, 0><<<dim3(TE / 128, TT / 128), 128, HG_SMEM>>>(
            h16, w16 + W16_F2W(l), f2b + l * TE, y, nullptr, TE, 4 * TE);
        add_ln_kernel<<<TT, 128>>>(x, y, l2g + l * TE, l2b + l * TE, x16);
    }

    cls_kernel<<<1, 64>>>(x, cw, cb, out);
}

// round 10
// speedup vs baseline: 2.2460x; 1.0143x over previous
#include <cuda_runtime.h>
#include <cuda_fp16.h>
#include <cstdint>
#include <math.h>

// Problem constants
#define TB 32      // batch
#define TS 512     // seq len
#define TE 512     // d_model
#define THD 64     // head dim
#define TNH 8      // heads
#define TL 3       // layers
#define TT (TB*TS) // tokens = 16384
#define QKVW 1536  // 3*E

// Scratch (device globals; allocation-free contract)
__device__ float  g_x[(size_t)TT * TE];        // running hidden fp32   32 MB
__device__ float  g_y[(size_t)TT * TE];        // gemm out fp32         32 MB
__device__ __half g_qkv16[(size_t)TT * QKVW];  // qkv fp16              48 MB
__device__ __half g_x16[(size_t)TT * TE];      // hidden fp16           16 MB
__device__ __half g_att16[(size_t)TT * TE];    // attn concat fp16      16 MB
__device__ __half g_h16[(size_t)TT * 4 * TE];  // ffn hidden fp16       64 MB
__device__ __half g_p16[(size_t)TB * TNH * TS * TS];  // probs fp16    134 MB
#define W16_TOTAL 9437184
__device__ __half g_w16[W16_TOTAL];            // all weights fp16      18 MB
#define W16_IPW(l) ((size_t)(l) * 786432)
#define W16_OPW(l) (2359296 + (size_t)(l) * 262144)
#define W16_F1W(l) (3145728 + (size_t)(l) * 1048576)
#define W16_F2W(l) (6291456 + (size_t)(l) * 1048576)

#define MMA_F16(d, a, b)                                                      \
    asm volatile(                                                             \
        "mma.sync.aligned.m16n8k16.row.col.f32.f16.f16.f32 "                  \
        "{%0,%1,%2,%3}, {%4,%5,%6,%7}, {%8,%9}, {%0,%1,%2,%3};"               \
        : "+f"(d[0]), "+f"(d[1]), "+f"(d[2]), "+f"(d[3])                      \
        : "r"(a[0]), "r"(a[1]), "r"(a[2]), "r"(a[3]), "r"(b[0]), "r"(b[1]))

#define LDSM4(r0, r1, r2, r3, addr)                                           \
    asm volatile("ldmatrix.sync.aligned.m8n8.x4.shared.b16 {%0,%1,%2,%3}, [%4];" \
        : "=r"(r0), "=r"(r1), "=r"(r2), "=r"(r3) : "r"(addr))

#define LDSM2(r0, r1, addr)                                                   \
    asm volatile("ldmatrix.sync.aligned.m8n8.x2.shared.b16 {%0,%1}, [%2];"    \
        : "=r"(r0), "=r"(r1) : "r"(addr))

#define LDSM2T(r0, r1, addr)                                                  \
    asm volatile("ldmatrix.sync.aligned.m8n8.x2.trans.shared.b16 {%0,%1}, [%2];" \
        : "=r"(r0), "=r"(r1) : "r"(addr))

__device__ __forceinline__ void cpa16(uint32_t s, const void* g) {
    asm volatile("cp.async.cg.shared.global [%0], [%1], 16;" :: "r"(s), "l"(g));
}
__device__ __forceinline__ void cpa_commit() {
    asm volatile("cp.async.commit_group;");
}

// fp16 tile swizzles: chunk = 16B unit
// 64B-pitch rows (32 halfs) for hgemm
__device__ __forceinline__ uint32_t hswz(int row, int chunk) {
    return (uint32_t)(row * 64 + (((chunk + (row >> 1)) & 3) << 4));
}
// 128B-pitch rows (64 halfs) for attention tiles
#define ASWZ(row, c8) ((uint32_t)(((row) << 7) | ((((c8) ^ ((row) & 7))) << 4)))

// ---------------------------------------------------------------------------
// Weight conversion fp32 -> fp16 (once per launch, ~40us)
// ---------------------------------------------------------------------------
__global__ __launch_bounds__(256) void cvtw_kernel(
    const float* __restrict__ ipw, const float* __restrict__ opw,
    const float* __restrict__ f1w, const float* __restrict__ f2w,
    __half* __restrict__ w16) {
    size_t i = ((size_t)blockIdx.x * 256 + threadIdx.x) * 4;
    const float* src; size_t off;
    if (i < 2359296)      { src = ipw; off = i; }
    else if (i < 3145728) { src = opw; off = i - 2359296; }
    else if (i < 6291456) { src = f1w; off = i - 3145728; }
    else                  { src = f2w; off = i - 6291456; }
    float4 v = *reinterpret_cast<const float4*>(src + off);
    __half2* dst = reinterpret_cast<__half2*>(w16 + i);
    dst[0] = __floats2half2_rn(v.x, v.y);
    dst[1] = __floats2half2_rn(v.z, v.w);
}

// ---------------------------------------------------------------------------
// Embedding: x fp32 + fp16 twin
// ---------------------------------------------------------------------------
__global__ __launch_bounds__(256) void embed_kernel(
    const int* __restrict__ ids, const float* __restrict__ emb,
    const float* __restrict__ pos, float* __restrict__ x, __half* __restrict__ x16) {
    int idx = blockIdx.x * blockDim.x + threadIdx.x;
    int token = idx >> 7;
    int c = idx & 127;
    float4 e = reinterpret_cast<const float4*>(emb)[(size_t)ids[token] * 128 + c];
    float4 p = reinterpret_cast<const float4*>(pos)[(size_t)(token & (TS - 1)) * 128 + c];
    float4 o;
    o.x = e.x + p.x; o.y = e.y + p.y; o.z = e.z + p.z; o.w = e.w + p.w;
    reinterpret_cast<float4*>(x)[idx] = o;
    __half2* h = reinterpret_cast<__half2*>(x16) + idx * 2;
    h[0] = __floats2half2_rn(o.x, o.y);
    h[1] = __floats2half2_rn(o.z, o.w);
}

// ---------------------------------------------------------------------------
// FP16 tensor-core GEMM (proven): C = A @ W^T + bias, opt GELU,
// fp32 or fp16 output. Block 128x128, 128 thr, warp tile 64x64, 4-stage ring.
// ---------------------------------------------------------------------------
#define HSTG 16384
#define HG_SMEM (4 * HSTG)

template <int ACT, int OUT16>
__global__ __launch_bounds__(128, 2) void hgemm_kernel(
    const __half* __restrict__ A, const __half* __restrict__ W,
    const float* __restrict__ bias, float* __restrict__ C,
    __half* __restrict__ C16, int N, int K) {
    extern __shared__ char smraw[];
    uint32_t base;
    asm("{ .reg .u64 t; cvta.to.shared.u64 t, %1; cvt.u32.u64 %0, t; }"
        : "=r"(base) : "l"(smraw));

    const int t = threadIdx.x;
    const int lane = t & 31;
    const int warp = t >> 5;
    const int wr = (warp >> 1) * 64;
    const int wc = (warp & 1) * 64;
    const int qr = lane >> 2;
    const int qc = lane & 3;

    const int m0 = blockIdx.y * 128;
    const int n0 = blockIdx.x * 128;
    const int KT = K >> 5;

    const int arow = lane & 15;
    const int achk = lane >> 4;
    const int brow = lane & 7;
    const int bchk = (lane >> 3) & 1;

    float acc[4][8][4];
#pragma unroll
    for (int i = 0; i < 4; i++)
#pragma unroll
        for (int j = 0; j < 8; j++)
#pragma unroll
            for (int r = 0; r < 4; r++) acc[i][j][r] = 0.f;

#pragma unroll
    for (int s = 0; s < 3; s++) {
        uint32_t sb = base + s * HSTG;
#pragma unroll
        for (int i = 0; i < 4; i++) {
            int idx = t + 128 * i;
            int row = idx >> 2, c = idx & 3;
            cpa16(sb + hswz(row, c), A + (size_t)(m0 + row) * K + s * 32 + c * 8);
            cpa16(sb + 8192 + hswz(row, c), W + (size_t)(n0 + row) * K + s * 32 + c * 8);
        }
        cpa_commit();
    }

    for (int kt = 0; kt < KT; kt++) {
        int pend = KT - 1 - kt; if (pend > 2) pend = 2;
        if (pend == 2)      asm volatile("cp.async.wait_group 2;");
        else if (pend == 1) asm volatile("cp.async.wait_group 1;");
        else                asm volatile("cp.async.wait_group 0;");
        __syncthreads();

        if (kt + 3 < KT) {
            int j = kt + 3;
            uint32_t sb = base + (j & 3) * HSTG;
#pragma unroll
            for (int i = 0; i < 4; i++) {
                int idx = t + 128 * i;
                int row = idx >> 2, c = idx & 3;
                cpa16(sb + hswz(row, c), A + (size_t)(m0 + row) * K + j * 32 + c * 8);
                cpa16(sb + 8192 + hswz(row, c), W + (size_t)(n0 + row) * K + j * 32 + c * 8);
            }
            cpa_commit();
        } else {
            cpa_commit();
        }

        const uint32_t sb = base + (kt & 3) * HSTG;
#pragma unroll
        for (int s2 = 0; s2 < 2; s2++) {
            uint32_t a[4][4], bw[8][2];
#pragma unroll
            for (int mi = 0; mi < 4; mi++) {
                uint32_t ad = sb + hswz(wr + mi * 16 + arow, 2 * s2 + achk);
                LDSM4(a[mi][0], a[mi][1], a[mi][2], a[mi][3], ad);
            }
#pragma unroll
            for (int ni = 0; ni < 8; ni++) {
                uint32_t bd = sb + 8192 + hswz(wc + ni * 8 + brow, 2 * s2 + bchk);
                LDSM2(bw[ni][0], bw[ni][1], bd);
            }
#pragma unroll
            for (int mi = 0; mi < 4; mi++)
#pragma unroll
                for (int ni = 0; ni < 8; ni++) MMA_F16(acc[mi][ni], a[mi], bw[ni]);
        }
    }

#pragma unroll
    for (int mi = 0; mi < 4; mi++) {
#pragma unroll
        for (int ni = 0; ni < 8; ni++) {
            int col = n0 + wc + ni * 8 + qc * 2;
            float b0 = bias[col], b1 = bias[col + 1];
#pragma unroll
            for (int half = 0; half < 2; half++) {
                int row = m0 + wr + mi * 16 + qr + half * 8;
                float v0 = acc[mi][ni][half * 2 + 0] + b0;
                float v1 = acc[mi][ni][half * 2 + 1] + b1;
                if (ACT == 1) {
                    v0 = 0.5f * v0 * (1.f + erff(v0 * 0.70710678118654752f));
                    v1 = 0.5f * v1 * (1.f + erff(v1 * 0.70710678118654752f));
                }
                if (OUT16) {
                    *reinterpret_cast<__half2*>(C16 + (size_t)row * N + col) =
                        __floats2half2_rn(v0, v1);
                } else {
                    float2 o; o.x = v0; o.y = v1;
                    *reinterpret_cast<float2*>(C + (size_t)row * N + col) = o;
                }
            }
        }
    }
}

// ---------------------------------------------------------------------------
// Fused attention scores + softmax, fp16 tensor cores.
// Block: 32 q-rows x 512 keys for one (b,h). 4-stage K ring (2 chunks in
// flight). Writes fp32 probs via streaming stores + fp16 copy for AV.
// ---------------------------------------------------------------------------
__global__ __launch_bounds__(256, 2) void attn_fused16_kernel(
    const __half* __restrict__ qkv16, const int* __restrict__ mask,
    float* __restrict__ attn, __half* __restrict__ p16) {
    __shared__ __align__(128) char smQ[32 * 128];     // 4 KB
    __shared__ __align__(128) char smK[4 * 64 * 128]; // 32 KB
    __shared__ float biasS[512];
    __shared__ float red[32 * 9];

    const int t = threadIdx.x, lane = t & 31, warp = t >> 5;
    const int qr = lane >> 2, qc = lane & 3;
    const int bh = blockIdx.y, b = bh >> 3, h = bh & 7;
    const int m0 = blockIdx.x * 32;
    const __half* qb = qkv16 + (size_t)b * TS * QKVW + h * THD;
    const __half* kb = qb + TE;

    uint32_t qbase = (uint32_t)__cvta_generic_to_shared(smQ);
    uint32_t kbase = (uint32_t)__cvta_generic_to_shared(smK);

    for (int i = t; i < 512; i += 256)
        biasS[i] = (mask[b * TS + i] == 0) ? -1e30f : 0.f;

    // prologue: Q + K0 -> group0; K1 -> group1; K2 -> group2
    {
        int row = t >> 3, c8 = t & 7;
        cpa16(qbase + ASWZ(row, c8), qb + (size_t)(m0 + row) * QKVW + c8 * 8);
#pragma unroll
        for (int i = 0; i < 2; i++) {
            int u = t + 256 * i;
            int kr = u >> 3, kc = u & 7;
            cpa16(kbase + ASWZ(kr, kc), kb + (size_t)kr * QKVW + kc * 8);
        }
    }
    cpa_commit();
#pragma unroll
    for (int s = 1; s < 3; s++) {
#pragma unroll
        for (int i = 0; i < 2; i++) {
            int u = t + 256 * i;
            int kr = u >> 3, kc = u & 7;
            cpa16(kbase + s * 8192 + ASWZ(kr, kc), kb + (size_t)(s * 64 + kr) * QKVW + kc * 8);
        }
        cpa_commit();
    }

    float acc[8][2][4];
#pragma unroll
    for (int c = 0; c < 8; c++)
#pragma unroll
        for (int mi = 0; mi < 2; mi++)
#pragma unroll
            for (int r = 0; r < 4; r++) acc[c][mi][r] = 0.f;

    const int arow = lane & 15, achk = lane >> 4;
    const int brow = lane & 7, bchk = (lane >> 3) & 1;

    for (int c = 0; c < 8; c++) {
        if (c < 6)      asm volatile("cp.async.wait_group 2;");
        else if (c == 6) asm volatile("cp.async.wait_group 1;");
        else             asm volatile("cp.async.wait_group 0;");
        __syncthreads();

        if (c + 3 < 8) {
            uint32_t kbn = kbase + ((c + 3) & 3) * 8192;
#pragma unroll
            for (int i = 0; i < 2; i++) {
                int u = t + 256 * i;
                int kr = u >> 3, kc = u & 7;
                cpa16(kbn + ASWZ(kr, kc), kb + (size_t)((c + 3) * 64 + kr) * QKVW + kc * 8);
            }
            cpa_commit();
        }

        const uint32_t kbc = kbase + (c & 3) * 8192;
#pragma unroll
        for (int s = 0; s < 4; s++) {
            uint32_t a[2][4], bw[2];
#pragma unroll
            for (int mi = 0; mi < 2; mi++)
                LDSM4(a[mi][0], a[mi][1], a[mi][2], a[mi][3],
                      qbase + ASWZ(mi * 16 + arow, 2 * s + achk));
            LDSM2(bw[0], bw[1], kbc + ASWZ(warp * 8 + brow, 2 * s + bchk));
#pragma unroll
            for (int mi = 0; mi < 2; mi++) MMA_F16(acc[c][mi], a[mi], bw);
        }
    }

    // ---- softmax over 512 keys per row (32 rows) ----
    float bm[2][2], bs[2][2];
    const float scale = 0.125f;
#pragma unroll
    for (int mi = 0; mi < 2; mi++) {
#pragma unroll
        for (int h2 = 0; h2 < 2; h2++) {
            float m = -3.4e38f;
#pragma unroll
            for (int c = 0; c < 8; c++) {
                int col = c * 64 + warp * 8 + qc * 2;
                float v0 = acc[c][mi][2 * h2 + 0] * scale + biasS[col];
                float v1 = acc[c][mi][2 * h2 + 1] * scale + biasS[col + 1];
                acc[c][mi][2 * h2 + 0] = v0;
                acc[c][mi][2 * h2 + 1] = v1;
                m = fmaxf(m, fmaxf(v0, v1));
            }
            m = fmaxf(m, __shfl_xor_sync(0xFFFFFFFFu, m, 1));
            m = fmaxf(m, __shfl_xor_sync(0xFFFFFFFFu, m, 2));
            bm[mi][h2] = m;
        }
    }
    if (qc == 0) {
#pragma unroll
        for (int mi = 0; mi < 2; mi++)
#pragma unroll
            for (int h2 = 0; h2 < 2; h2++)
                red[(mi * 16 + qr + h2 * 8) * 9 + warp] = bm[mi][h2];
    }
    __syncthreads();
#pragma unroll
    for (int mi = 0; mi < 2; mi++)
#pragma unroll
        for (int h2 = 0; h2 < 2; h2++) {
            int row = mi * 16 + qr + h2 * 8;
            float m = red[row * 9 + 0];
#pragma unroll
            for (int w2 = 1; w2 < 8; w2++) m = fmaxf(m, red[row * 9 + w2]);
            bm[mi][h2] = m;
        }
    __syncthreads();
#pragma unroll
    for (int mi = 0; mi < 2; mi++) {
#pragma unroll
        for (int h2 = 0; h2 < 2; h2++) {
            float m = bm[mi][h2];
            float s = 0.f;
#pragma unroll
            for (int c = 0; c < 8; c++) {
                float e0 = __expf(acc[c][mi][2 * h2 + 0] - m);
                float e1 = __expf(acc[c][mi][2 * h2 + 1] - m);
                acc[c][mi][2 * h2 + 0] = e0;
                acc[c][mi][2 * h2 + 1] = e1;
                s += e0 + e1;
            }
            s += __shfl_xor_sync(0xFFFFFFFFu, s, 1);
            s += __shfl_xor_sync(0xFFFFFFFFu, s, 2);
            bs[mi][h2] = s;
        }
    }
    if (qc == 0) {
#pragma unroll
        for (int mi = 0; mi < 2; mi++)
#pragma unroll
            for (int h2 = 0; h2 < 2; h2++)
                red[(mi * 16 + qr + h2 * 8) * 9 + warp] = bs[mi][h2];
    }
    __syncthreads();
#pragma unroll
    for (int mi = 0; mi < 2; mi++)
#pragma unroll
        for (int h2 = 0; h2 < 2; h2++) {
            int row = mi * 16 + qr + h2 * 8;
            float s = 0.f;
#pragma unroll
            for (int w2 = 0; w2 < 8; w2++) s += red[row * 9 + w2];
            float inv = 1.f / s;
            float* orow = attn + ((size_t)bh * TS + m0 + row) * TS;
            __half* prow = p16 + ((size_t)bh * TS + m0 + row) * TS;
#pragma unroll
            for (int c = 0; c < 8; c++) {
                int col = c * 64 + warp * 8 + qc * 2;
                float2 o;
                o.x = acc[c][mi][2 * h2 + 0] * inv;
                o.y = acc[c][mi][2 * h2 + 1] * inv;
                __stcs(reinterpret_cast<float2*>(orow + col), o);
                *reinterpret_cast<__half2*>(prow + col) = __floats2half2_rn(o.x, o.y);
            }
        }
}

// ---------------------------------------------------------------------------
// AV fp16 (proven round-9): per (b,h) O[64,64] tile = P16[64,512] @ V[512,64].
// ---------------------------------------------------------------------------
#define AV_STG 16384
#define AV_SMEM (3 * AV_STG)

__global__ __launch_bounds__(256, 2) void attn_av16_kernel(
    const __half* __restrict__ p16, const __half* __restrict__ qkv16,
    __half* __restrict__ outx) {
    extern __shared__ char smraw[];
    uint32_t base;
    asm("{ .reg .u64 t; cvta.to.shared.u64 t, %1; cvt.u32.u64 %0, t; }"
        : "=r"(base) : "l"(smraw));

    const int t = threadIdx.x, lane = t & 31, warp = t >> 5;
    const int qr = lane >> 2, qc = lane & 3;
    const int bh = blockIdx.y, b = bh >> 3, h = bh & 7;
    const int m0 = blockIdx.x * 64;
    const int wr = (warp & 3) * 16;
    const int wc = (warp >> 2) * 32;
    const __half* Pb = p16 + ((size_t)bh * TS + m0) * TS;
    const __half* vb = qkv16 + (size_t)b * TS * QKVW + 2 * TE + h * THD;

    const int arow = lane & 15, achk = lane >> 4;
    const int trow = lane & 15;

    float acc[4][4];
#pragma unroll
    for (int ni = 0; ni < 4; ni++)
#pragma unroll
        for (int r = 0; r < 4; r++) acc[ni][r] = 0.f;

#pragma unroll
    for (int s = 0; s < 2; s++) {
        uint32_t sb = base + s * AV_STG;
#pragma unroll
        for (int i = 0; i < 2; i++) {
            int u = t + 256 * i;
            int row = u >> 3, c8 = u & 7;
            cpa16(sb + ASWZ(row, c8), Pb + (size_t)row * TS + s * 64 + c8 * 8);
            cpa16(sb + 8192 + ASWZ(row, c8), vb + (size_t)(s * 64 + row) * QKVW + c8 * 8);
        }
        cpa_commit();
    }

    for (int kc = 0; kc < 8; kc++) {
        if (kc < 7) asm volatile("cp.async.wait_group 1;");
        else        asm volatile("cp.async.wait_group 0;");
        __syncthreads();

        if (kc + 2 < 8) {
            uint32_t sb = base + ((kc + 2) % 3) * AV_STG;
#pragma unroll
            for (int i = 0; i < 2; i++) {
                int u = t + 256 * i;
                int row = u >> 3, c8 = u & 7;
                cpa16(sb + ASWZ(row, c8), Pb + (size_t)row * TS + (kc + 2) * 64 + c8 * 8);
                cpa16(sb + 8192 + ASWZ(row, c8),
                      vb + (size_t)((kc + 2) * 64 + row) * QKVW + c8 * 8);
            }
            cpa_commit();
        }

        const uint32_t sb = base + (kc % 3) * AV_STG;
#pragma unroll
        for (int s = 0; s < 4; s++) {
            uint32_t a[4];
            LDSM4(a[0], a[1], a[2], a[3], sb + ASWZ(wr + arow, 2 * s + achk));
#pragma unroll
            for (int ni = 0; ni < 4; ni++) {
                uint32_t bw[2];
                LDSM2T(bw[0], bw[1],
                       sb + 8192 + ASWZ(s * 16 + trow, (warp >> 2) * 4 + ni));
                MMA_F16(acc[ni], a, bw);
            }
        }
    }

#pragma unroll
    for (int ni = 0; ni < 4; ni++) {
#pragma unroll
        for (int h2 = 0; h2 < 2; h2++) {
            int row = m0 + wr + qr + h2 * 8;
            int col = wc + ni * 8 + qc * 2;
            *reinterpret_cast<__half2*>(outx + ((size_t)b * TS + row) * TE + h * THD + col) =
                __floats2half2_rn(acc[ni][2 * h2 + 0], acc[ni][2 * h2 + 1]);
        }
    }
}

// ---------------------------------------------------------------------------
// Fused residual + LayerNorm; writes fp32 x and fp16 twin.
// ---------------------------------------------------------------------------
__global__ __launch_bounds__(128) void add_ln_kernel(
    float* __restrict__ x, const float* __restrict__ y,
    const float* __restrict__ g, const float* __restrict__ bb,
    __half* __restrict__ x16) {
    const size_t row = blockIdx.x;
    const int t = threadIdx.x;
    float4 xv = reinterpret_cast<float4*>(x + row * TE)[t];
    float4 yv = reinterpret_cast<const float4*>(y + row * TE)[t];
    float4 s;
    s.x = xv.x + yv.x; s.y = xv.y + yv.y; s.z = xv.z + yv.z; s.w = xv.w + yv.w;
    float sum = s.x + s.y + s.z + s.w;
    float sq = s.x * s.x + s.y * s.y + s.z * s.z + s.w * s.w;
#pragma unroll
    for (int o = 16; o; o >>= 1) {
        sum += __shfl_xor_sync(0xFFFFFFFFu, sum, o);
        sq  += __shfl_xor_sync(0xFFFFFFFFu, sq, o);
    }
    __shared__ float s1[4], s2[4];
    if ((t & 31) == 0) { s1[t >> 5] = sum; s2[t >> 5] = sq; }
    __syncthreads();
    sum = s1[0] + s1[1] + s1[2] + s1[3];
    sq  = s2[0] + s2[1] + s2[2] + s2[3];
    const float mean = sum * (1.f / TE);
    const float var = sq * (1.f / TE) - mean * mean;
    const float rstd = rsqrtf(var + 1e-5f);
    float4 gv = reinterpret_cast<const float4*>(g)[t];
    float4 bv = reinterpret_cast<const float4*>(bb)[t];
    float4 o;
    o.x = (s.x - mean) * rstd * gv.x + bv.x;
    o.y = (s.y - mean) * rstd * gv.y + bv.y;
    o.z = (s.z - mean) * rstd * gv.z + bv.z;
    o.w = (s.w - mean) * rstd * gv.w + bv.w;
    reinterpret_cast<float4*>(x + row * TE)[t] = o;
    __half2* hx = reinterpret_cast<__half2*>(x16 + row * TE) + t * 2;
    hx[0] = __floats2half2_rn(o.x, o.y);
    hx[1] = __floats2half2_rn(o.z, o.w);
}

// ---------------------------------------------------------------------------
// CLS head
// ---------------------------------------------------------------------------
__global__ void cls_kernel(const float* __restrict__ x, const float* __restrict__ w,
                           const float* __restrict__ cb, float* __restrict__ out) {
    int t = threadIdx.x;
    if (t >= TB * 2) return;
    int b = t >> 1, c = t & 1;
    const float* xr = x + (size_t)b * TS * TE;
    const float* wr = w + c * TE;
    float s = cb[c];
    for (int e = 0; e < TE; e++) s = fmaf(xr[e], wr[e], s);
    out[b * 2 + c] = s;
}

// ---------------------------------------------------------------------------
extern "C" void kernel_launch(void* const* d_in, const int* in_sizes, int n_in,
                              void* d_out, int out_size) {
    const int*   ids  = (const int*)d_in[0];
    const int*   mask = (const int*)d_in[1];
    const float* emb  = (const float*)d_in[2];
    const float* pos  = (const float*)d_in[3];
    const float* ipw  = (const float*)d_in[4];
    const float* ipb  = (const float*)d_in[5];
    const float* opw  = (const float*)d_in[6];
    const float* opb  = (const float*)d_in[7];
    const float* l1g  = (const float*)d_in[8];
    const float* l1b  = (const float*)d_in[9];
    const float* l2g  = (const float*)d_in[10];
    const float* l2b  = (const float*)d_in[11];
    const float* f1w  = (const float*)d_in[12];
    const float* f1b  = (const float*)d_in[13];
    const float* f2w  = (const float*)d_in[14];
    const float* f2b  = (const float*)d_in[15];
    const float* cw   = (const float*)d_in[16];
    const float* cb   = (const float*)d_in[17];
    float* out = (float*)d_out;
    float* attn_base = out + TB * 2;

    float *x, *y;
    __half *qkv16, *x16, *att16, *h16, *w16, *p16;
    cudaGetSymbolAddress((void**)&x,      g_x);
    cudaGetSymbolAddress((void**)&y,      g_y);
    cudaGetSymbolAddress((void**)&qkv16,  g_qkv16);
    cudaGetSymbolAddress((void**)&x16,    g_x16);
    cudaGetSymbolAddress((void**)&att16,  g_att16);
    cudaGetSymbolAddress((void**)&h16,    g_h16);
    cudaGetSymbolAddress((void**)&w16,    g_w16);
    cudaGetSymbolAddress((void**)&p16,    g_p16);

    cudaFuncSetAttribute(hgemm_kernel<0, 0>, cudaFuncAttributeMaxDynamicSharedMemorySize, HG_SMEM);
    cudaFuncSetAttribute(hgemm_kernel<0, 1>, cudaFuncAttributeMaxDynamicSharedMemorySize, HG_SMEM);
    cudaFuncSetAttribute(hgemm_kernel<1, 1>, cudaFuncAttributeMaxDynamicSharedMemorySize, HG_SMEM);
    cudaFuncSetAttribute(attn_av16_kernel, cudaFuncAttributeMaxDynamicSharedMemorySize, AV_SMEM);

    cvtw_kernel<<<W16_TOTAL / 4 / 256, 256>>>(ipw, opw, f1w, f2w, w16);
    embed_kernel<<<(TT * 128) / 256, 256>>>(ids, emb, pos, x, x16);

    for (int l = 0; l < TL; l++) {
        hgemm_kernel<0, 1><<<dim3(QKVW / 128, TT / 128), 128, HG_SMEM>>>(
            x16, w16 + W16_IPW(l), ipb + l * QKVW, nullptr, qkv16, QKVW, TE);

        float* attn_l = attn_base + (size_t)l * TB * TNH * TS * TS;
        attn_fused16_kernel<<<dim3(16, TB * TNH), 256>>>(qkv16, mask, attn_l, p16);
        attn_av16_kernel<<<dim3(8, TB * TNH), 256, AV_SMEM>>>(p16, qkv16, att16);

        hgemm_kernel<0, 0><<<dim3(TE / 128, TT / 128), 128, HG_SMEM>>>(
            att16, w16 + W16_OPW(l), opb + l * TE, y, nullptr, TE, TE);
        add_ln_kernel<<<TT, 128>>>(x, y, l1g + l * TE, l1b + l * TE, x16);

        hgemm_kernel<1, 1><<<dim3(4 * TE / 128, TT / 128), 128, HG_SMEM>>>(
            x16, w16 + W16_F1W(l), f1b + l * 4 * TE, nullptr, h16, 4 * TE, TE);
        hgemm_kernel<0, 0><<<dim3(TE / 128, TT / 128), 128, HG_SMEM>>>(
            h16, w16 + W16_F2W(l), f2b + l * TE, y, nullptr, TE, 4 * TE);
        add_ln_kernel<<<TT, 128>>>(x, y, l2g + l * TE, l2b + l * TE, x16);
    }

    cls_kernel<<<1, 64>>>(x, cw, cb, out);
}

// round 11
// speedup vs baseline: 2.3266x; 1.0359x over previous
#include <cuda_runtime.h>
#include <cuda_fp16.h>
#include <cstdint>
#include <math.h>

// Problem constants
#define TB 32      // batch
#define TS 512     // seq len
#define TE 512     // d_model
#define THD 64     // head dim
#define TNH 8      // heads
#define TL 3       // layers
#define TT (TB*TS) // tokens = 16384
#define QKVW 1536  // 3*E

// Scratch (device globals; allocation-free contract)
__device__ float  g_x[(size_t)TT * TE];        // running hidden fp32   32 MB
__device__ float  g_y[(size_t)TT * TE];        // gemm out fp32         32 MB
__device__ __half g_qkv16[(size_t)TT * QKVW];  // qkv fp16              48 MB
__device__ __half g_x16[(size_t)TT * TE];      // hidden fp16           16 MB
__device__ __half g_att16[(size_t)TT * TE];    // attn concat fp16      16 MB
__device__ __half g_h16[(size_t)TT * 4 * TE];  // ffn hidden fp16       64 MB
#define W16_TOTAL 9437184
__device__ __half g_w16[W16_TOTAL];            // all weights fp16      18 MB
#define W16_IPW(l) ((size_t)(l) * 786432)
#define W16_OPW(l) (2359296 + (size_t)(l) * 262144)
#define W16_F1W(l) (3145728 + (size_t)(l) * 1048576)
#define W16_F2W(l) (6291456 + (size_t)(l) * 1048576)

#define MMA_F16(d, a, b)                                                      \
    asm volatile(                                                             \
        "mma.sync.aligned.m16n8k16.row.col.f32.f16.f16.f32 "                  \
        "{%0,%1,%2,%3}, {%4,%5,%6,%7}, {%8,%9}, {%0,%1,%2,%3};"               \
        : "+f"(d[0]), "+f"(d[1]), "+f"(d[2]), "+f"(d[3])                      \
        : "r"(a[0]), "r"(a[1]), "r"(a[2]), "r"(a[3]), "r"(b[0]), "r"(b[1]))

#define LDSM4(r0, r1, r2, r3, addr)                                           \
    asm volatile("ldmatrix.sync.aligned.m8n8.x4.shared.b16 {%0,%1,%2,%3}, [%4];" \
        : "=r"(r0), "=r"(r1), "=r"(r2), "=r"(r3) : "r"(addr))

#define LDSM2(r0, r1, addr)                                                   \
    asm volatile("ldmatrix.sync.aligned.m8n8.x2.shared.b16 {%0,%1}, [%2];"    \
        : "=r"(r0), "=r"(r1) : "r"(addr))

#define LDSM2T(r0, r1, addr)                                                  \
    asm volatile("ldmatrix.sync.aligned.m8n8.x2.trans.shared.b16 {%0,%1}, [%2];" \
        : "=r"(r0), "=r"(r1) : "r"(addr))

__device__ __forceinline__ void cpa16(uint32_t s, const void* g) {
    asm volatile("cp.async.cg.shared.global [%0], [%1], 16;" :: "r"(s), "l"(g));
}
__device__ __forceinline__ void cpa_commit() {
    asm volatile("cp.async.commit_group;");
}

// fp16 tile swizzles: chunk = 16B unit
// 64B-pitch rows (32 halfs) for hgemm
__device__ __forceinline__ uint32_t hswz(int row, int chunk) {
    return (uint32_t)(row * 64 + (((chunk + (row >> 1)) & 3) << 4));
}
// 128B-pitch rows (64 halfs) for attention tiles
#define ASWZ(row, c8) ((uint32_t)(((row) << 7) | ((((c8) ^ ((row) & 7))) << 4)))
// 1024B-pitch rows (512 halfs) for the P-probability smem tile
#define PSWZ(row, k8) ((uint32_t)(((row) << 10) | \
    (((((k8) & ~7) | (((k8) & 7) ^ ((row) & 7)))) << 4)))

// ---------------------------------------------------------------------------
// Weight conversion fp32 -> fp16 (once per launch, ~40us)
// ---------------------------------------------------------------------------
__global__ __launch_bounds__(256) void cvtw_kernel(
    const float* __restrict__ ipw, const float* __restrict__ opw,
    const float* __restrict__ f1w, const float* __restrict__ f2w,
    __half* __restrict__ w16) {
    size_t i = ((size_t)blockIdx.x * 256 + threadIdx.x) * 4;
    const float* src; size_t off;
    if (i < 2359296)      { src = ipw; off = i; }
    else if (i < 3145728) { src = opw; off = i - 2359296; }
    else if (i < 6291456) { src = f1w; off = i - 3145728; }
    else                  { src = f2w; off = i - 6291456; }
    float4 v = *reinterpret_cast<const float4*>(src + off);
    __half2* dst = reinterpret_cast<__half2*>(w16 + i);
    dst[0] = __floats2half2_rn(v.x, v.y);
    dst[1] = __floats2half2_rn(v.z, v.w);
}

// ---------------------------------------------------------------------------
// Embedding: x fp32 + fp16 twin
// ---------------------------------------------------------------------------
__global__ __launch_bounds__(256) void embed_kernel(
    const int* __restrict__ ids, const float* __restrict__ emb,
    const float* __restrict__ pos, float* __restrict__ x, __half* __restrict__ x16) {
    int idx = blockIdx.x * blockDim.x + threadIdx.x;
    int token = idx >> 7;
    int c = idx & 127;
    float4 e = reinterpret_cast<const float4*>(emb)[(size_t)ids[token] * 128 + c];
    float4 p = reinterpret_cast<const float4*>(pos)[(size_t)(token & (TS - 1)) * 128 + c];
    float4 o;
    o.x = e.x + p.x; o.y = e.y + p.y; o.z = e.z + p.z; o.w = e.w + p.w;
    reinterpret_cast<float4*>(x)[idx] = o;
    __half2* h = reinterpret_cast<__half2*>(x16) + idx * 2;
    h[0] = __floats2half2_rn(o.x, o.y);
    h[1] = __floats2half2_rn(o.z, o.w);
}

// ---------------------------------------------------------------------------
// FP16 tensor-core GEMM (proven): C = A @ W^T + bias, opt GELU,
// fp32 or fp16 output. Block 128x128, 128 thr, warp tile 64x64, 4-stage ring.
// ---------------------------------------------------------------------------
#define HSTG 16384
#define HG_SMEM (4 * HSTG)

template <int ACT, int OUT16>
__global__ __launch_bounds__(128, 2) void hgemm_kernel(
    const __half* __restrict__ A, const __half* __restrict__ W,
    const float* __restrict__ bias, float* __restrict__ C,
    __half* __restrict__ C16, int N, int K) {
    extern __shared__ char smraw[];
    uint32_t base;
    asm("{ .reg .u64 t; cvta.to.shared.u64 t, %1; cvt.u32.u64 %0, t; }"
        : "=r"(base) : "l"(smraw));

    const int t = threadIdx.x;
    const int lane = t & 31;
    const int warp = t >> 5;
    const int wr = (warp >> 1) * 64;
    const int wc = (warp & 1) * 64;
    const int qr = lane >> 2;
    const int qc = lane & 3;

    const int m0 = blockIdx.y * 128;
    const int n0 = blockIdx.x * 128;
    const int KT = K >> 5;

    const int arow = lane & 15;
    const int achk = lane >> 4;
    const int brow = lane & 7;
    const int bchk = (lane >> 3) & 1;

    float acc[4][8][4];
#pragma unroll
    for (int i = 0; i < 4; i++)
#pragma unroll
        for (int j = 0; j < 8; j++)
#pragma unroll
            for (int r = 0; r < 4; r++) acc[i][j][r] = 0.f;

#pragma unroll
    for (int s = 0; s < 3; s++) {
        uint32_t sb = base + s * HSTG;
#pragma unroll
        for (int i = 0; i < 4; i++) {
            int idx = t + 128 * i;
            int row = idx >> 2, c = idx & 3;
            cpa16(sb + hswz(row, c), A + (size_t)(m0 + row) * K + s * 32 + c * 8);
            cpa16(sb + 8192 + hswz(row, c), W + (size_t)(n0 + row) * K + s * 32 + c * 8);
        }
        cpa_commit();
    }

    for (int kt = 0; kt < KT; kt++) {
        int pend = KT - 1 - kt; if (pend > 2) pend = 2;
        if (pend == 2)      asm volatile("cp.async.wait_group 2;");
        else if (pend == 1) asm volatile("cp.async.wait_group 1;");
        else                asm volatile("cp.async.wait_group 0;");
        __syncthreads();

        if (kt + 3 < KT) {
            int j = kt + 3;
            uint32_t sb = base + (j & 3) * HSTG;
#pragma unroll
            for (int i = 0; i < 4; i++) {
                int idx = t + 128 * i;
                int row = idx >> 2, c = idx & 3;
                cpa16(sb + hswz(row, c), A + (size_t)(m0 + row) * K + j * 32 + c * 8);
                cpa16(sb + 8192 + hswz(row, c), W + (size_t)(n0 + row) * K + j * 32 + c * 8);
            }
            cpa_commit();
        } else {
            cpa_commit();
        }

        const uint32_t sb = base + (kt & 3) * HSTG;
#pragma unroll
        for (int s2 = 0; s2 < 2; s2++) {
            uint32_t a[4][4], bw[8][2];
#pragma unroll
            for (int mi = 0; mi < 4; mi++) {
                uint32_t ad = sb + hswz(wr + mi * 16 + arow, 2 * s2 + achk);
                LDSM4(a[mi][0], a[mi][1], a[mi][2], a[mi][3], ad);
            }
#pragma unroll
            for (int ni = 0; ni < 8; ni++) {
                uint32_t bd = sb + 8192 + hswz(wc + ni * 8 + brow, 2 * s2 + bchk);
                LDSM2(bw[ni][0], bw[ni][1], bd);
            }
#pragma unroll
            for (int mi = 0; mi < 4; mi++)
#pragma unroll
                for (int ni = 0; ni < 8; ni++) MMA_F16(acc[mi][ni], a[mi], bw[ni]);
        }
    }

#pragma unroll
    for (int mi = 0; mi < 4; mi++) {
#pragma unroll
        for (int ni = 0; ni < 8; ni++) {
            int col = n0 + wc + ni * 8 + qc * 2;
            float b0 = bias[col], b1 = bias[col + 1];
#pragma unroll
            for (int half = 0; half < 2; half++) {
                int row = m0 + wr + mi * 16 + qr + half * 8;
                float v0 = acc[mi][ni][half * 2 + 0] + b0;
                float v1 = acc[mi][ni][half * 2 + 1] + b1;
                if (ACT == 1) {
                    v0 = 0.5f * v0 * (1.f + erff(v0 * 0.70710678118654752f));
                    v1 = 0.5f * v1 * (1.f + erff(v1 * 0.70710678118654752f));
                }
                if (OUT16) {
                    *reinterpret_cast<__half2*>(C16 + (size_t)row * N + col) =
                        __floats2half2_rn(v0, v1);
                } else {
                    float2 o; o.x = v0; o.y = v1;
                    *reinterpret_cast<float2*>(C + (size_t)row * N + col) = o;
                }
            }
        }
    }
}

// ---------------------------------------------------------------------------
// Fully fused attention: scores + softmax + AV in one kernel.
// Block: 32 q-rows x 512 keys for one (b,h).
// Phase 1: stream K chunks (4-slot ring), fp16 mma scores; softmax in regs;
//          write fp32 probs (required output) + fp16 P to SMEM.
// Phase 2: stream V chunks through the same ring; warp w computes O for head
//          dims [w*8, w*8+8) over all 512 keys (P A-frags from SMEM via
//          ldmatrix, V B-frags via ldmatrix.trans); writes att16.
// Dynamic smem: ring 32KB + Psm 32KB + bias 2KB + red 1.2KB = 68.7KB.
// ---------------------------------------------------------------------------
#define AF_SMEM 68736

__global__ __launch_bounds__(256, 2) void attn_fused16_kernel(
    const __half* __restrict__ qkv16, const int* __restrict__ mask,
    float* __restrict__ attn, __half* __restrict__ att16) {
    extern __shared__ char smraw[];
    uint32_t base;
    asm("{ .reg .u64 t; cvta.to.shared.u64 t, %1; cvt.u32.u64 %0, t; }"
        : "=r"(base) : "l"(smraw));
    const uint32_t pbase = base + 32768;          // Psm (Q tile lives here in phase 1)
    float* biasS = reinterpret_cast<float*>(smraw + 65536);
    float* red   = reinterpret_cast<float*>(smraw + 67584);

    const int t = threadIdx.x, lane = t & 31, warp = t >> 5;
    const int qr = lane >> 2, qc = lane & 3;
    const int bh = blockIdx.y, b = bh >> 3, h = bh & 7;
    const int m0 = blockIdx.x * 32;
    const __half* qb = qkv16 + (size_t)b * TS * QKVW + h * THD;
    const __half* kb = qb + TE;
    const __half* vb = qb + 2 * TE;

    for (int i = t; i < 512; i += 256)
        biasS[i] = (mask[b * TS + i] == 0) ? -1e30f : 0.f;

    // prologue: Q + K0 -> group0; K1 -> group1; K2 -> group2
    {
        int row = t >> 3, c8 = t & 7;
        cpa16(pbase + ASWZ(row, c8), qb + (size_t)(m0 + row) * QKVW + c8 * 8);
#pragma unroll
        for (int i = 0; i < 2; i++) {
            int u = t + 256 * i;
            int kr = u >> 3, kc = u & 7;
            cpa16(base + ASWZ(kr, kc), kb + (size_t)kr * QKVW + kc * 8);
        }
    }
    cpa_commit();
#pragma unroll
    for (int s = 1; s < 3; s++) {
#pragma unroll
        for (int i = 0; i < 2; i++) {
            int u = t + 256 * i;
            int kr = u >> 3, kc = u & 7;
            cpa16(base + s * 8192 + ASWZ(kr, kc), kb + (size_t)(s * 64 + kr) * QKVW + kc * 8);
        }
        cpa_commit();
    }

    float acc[8][2][4];
#pragma unroll
    for (int c = 0; c < 8; c++)
#pragma unroll
        for (int mi = 0; mi < 2; mi++)
#pragma unroll
            for (int r = 0; r < 4; r++) acc[c][mi][r] = 0.f;

    const int arow = lane & 15, achk = lane >> 4;
    const int brow = lane & 7, bchk = (lane >> 3) & 1;

    // ---- Phase 1: QK^T ----
    for (int c = 0; c < 8; c++) {
        if (c < 6)       asm volatile("cp.async.wait_group 2;");
        else if (c == 6) asm volatile("cp.async.wait_group 1;");
        else             asm volatile("cp.async.wait_group 0;");
        __syncthreads();

        if (c + 3 < 8) {
            uint32_t kbn = base + ((c + 3) & 3) * 8192;
#pragma unroll
            for (int i = 0; i < 2; i++) {
                int u = t + 256 * i;
                int kr = u >> 3, kc = u & 7;
                cpa16(kbn + ASWZ(kr, kc), kb + (size_t)((c + 3) * 64 + kr) * QKVW + kc * 8);
            }
            cpa_commit();
        }

        const uint32_t kbc = base + (c & 3) * 8192;
#pragma unroll
        for (int s = 0; s < 4; s++) {
            uint32_t a[2][4], bw[2];
#pragma unroll
            for (int mi = 0; mi < 2; mi++)
                LDSM4(a[mi][0], a[mi][1], a[mi][2], a[mi][3],
                      pbase + ASWZ(mi * 16 + arow, 2 * s + achk));
            LDSM2(bw[0], bw[1], kbc + ASWZ(warp * 8 + brow, 2 * s + bchk));
#pragma unroll
            for (int mi = 0; mi < 2; mi++) MMA_F16(acc[c][mi], a[mi], bw);
        }
    }

    // Early V prefetch: chunks 0..2 into ring slots 0..2 (overlaps softmax).
    // All warps are past the c=7 barrier, so only slot 3 is still being read.
#pragma unroll
    for (int s = 0; s < 3; s++) {
#pragma unroll
        for (int i = 0; i < 2; i++) {
            int u = t + 256 * i;
            int vr = u >> 3, vc = u & 7;
            cpa16(base + s * 8192 + ASWZ(vr, vc), vb + (size_t)(s * 64 + vr) * QKVW + vc * 8);
        }
        cpa_commit();
    }

    // ---- softmax over 512 keys per row (32 rows) ----
    float bm[2][2], bs[2][2];
    const float scale = 0.125f;
#pragma unroll
    for (int mi = 0; mi < 2; mi++) {
#pragma unroll
        for (int h2 = 0; h2 < 2; h2++) {
            float m = -3.4e38f;
#pragma unroll
            for (int c = 0; c < 8; c++) {
                int col = c * 64 + warp * 8 + qc * 2;
                float v0 = acc[c][mi][2 * h2 + 0] * scale + biasS[col];
                float v1 = acc[c][mi][2 * h2 + 1] * scale + biasS[col + 1];
                acc[c][mi][2 * h2 + 0] = v0;
                acc[c][mi][2 * h2 + 1] = v1;
                m = fmaxf(m, fmaxf(v0, v1));
            }
            m = fmaxf(m, __shfl_xor_sync(0xFFFFFFFFu, m, 1));
            m = fmaxf(m, __shfl_xor_sync(0xFFFFFFFFu, m, 2));
            bm[mi][h2] = m;
        }
    }
    if (qc == 0) {
#pragma unroll
        for (int mi = 0; mi < 2; mi++)
#pragma unroll
            for (int h2 = 0; h2 < 2; h2++)
                red[(mi * 16 + qr + h2 * 8) * 9 + warp] = bm[mi][h2];
    }
    __syncthreads();
#pragma unroll
    for (int mi = 0; mi < 2; mi++)
#pragma unroll
        for (int h2 = 0; h2 < 2; h2++) {
            int row = mi * 16 + qr + h2 * 8;
            float m = red[row * 9 + 0];
#pragma unroll
            for (int w2 = 1; w2 < 8; w2++) m = fmaxf(m, red[row * 9 + w2]);
            bm[mi][h2] = m;
        }
    __syncthreads();
#pragma unroll
    for (int mi = 0; mi < 2; mi++) {
#pragma unroll
        for (int h2 = 0; h2 < 2; h2++) {
            float m = bm[mi][h2];
            float s = 0.f;
#pragma unroll
            for (int c = 0; c < 8; c++) {
                float e0 = __expf(acc[c][mi][2 * h2 + 0] - m);
                float e1 = __expf(acc[c][mi][2 * h2 + 1] - m);
                acc[c][mi][2 * h2 + 0] = e0;
                acc[c][mi][2 * h2 + 1] = e1;
                s += e0 + e1;
            }
            s += __shfl_xor_sync(0xFFFFFFFFu, s, 1);
            s += __shfl_xor_sync(0xFFFFFFFFu, s, 2);
            bs[mi][h2] = s;
        }
    }
    if (qc == 0) {
#pragma unroll
        for (int mi = 0; mi < 2; mi++)
#pragma unroll
            for (int h2 = 0; h2 < 2; h2++)
                red[(mi * 16 + qr + h2 * 8) * 9 + warp] = bs[mi][h2];
    }
    __syncthreads();
    // normalize; write fp32 probs (streaming) + fp16 P into SMEM
#pragma unroll
    for (int mi = 0; mi < 2; mi++)
#pragma unroll
        for (int h2 = 0; h2 < 2; h2++) {
            int row = mi * 16 + qr + h2 * 8;
            float s = 0.f;
#pragma unroll
            for (int w2 = 0; w2 < 8; w2++) s += red[row * 9 + w2];
            float inv = 1.f / s;
            float* orow = attn + ((size_t)bh * TS + m0 + row) * TS;
#pragma unroll
            for (int c = 0; c < 8; c++) {
                int col = c * 64 + warp * 8 + qc * 2;
                float2 o;
                o.x = acc[c][mi][2 * h2 + 0] * inv;
                o.y = acc[c][mi][2 * h2 + 1] * inv;
                __stcs(reinterpret_cast<float2*>(orow + col), o);
                __half2 hv = __floats2half2_rn(o.x, o.y);
                uint32_t u = *reinterpret_cast<uint32_t*>(&hv);
                asm volatile("st.shared.b32 [%0], %1;"
                             :: "r"(pbase + PSWZ(row, c * 8 + warp) + qc * 4), "r"(u)
                             : "memory");
            }
        }

    // ---- Phase 2: O = P @ V, warp w owns head dims [w*8, w*8+8) ----
    float oacc[2][4];
#pragma unroll
    for (int mi = 0; mi < 2; mi++)
#pragma unroll
        for (int r = 0; r < 4; r++) oacc[mi][r] = 0.f;

    for (int v = 0; v < 8; v++) {
        if (v < 6)       asm volatile("cp.async.wait_group 2;");
        else if (v == 6) asm volatile("cp.async.wait_group 1;");
        else             asm volatile("cp.async.wait_group 0;");
        __syncthreads();   // also orders Psm stores before first reads (v=0)

        if (v + 3 < 8) {
            uint32_t vbn = base + ((v + 3) & 3) * 8192;
#pragma unroll
            for (int i = 0; i < 2; i++) {
                int u = t + 256 * i;
                int vr = u >> 3, vc = u & 7;
                cpa16(vbn + ASWZ(vr, vc), vb + (size_t)((v + 3) * 64 + vr) * QKVW + vc * 8);
            }
            cpa_commit();
        }

        const uint32_t vbc = base + (v & 3) * 8192;
#pragma unroll
        for (int s = 0; s < 4; s++) {
            uint32_t a[2][4], bw[2];
#pragma unroll
            for (int mi = 0; mi < 2; mi++)
                LDSM4(a[mi][0], a[mi][1], a[mi][2], a[mi][3],
                      pbase + PSWZ(mi * 16 + arow, v * 8 + s * 2 + achk));
            LDSM2T(bw[0], bw[1], vbc + ASWZ(s * 16 + (lane & 15), warp));
#pragma unroll
            for (int mi = 0; mi < 2; mi++) MMA_F16(oacc[mi], a[mi], bw);
        }
    }

    // epilogue: write att16 (concat layout)
#pragma unroll
    for (int mi = 0; mi < 2; mi++) {
#pragma unroll
        for (int h2 = 0; h2 < 2; h2++) {
            int row = m0 + mi * 16 + qr + h2 * 8;
            int col = h * THD + warp * 8 + qc * 2;
            *reinterpret_cast<__half2*>(att16 + ((size_t)b * TS + row) * TE + col) =
                __floats2half2_rn(oacc[mi][2 * h2 + 0], oacc[mi][2 * h2 + 1]);
        }
    }
}

// ---------------------------------------------------------------------------
// Fused residual + LayerNorm; writes fp32 x and fp16 twin.
// ---------------------------------------------------------------------------
__global__ __launch_bounds__(128) void add_ln_kernel(
    float* __restrict__ x, const float* __restrict__ y,
    const float* __restrict__ g, const float* __restrict__ bb,
    __half* __restrict__ x16) {
    const size_t row = blockIdx.x;
    const int t = threadIdx.x;
    float4 xv = reinterpret_cast<float4*>(x + row * TE)[t];
    float4 yv = reinterpret_cast<const float4*>(y + row * TE)[t];
    float4 s;
    s.x = xv.x + yv.x; s.y = xv.y + yv.y; s.z = xv.z + yv.z; s.w = xv.w + yv.w;
    float sum = s.x + s.y + s.z + s.w;
    float sq = s.x * s.x + s.y * s.y + s.z * s.z + s.w * s.w;
#pragma unroll
    for (int o = 16; o; o >>= 1) {
        sum += __shfl_xor_sync(0xFFFFFFFFu, sum, o);
        sq  += __shfl_xor_sync(0xFFFFFFFFu, sq, o);
    }
    __shared__ float s1[4], s2[4];
    if ((t & 31) == 0) { s1[t >> 5] = sum; s2[t >> 5] = sq; }
    __syncthreads();
    sum = s1[0] + s1[1] + s1[2] + s1[3];
    sq  = s2[0] + s2[1] + s2[2] + s2[3];
    const float mean = sum * (1.f / TE);
    const float var = sq * (1.f / TE) - mean * mean;
    const float rstd = rsqrtf(var + 1e-5f);
    float4 gv = reinterpret_cast<const float4*>(g)[t];
    float4 bv = reinterpret_cast<const float4*>(bb)[t];
    float4 o;
    o.x = (s.x - mean) * rstd * gv.x + bv.x;
    o.y = (s.y - mean) * rstd * gv.y + bv.y;
    o.z = (s.z - mean) * rstd * gv.z + bv.z;
    o.w = (s.w - mean) * rstd * gv.w + bv.w;
    reinterpret_cast<float4*>(x + row * TE)[t] = o;
    __half2* hx = reinterpret_cast<__half2*>(x16 + row * TE) + t * 2;
    hx[0] = __floats2half2_rn(o.x, o.y);
    hx[1] = __floats2half2_rn(o.z, o.w);
}

// ---------------------------------------------------------------------------
// CLS head
// ---------------------------------------------------------------------------
__global__ void cls_kernel(const float* __restrict__ x, const float* __restrict__ w,
                           const float* __restrict__ cb, float* __restrict__ out) {
    int t = threadIdx.x;
    if (t >= TB * 2) return;
    int b = t >> 1, c = t & 1;
    const float* xr = x + (size_t)b * TS * TE;
    const float* wr = w + c * TE;
    float s = cb[c];
    for (int e = 0; e < TE; e++) s = fmaf(xr[e], wr[e], s);
    out[b * 2 + c] = s;
}

// ---------------------------------------------------------------------------
extern "C" void kernel_launch(void* const* d_in, const int* in_sizes, int n_in,
                              void* d_out, int out_size) {
    const int*   ids  = (const int*)d_in[0];
    const int*   mask = (const int*)d_in[1];
    const float* emb  = (const float*)d_in[2];
    const float* pos  = (const float*)d_in[3];
    const float* ipw  = (const float*)d_in[4];
    const float* ipb  = (const float*)d_in[5];
    const float* opw  = (const float*)d_in[6];
    const float* opb  = (const float*)d_in[7];
    const float* l1g  = (const float*)d_in[8];
    const float* l1b  = (const float*)d_in[9];
    const float* l2g  = (const float*)d_in[10];
    const float* l2b  = (const float*)d_in[11];
    const float* f1w  = (const float*)d_in[12];
    const float* f1b  = (const float*)d_in[13];
    const float* f2w  = (const float*)d_in[14];
    const float* f2b  = (const float*)d_in[15];
    const float* cw   = (const float*)d_in[16];
    const float* cb   = (const float*)d_in[17];
    float* out = (float*)d_out;
    float* attn_base = out + TB * 2;

    float *x, *y;
    __half *qkv16, *x16, *att16, *h16, *w16;
    cudaGetSymbolAddress((void**)&x,      g_x);
    cudaGetSymbolAddress((void**)&y,      g_y);
    cudaGetSymbolAddress((void**)&qkv16,  g_qkv16);
    cudaGetSymbolAddress((void**)&x16,    g_x16);
    cudaGetSymbolAddress((void**)&att16,  g_att16);
    cudaGetSymbolAddress((void**)&h16,    g_h16);
    cudaGetSymbolAddress((void**)&w16,    g_w16);

    cudaFuncSetAttribute(hgemm_kernel<0, 0>, cudaFuncAttributeMaxDynamicSharedMemorySize, HG_SMEM);
    cudaFuncSetAttribute(hgemm_kernel<0, 1>, cudaFuncAttributeMaxDynamicSharedMemorySize, HG_SMEM);
    cudaFuncSetAttribute(hgemm_kernel<1, 1>, cudaFuncAttributeMaxDynamicSharedMemorySize, HG_SMEM);
    cudaFuncSetAttribute(attn_fused16_kernel, cudaFuncAttributeMaxDynamicSharedMemorySize, AF_SMEM);

    cvtw_kernel<<<W16_TOTAL / 4 / 256, 256>>>(ipw, opw, f1w, f2w, w16);
    embed_kernel<<<(TT * 128) / 256, 256>>>(ids, emb, pos, x, x16);

    for (int l = 0; l < TL; l++) {
        hgemm_kernel<0, 1><<<dim3(QKVW / 128, TT / 128), 128, HG_SMEM>>>(
            x16, w16 + W16_IPW(l), ipb + l * QKVW, nullptr, qkv16, QKVW, TE);

        float* attn_l = attn_base + (size_t)l * TB * TNH * TS * TS;
        attn_fused16_kernel<<<dim3(16, TB * TNH), 256, AF_SMEM>>>(
            qkv16, mask, attn_l, att16);

        hgemm_kernel<0, 0><<<dim3(TE / 128, TT / 128), 128, HG_SMEM>>>(
            att16, w16 + W16_OPW(l), opb + l * TE, y, nullptr, TE, TE);
        add_ln_kernel<<<TT, 128>>>(x, y, l1g + l * TE, l1b + l * TE, x16);

        hgemm_kernel<1, 1><<<dim3(4 * TE / 128, TT / 128), 128, HG_SMEM>>>(
            x16, w16 + W16_F1W(l), f1b + l * 4 * TE, nullptr, h16, 4 * TE, TE);
        hgemm_kernel<0, 0><<<dim3(TE / 128, TT / 128), 128, HG_SMEM>>>(
            h16, w16 + W16_F2W(l), f2b + l * TE, y, nullptr, TE, 4 * TE);
        add_ln_kernel<<<TT, 128>>>(x, y, l2g + l * TE, l2b + l * TE, x16);
    }

    cls_kernel<<<1, 64>>>(x, cw, cb, out);
}

// round 12
// speedup vs baseline: 2.3593x; 1.0141x over previous
#include <cuda_runtime.h>
#include <cuda_fp16.h>
#include <cstdint>
#include <math.h>

// Problem constants
#define TB 32      // batch
#define TS 512     // seq len
#define TE 512     // d_model
#define THD 64     // head dim
#define TNH 8      // heads
#define TL 3       // layers
#define TT (TB*TS) // tokens = 16384
#define QKVW 1536  // 3*E

// Scratch (device globals; allocation-free contract)
__device__ float  g_x[(size_t)TT * TE];        // running hidden fp32   32 MB
__device__ float  g_y[(size_t)TT * TE];        // gemm out fp32         32 MB
__device__ __half g_qkv16[(size_t)TT * QKVW];  // qkv fp16              48 MB
__device__ __half g_x16[(size_t)TT * TE];      // hidden fp16           16 MB
__device__ __half g_att16[(size_t)TT * TE];    // attn concat fp16      16 MB
__device__ __half g_h16[(size_t)TT * 4 * TE];  // ffn hidden fp16       64 MB
#define W16_TOTAL 9437184
__device__ __half g_w16[W16_TOTAL];            // all weights fp16      18 MB
#define W16_IPW(l) ((size_t)(l) * 786432)
#define W16_OPW(l) (2359296 + (size_t)(l) * 262144)
#define W16_F1W(l) (3145728 + (size_t)(l) * 1048576)
#define W16_F2W(l) (6291456 + (size_t)(l) * 1048576)

#define MMA_F16(d, a, b)                                                      \
    asm volatile(                                                             \
        "mma.sync.aligned.m16n8k16.row.col.f32.f16.f16.f32 "                  \
        "{%0,%1,%2,%3}, {%4,%5,%6,%7}, {%8,%9}, {%0,%1,%2,%3};"               \
        : "+f"(d[0]), "+f"(d[1]), "+f"(d[2]), "+f"(d[3])                      \
        : "r"(a[0]), "r"(a[1]), "r"(a[2]), "r"(a[3]), "r"(b[0]), "r"(b[1]))

#define LDSM4(r0, r1, r2, r3, addr)                                           \
    asm volatile("ldmatrix.sync.aligned.m8n8.x4.shared.b16 {%0,%1,%2,%3}, [%4];" \
        : "=r"(r0), "=r"(r1), "=r"(r2), "=r"(r3) : "r"(addr))

#define LDSM2(r0, r1, addr)                                                   \
    asm volatile("ldmatrix.sync.aligned.m8n8.x2.shared.b16 {%0,%1}, [%2];"    \
        : "=r"(r0), "=r"(r1) : "r"(addr))

#define LDSM4T(r0, r1, r2, r3, addr)                                          \
    asm volatile("ldmatrix.sync.aligned.m8n8.x4.trans.shared.b16 {%0,%1,%2,%3}, [%4];" \
        : "=r"(r0), "=r"(r1), "=r"(r2), "=r"(r3) : "r"(addr))

__device__ __forceinline__ void cpa16(uint32_t s, const void* g) {
    asm volatile("cp.async.cg.shared.global [%0], [%1], 16;" :: "r"(s), "l"(g));
}
__device__ __forceinline__ void cpa_commit() {
    asm volatile("cp.async.commit_group;");
}

// fp16 tile swizzles: chunk = 16B unit
// 64B-pitch rows (32 halfs) for hgemm
__device__ __forceinline__ uint32_t hswz(int row, int chunk) {
    return (uint32_t)(row * 64 + (((chunk + (row >> 1)) & 3) << 4));
}
// 128B-pitch rows (64 halfs) for attention tiles
#define ASWZ(row, c8) ((uint32_t)(((row) << 7) | ((((c8) ^ ((row) & 7))) << 4)))
// 1024B-pitch rows (512 halfs) for the P-probability smem tile
#define PSWZ(row, k8) ((uint32_t)(((row) << 10) | \
    (((((k8) & ~7) | (((k8) & 7) ^ ((row) & 7)))) << 4)))

// ---------------------------------------------------------------------------
// Weight conversion fp32 -> fp16 (once per launch, ~40us)
// ---------------------------------------------------------------------------
__global__ __launch_bounds__(256) void cvtw_kernel(
    const float* __restrict__ ipw, const float* __restrict__ opw,
    const float* __restrict__ f1w, const float* __restrict__ f2w,
    __half* __restrict__ w16) {
    size_t i = ((size_t)blockIdx.x * 256 + threadIdx.x) * 4;
    const float* src; size_t off;
    if (i < 2359296)      { src = ipw; off = i; }
    else if (i < 3145728) { src = opw; off = i - 2359296; }
    else if (i < 6291456) { src = f1w; off = i - 3145728; }
    else                  { src = f2w; off = i - 6291456; }
    float4 v = *reinterpret_cast<const float4*>(src + off);
    __half2* dst = reinterpret_cast<__half2*>(w16 + i);
    dst[0] = __floats2half2_rn(v.x, v.y);
    dst[1] = __floats2half2_rn(v.z, v.w);
}

// ---------------------------------------------------------------------------
// Embedding: x fp32 + fp16 twin
// ---------------------------------------------------------------------------
__global__ __launch_bounds__(256) void embed_kernel(
    const int* __restrict__ ids, const float* __restrict__ emb,
    const float* __restrict__ pos, float* __restrict__ x, __half* __restrict__ x16) {
    int idx = blockIdx.x * blockDim.x + threadIdx.x;
    int token = idx >> 7;
    int c = idx & 127;
    float4 e = reinterpret_cast<const float4*>(emb)[(size_t)ids[token] * 128 + c];
    float4 p = reinterpret_cast<const float4*>(pos)[(size_t)(token & (TS - 1)) * 128 + c];
    float4 o;
    o.x = e.x + p.x; o.y = e.y + p.y; o.z = e.z + p.z; o.w = e.w + p.w;
    reinterpret_cast<float4*>(x)[idx] = o;
    __half2* h = reinterpret_cast<__half2*>(x16) + idx * 2;
    h[0] = __floats2half2_rn(o.x, o.y);
    h[1] = __floats2half2_rn(o.z, o.w);
}

// ---------------------------------------------------------------------------
// FP16 tensor-core GEMM (proven): C = A @ W^T + bias, opt GELU,
// fp32 or fp16 output. Block 128x128, 128 thr, warp tile 64x64, 4-stage ring.
// ---------------------------------------------------------------------------
#define HSTG 16384
#define HG_SMEM (4 * HSTG)

template <int ACT, int OUT16>
__global__ __launch_bounds__(128, 2) void hgemm_kernel(
    const __half* __restrict__ A, const __half* __restrict__ W,
    const float* __restrict__ bias, float* __restrict__ C,
    __half* __restrict__ C16, int N, int K) {
    extern __shared__ char smraw[];
    uint32_t base;
    asm("{ .reg .u64 t; cvta.to.shared.u64 t, %1; cvt.u32.u64 %0, t; }"
        : "=r"(base) : "l"(smraw));

    const int t = threadIdx.x;
    const int lane = t & 31;
    const int warp = t >> 5;
    const int wr = (warp >> 1) * 64;
    const int wc = (warp & 1) * 64;
    const int qr = lane >> 2;
    const int qc = lane & 3;

    const int m0 = blockIdx.y * 128;
    const int n0 = blockIdx.x * 128;
    const int KT = K >> 5;

    const int arow = lane & 15;
    const int achk = lane >> 4;
    const int brow = lane & 7;
    const int bchk = (lane >> 3) & 1;

    float acc[4][8][4];
#pragma unroll
    for (int i = 0; i < 4; i++)
#pragma unroll
        for (int j = 0; j < 8; j++)
#pragma unroll
            for (int r = 0; r < 4; r++) acc[i][j][r] = 0.f;

#pragma unroll
    for (int s = 0; s < 3; s++) {
        uint32_t sb = base + s * HSTG;
#pragma unroll
        for (int i = 0; i < 4; i++) {
            int idx = t + 128 * i;
            int row = idx >> 2, c = idx & 3;
            cpa16(sb + hswz(row, c), A + (size_t)(m0 + row) * K + s * 32 + c * 8);
            cpa16(sb + 8192 + hswz(row, c), W + (size_t)(n0 + row) * K + s * 32 + c * 8);
        }
        cpa_commit();
    }

    for (int kt = 0; kt < KT; kt++) {
        int pend = KT - 1 - kt; if (pend > 2) pend = 2;
        if (pend == 2)      asm volatile("cp.async.wait_group 2;");
        else if (pend == 1) asm volatile("cp.async.wait_group 1;");
        else                asm volatile("cp.async.wait_group 0;");
        __syncthreads();

        if (kt + 3 < KT) {
            int j = kt + 3;
            uint32_t sb = base + (j & 3) * HSTG;
#pragma unroll
            for (int i = 0; i < 4; i++) {
                int idx = t + 128 * i;
                int row = idx >> 2, c = idx & 3;
                cpa16(sb + hswz(row, c), A + (size_t)(m0 + row) * K + j * 32 + c * 8);
                cpa16(sb + 8192 + hswz(row, c), W + (size_t)(n0 + row) * K + j * 32 + c * 8);
            }
            cpa_commit();
        } else {
            cpa_commit();
        }

        const uint32_t sb = base + (kt & 3) * HSTG;
#pragma unroll
        for (int s2 = 0; s2 < 2; s2++) {
            uint32_t a[4][4], bw[8][2];
#pragma unroll
            for (int mi = 0; mi < 4; mi++) {
                uint32_t ad = sb + hswz(wr + mi * 16 + arow, 2 * s2 + achk);
                LDSM4(a[mi][0], a[mi][1], a[mi][2], a[mi][3], ad);
            }
#pragma unroll
            for (int ni = 0; ni < 8; ni++) {
                uint32_t bd = sb + 8192 + hswz(wc + ni * 8 + brow, 2 * s2 + bchk);
                LDSM2(bw[ni][0], bw[ni][1], bd);
            }
#pragma unroll
            for (int mi = 0; mi < 4; mi++)
#pragma unroll
                for (int ni = 0; ni < 8; ni++) MMA_F16(acc[mi][ni], a[mi], bw[ni]);
        }
    }

#pragma unroll
    for (int mi = 0; mi < 4; mi++) {
#pragma unroll
        for (int ni = 0; ni < 8; ni++) {
            int col = n0 + wc + ni * 8 + qc * 2;
            float b0 = bias[col], b1 = bias[col + 1];
#pragma unroll
            for (int half = 0; half < 2; half++) {
                int row = m0 + wr + mi * 16 + qr + half * 8;
                float v0 = acc[mi][ni][half * 2 + 0] + b0;
                float v1 = acc[mi][ni][half * 2 + 1] + b1;
                if (ACT == 1) {
                    v0 = 0.5f * v0 * (1.f + erff(v0 * 0.70710678118654752f));
                    v1 = 0.5f * v1 * (1.f + erff(v1 * 0.70710678118654752f));
                }
                if (OUT16) {
                    *reinterpret_cast<__half2*>(C16 + (size_t)row * N + col) =
                        __floats2half2_rn(v0, v1);
                } else {
                    float2 o; o.x = v0; o.y = v1;
                    *reinterpret_cast<float2*>(C + (size_t)row * N + col) = o;
                }
            }
        }
    }
}

// ---------------------------------------------------------------------------
// Fully fused attention v2: scores + softmax + AV, K/V fully smem-resident.
// Block: 32 q-rows x 512 keys for one (b,h).
// SMEM: [0,64K) K then V (512 rows x 128B, ASWZ); [64K,96K) Q then P (PSWZ);
//       bias 2KB; red 1.2KB. Total 101504 B; 2 blocks/SM.
// Phase 1: s-outer/chunk-inner (Q frags loaded once per s; K via paired-chunk
//          LDSM4). Phase 2: V via x4-trans ldmatrix, 2 wait-points each.
// ---------------------------------------------------------------------------
#define AF_SMEM 101504

__global__ __launch_bounds__(256, 2) void attn_fused16_kernel(
    const __half* __restrict__ qkv16, const int* __restrict__ mask,
    float* __restrict__ attn, __half* __restrict__ att16) {
    extern __shared__ char smraw[];
    uint32_t base;
    asm("{ .reg .u64 t; cvta.to.shared.u64 t, %1; cvt.u32.u64 %0, t; }"
        : "=r"(base) : "l"(smraw));
    const uint32_t pbase = base + 65536;          // Q (phase 1) then P
    float* biasS = reinterpret_cast<float*>(smraw + 98304);
    float* red   = reinterpret_cast<float*>(smraw + 100352);

    const int t = threadIdx.x, lane = t & 31, warp = t >> 5;
    const int qr = lane >> 2, qc = lane & 3;
    const int bh = blockIdx.y, b = bh >> 3, h = bh & 7;
    const int m0 = blockIdx.x * 32;
    const __half* qb = qkv16 + (size_t)b * TS * QKVW + h * THD;
    const __half* kb = qb + TE;
    const __half* vb = qb + 2 * TE;

    for (int i = t; i < 512; i += 256)
        biasS[i] = (mask[b * TS + i] == 0) ? -1e30f : 0.f;

    // prologue: Q + K keys 0..255 -> group A; K keys 256..511 -> group B
    {
        int row = t >> 3, c8 = t & 7;
        cpa16(pbase + ASWZ(row, c8), qb + (size_t)(m0 + row) * QKVW + c8 * 8);
#pragma unroll
        for (int i = 0; i < 8; i++) {
            int u = t + 256 * i;
            int kr = u >> 3, kc = u & 7;
            cpa16(base + ASWZ(kr, kc), kb + (size_t)kr * QKVW + kc * 8);
        }
    }
    cpa_commit();
#pragma unroll
    for (int i = 0; i < 8; i++) {
        int u = t + 256 * i;
        int kr = 256 + (u >> 3), kc = u & 7;
        cpa16(base + ASWZ(kr, kc), kb + (size_t)kr * QKVW + kc * 8);
    }
    cpa_commit();

    float acc[8][2][4];
#pragma unroll
    for (int c = 0; c < 8; c++)
#pragma unroll
        for (int mi = 0; mi < 2; mi++)
#pragma unroll
            for (int r = 0; r < 4; r++) acc[c][mi][r] = 0.f;

    const int arow = lane & 15, achk = lane >> 4;
    // phase-1 K paired-chunk LDSM4 addressing components
    const int kchk_off = lane >> 4;        // 0: chunk c, 1: chunk c+1
    const int kk_half  = (lane >> 3) & 1;  // k-chunk half within k16 step
    const int krow8    = lane & 7;

    // ---- Phase 1: QK^T (s-outer, chunk-inner) ----
    asm volatile("cp.async.wait_group 1;");
    __syncthreads();
#pragma unroll
    for (int hf = 0; hf < 2; hf++) {
        if (hf == 1) {
            asm volatile("cp.async.wait_group 0;");
            __syncthreads();
        }
#pragma unroll
        for (int s = 0; s < 4; s++) {
            uint32_t qf[2][4];
#pragma unroll
            for (int mi = 0; mi < 2; mi++)
                LDSM4(qf[mi][0], qf[mi][1], qf[mi][2], qf[mi][3],
                      pbase + ASWZ(mi * 16 + arow, 2 * s + achk));
#pragma unroll
            for (int cc = 0; cc < 2; cc++) {
                const int c = hf * 4 + cc * 2;
                uint32_t k4[4];
                LDSM4(k4[0], k4[1], k4[2], k4[3],
                      base + ASWZ((c + kchk_off) * 64 + warp * 8 + krow8,
                                  2 * s + kk_half));
#pragma unroll
                for (int mi = 0; mi < 2; mi++) {
                    MMA_F16(acc[c][mi], qf[mi], (k4 + 0));
                    MMA_F16(acc[c + 1][mi], qf[mi], (k4 + 2));
                }
            }
        }
    }
    __syncthreads();   // all K reads done; V may overwrite

    // Issue V loads (overlap with softmax): keys 0..255 -> group A; 256..511 -> B
#pragma unroll
    for (int i = 0; i < 8; i++) {
        int u = t + 256 * i;
        int vr = u >> 3, vc = u & 7;
        cpa16(base + ASWZ(vr, vc), vb + (size_t)vr * QKVW + vc * 8);
    }
    cpa_commit();
#pragma unroll
    for (int i = 0; i < 8; i++) {
        int u = t + 256 * i;
        int vr = 256 + (u >> 3), vc = u & 7;
        cpa16(base + ASWZ(vr, vc), vb + (size_t)vr * QKVW + vc * 8);
    }
    cpa_commit();

    // ---- softmax over 512 keys per row (32 rows) ----
    float bm[2][2], bs[2][2];
    const float scale = 0.125f;
#pragma unroll
    for (int mi = 0; mi < 2; mi++) {
#pragma unroll
        for (int h2 = 0; h2 < 2; h2++) {
            float m = -3.4e38f;
#pragma unroll
            for (int c = 0; c < 8; c++) {
                int col = c * 64 + warp * 8 + qc * 2;
                float v0 = acc[c][mi][2 * h2 + 0] * scale + biasS[col];
                float v1 = acc[c][mi][2 * h2 + 1] * scale + biasS[col + 1];
                acc[c][mi][2 * h2 + 0] = v0;
                acc[c][mi][2 * h2 + 1] = v1;
                m = fmaxf(m, fmaxf(v0, v1));
            }
            m = fmaxf(m, __shfl_xor_sync(0xFFFFFFFFu, m, 1));
            m = fmaxf(m, __shfl_xor_sync(0xFFFFFFFFu, m, 2));
            bm[mi][h2] = m;
        }
    }
    if (qc == 0) {
#pragma unroll
        for (int mi = 0; mi < 2; mi++)
#pragma unroll
            for (int h2 = 0; h2 < 2; h2++)
                red[(mi * 16 + qr + h2 * 8) * 9 + warp] = bm[mi][h2];
    }
    __syncthreads();
#pragma unroll
    for (int mi = 0; mi < 2; mi++)
#pragma unroll
        for (int h2 = 0; h2 < 2; h2++) {
            int row = mi * 16 + qr + h2 * 8;
            float m = red[row * 9 + 0];
#pragma unroll
            for (int w2 = 1; w2 < 8; w2++) m = fmaxf(m, red[row * 9 + w2]);
            bm[mi][h2] = m;
        }
    __syncthreads();
#pragma unroll
    for (int mi = 0; mi < 2; mi++) {
#pragma unroll
        for (int h2 = 0; h2 < 2; h2++) {
            float m = bm[mi][h2];
            float s = 0.f;
#pragma unroll
            for (int c = 0; c < 8; c++) {
                float e0 = __expf(acc[c][mi][2 * h2 + 0] - m);
                float e1 = __expf(acc[c][mi][2 * h2 + 1] - m);
                acc[c][mi][2 * h2 + 0] = e0;
                acc[c][mi][2 * h2 + 1] = e1;
                s += e0 + e1;
            }
            s += __shfl_xor_sync(0xFFFFFFFFu, s, 1);
            s += __shfl_xor_sync(0xFFFFFFFFu, s, 2);
            bs[mi][h2] = s;
        }
    }
    if (qc == 0) {
#pragma unroll
        for (int mi = 0; mi < 2; mi++)
#pragma unroll
            for (int h2 = 0; h2 < 2; h2++)
                red[(mi * 16 + qr + h2 * 8) * 9 + warp] = bs[mi][h2];
    }
    __syncthreads();
    // normalize; write fp32 probs (streaming) + fp16 P into SMEM
#pragma unroll
    for (int mi = 0; mi < 2; mi++)
#pragma unroll
        for (int h2 = 0; h2 < 2; h2++) {
            int row = mi * 16 + qr + h2 * 8;
            float s = 0.f;
#pragma unroll
            for (int w2 = 0; w2 < 8; w2++) s += red[row * 9 + w2];
            float inv = 1.f / s;
            float* orow = attn + ((size_t)bh * TS + m0 + row) * TS;
#pragma unroll
            for (int c = 0; c < 8; c++) {
                int col = c * 64 + warp * 8 + qc * 2;
                float2 o;
                o.x = acc[c][mi][2 * h2 + 0] * inv;
                o.y = acc[c][mi][2 * h2 + 1] * inv;
                __stcs(reinterpret_cast<float2*>(orow + col), o);
                __half2 hv = __floats2half2_rn(o.x, o.y);
                uint32_t u = *reinterpret_cast<uint32_t*>(&hv);
                asm volatile("st.shared.b32 [%0], %1;"
                             :: "r"(pbase + PSWZ(row, c * 8 + warp) + qc * 4), "r"(u)
                             : "memory");
            }
        }

    // ---- Phase 2: O = P @ V; warp w owns head dims [w*8, w*8+8) ----
    float oacc[2][4];
#pragma unroll
    for (int mi = 0; mi < 2; mi++)
#pragma unroll
        for (int r = 0; r < 4; r++) oacc[mi][r] = 0.f;

    asm volatile("cp.async.wait_group 1;");
    __syncthreads();   // V keys 0..255 + all P stores visible
#pragma unroll
    for (int hf = 0; hf < 2; hf++) {
        if (hf == 1) {
            asm volatile("cp.async.wait_group 0;");
            __syncthreads();
        }
#pragma unroll
        for (int ks2 = 0; ks2 < 8; ks2++) {
            const int ks = hf * 16 + ks2 * 2;   // pair of k16 steps
            uint32_t bw4[4];
            LDSM4T(bw4[0], bw4[1], bw4[2], bw4[3],
                   base + ASWZ(ks * 16 + lane, warp));
#pragma unroll
            for (int k2 = 0; k2 < 2; k2++) {
                uint32_t af[2][4];
#pragma unroll
                for (int mi = 0; mi < 2; mi++)
                    LDSM4(af[mi][0], af[mi][1], af[mi][2], af[mi][3],
                          pbase + PSWZ(mi * 16 + arow, (ks + k2) * 2 + achk));
#pragma unroll
                for (int mi = 0; mi < 2; mi++)
                    MMA_F16(oacc[mi], af[mi], (bw4 + 2 * k2));
            }
        }
    }

    // epilogue: write att16 (concat layout)
#pragma unroll
    for (int mi = 0; mi < 2; mi++) {
#pragma unroll
        for (int h2 = 0; h2 < 2; h2++) {
            int row = m0 + mi * 16 + qr + h2 * 8;
            int col = h * THD + warp * 8 + qc * 2;
            *reinterpret_cast<__half2*>(att16 + ((size_t)b * TS + row) * TE + col) =
                __floats2half2_rn(oacc[mi][2 * h2 + 0], oacc[mi][2 * h2 + 1]);
        }
    }
}

// ---------------------------------------------------------------------------
// Fused residual + LayerNorm; writes fp32 x and fp16 twin.
// ---------------------------------------------------------------------------
__global__ __launch_bounds__(128) void add_ln_kernel(
    float* __restrict__ x, const float* __restrict__ y,
    const float* __restrict__ g, const float* __restrict__ bb,
    __half* __restrict__ x16) {
    const size_t row = blockIdx.x;
    const int t = threadIdx.x;
    float4 xv = reinterpret_cast<float4*>(x + row * TE)[t];
    float4 yv = reinterpret_cast<const float4*>(y + row * TE)[t];
    float4 s;
    s.x = xv.x + yv.x; s.y = xv.y + yv.y; s.z = xv.z + yv.z; s.w = xv.w + yv.w;
    float sum = s.x + s.y + s.z + s.w;
    float sq = s.x * s.x + s.y * s.y + s.z * s.z + s.w * s.w;
#pragma unroll
    for (int o = 16; o; o >>= 1) {
        sum += __shfl_xor_sync(0xFFFFFFFFu, sum, o);
        sq  += __shfl_xor_sync(0xFFFFFFFFu, sq, o);
    }
    __shared__ float s1[4], s2[4];
    if ((t & 31) == 0) { s1[t >> 5] = sum; s2[t >> 5] = sq; }
    __syncthreads();
    sum = s1[0] + s1[1] + s1[2] + s1[3];
    sq  = s2[0] + s2[1] + s2[2] + s2[3];
    const float mean = sum * (1.f / TE);
    const float var = sq * (1.f / TE) - mean * mean;
    const float rstd = rsqrtf(var + 1e-5f);
    float4 gv = reinterpret_cast<const float4*>(g)[t];
    float4 bv = reinterpret_cast<const float4*>(bb)[t];
    float4 o;
    o.x = (s.x - mean) * rstd * gv.x + bv.x;
    o.y = (s.y - mean) * rstd * gv.y + bv.y;
    o.z = (s.z - mean) * rstd * gv.z + bv.z;
    o.w = (s.w - mean) * rstd * gv.w + bv.w;
    reinterpret_cast<float4*>(x + row * TE)[t] = o;
    __half2* hx = reinterpret_cast<__half2*>(x16 + row * TE) + t * 2;
    hx[0] = __floats2half2_rn(o.x, o.y);
    hx[1] = __floats2half2_rn(o.z, o.w);
}

// ---------------------------------------------------------------------------
// CLS head
// ---------------------------------------------------------------------------
__global__ void cls_kernel(const float* __restrict__ x, const float* __restrict__ w,
                           const float* __restrict__ cb, float* __restrict__ out) {
    int t = threadIdx.x;
    if (t >= TB * 2) return;
    int b = t >> 1, c = t & 1;
    const float* xr = x + (size_t)b * TS * TE;
    const float* wr = w + c * TE;
    float s = cb[c];
    for (int e = 0; e < TE; e++) s = fmaf(xr[e], wr[e], s);
    out[b * 2 + c] = s;
}

// ---------------------------------------------------------------------------
extern "C" void kernel_launch(void* const* d_in, const int* in_sizes, int n_in,
                              void* d_out, int out_size) {
    const int*   ids  = (const int*)d_in[0];
    const int*   mask = (const int*)d_in[1];
    const float* emb  = (const float*)d_in[2];
    const float* pos  = (const float*)d_in[3];
    const float* ipw  = (const float*)d_in[4];
    const float* ipb  = (const float*)d_in[5];
    const float* opw  = (const float*)d_in[6];
    const float* opb  = (const float*)d_in[7];
    const float* l1g  = (const float*)d_in[8];
    const float* l1b  = (const float*)d_in[9];
    const float* l2g  = (const float*)d_in[10];
    const float* l2b  = (const float*)d_in[11];
    const float* f1w  = (const float*)d_in[12];
    const float* f1b  = (const float*)d_in[13];
    const float* f2w  = (const float*)d_in[14];
    const float* f2b  = (const float*)d_in[15];
    const float* cw   = (const float*)d_in[16];
    const float* cb   = (const float*)d_in[17];
    float* out = (float*)d_out;
    float* attn_base = out + TB * 2;

    float *x, *y;
    __half *qkv16, *x16, *att16, *h16, *w16;
    cudaGetSymbolAddress((void**)&x,      g_x);
    cudaGetSymbolAddress((void**)&y,      g_y);
    cudaGetSymbolAddress((void**)&qkv16,  g_qkv16);
    cudaGetSymbolAddress((void**)&x16,    g_x16);
    cudaGetSymbolAddress((void**)&att16,  g_att16);
    cudaGetSymbolAddress((void**)&h16,    g_h16);
    cudaGetSymbolAddress((void**)&w16,    g_w16);

    cudaFuncSetAttribute(hgemm_kernel<0, 0>, cudaFuncAttributeMaxDynamicSharedMemorySize, HG_SMEM);
    cudaFuncSetAttribute(hgemm_kernel<0, 1>, cudaFuncAttributeMaxDynamicSharedMemorySize, HG_SMEM);
    cudaFuncSetAttribute(hgemm_kernel<1, 1>, cudaFuncAttributeMaxDynamicSharedMemorySize, HG_SMEM);
    cudaFuncSetAttribute(attn_fused16_kernel, cudaFuncAttributeMaxDynamicSharedMemorySize, AF_SMEM);

    cvtw_kernel<<<W16_TOTAL / 4 / 256, 256>>>(ipw, opw, f1w, f2w, w16);
    embed_kernel<<<(TT * 128) / 256, 256>>>(ids, emb, pos, x, x16);

    for (int l = 0; l < TL; l++) {
        hgemm_kernel<0, 1><<<dim3(QKVW / 128, TT / 128), 128, HG_SMEM>>>(
            x16, w16 + W16_IPW(l), ipb + l * QKVW, nullptr, qkv16, QKVW, TE);

        float* attn_l = attn_base + (size_t)l * TB * TNH * TS * TS;
        attn_fused16_kernel<<<dim3(16, TB * TNH), 256, AF_SMEM>>>(
            qkv16, mask, attn_l, att16);

        hgemm_kernel<0, 0><<<dim3(TE / 128, TT / 128), 128, HG_SMEM>>>(
            att16, w16 + W16_OPW(l), opb + l * TE, y, nullptr, TE, TE);
        add_ln_kernel<<<TT, 128>>>(x, y, l1g + l * TE, l1b + l * TE, x16);

        hgemm_kernel<1, 1><<<dim3(4 * TE / 128, TT / 128), 128, HG_SMEM>>>(
            x16, w16 + W16_F1W(l), f1b + l * 4 * TE, nullptr, h16, 4 * TE, TE);
        hgemm_kernel<0, 0><<<dim3(TE / 128, TT / 128), 128, HG_SMEM>>>(
            h16, w16 + W16_F2W(l), f2b + l * TE, y, nullptr, TE, 4 * TE);
        add_ln_kernel<<<TT, 128>>>(x, y, l2g + l * TE, l2b + l * TE, x16);
    }

    cls_kernel<<<1, 64>>>(x, cw, cb, out);
}

// round 13
// speedup vs baseline: 2.3751x; 1.0067x over previous
#include <cuda_runtime.h>
#include <cuda_fp16.h>
#include <cstdint>
#include <math.h>

// Problem constants
#define TB 32      // batch
#define TS 512     // seq len
#define TE 512     // d_model
#define THD 64     // head dim
#define TNH 8      // heads
#define TL 3       // layers
#define TT (TB*TS) // tokens = 16384
#define QKVW 1536  // 3*E

// Scratch (device globals; allocation-free contract)
__device__ float  g_x[(size_t)TT * TE];        // running hidden fp32   32 MB
__device__ __half g_y16[(size_t)TT * TE];      // gemm out fp16         16 MB
__device__ __half g_qkv16[(size_t)TT * QKVW];  // qkv fp16              48 MB
__device__ __half g_x16[(size_t)TT * TE];      // hidden fp16           16 MB
__device__ __half g_att16[(size_t)TT * TE];    // attn concat fp16      16 MB
__device__ __half g_h16[(size_t)TT * 4 * TE];  // ffn hidden fp16       64 MB
#define W16_TOTAL 9437184
__device__ __half g_w16[W16_TOTAL];            // all weights fp16      18 MB
#define W16_IPW(l) ((size_t)(l) * 786432)
#define W16_OPW(l) (2359296 + (size_t)(l) * 262144)
#define W16_F1W(l) (3145728 + (size_t)(l) * 1048576)
#define W16_F2W(l) (6291456 + (size_t)(l) * 1048576)

#define MMA_F16(d, a, b)                                                      \
    asm volatile(                                                             \
        "mma.sync.aligned.m16n8k16.row.col.f32.f16.f16.f32 "                  \
        "{%0,%1,%2,%3}, {%4,%5,%6,%7}, {%8,%9}, {%0,%1,%2,%3};"               \
        : "+f"(d[0]), "+f"(d[1]), "+f"(d[2]), "+f"(d[3])                      \
        : "r"(a[0]), "r"(a[1]), "r"(a[2]), "r"(a[3]), "r"(b[0]), "r"(b[1]))

#define LDSM4(r0, r1, r2, r3, addr)                                           \
    asm volatile("ldmatrix.sync.aligned.m8n8.x4.shared.b16 {%0,%1,%2,%3}, [%4];" \
        : "=r"(r0), "=r"(r1), "=r"(r2), "=r"(r3) : "r"(addr))

#define LDSM2(r0, r1, addr)                                                   \
    asm volatile("ldmatrix.sync.aligned.m8n8.x2.shared.b16 {%0,%1}, [%2];"    \
        : "=r"(r0), "=r"(r1) : "r"(addr))

#define LDSM4T(r0, r1, r2, r3, addr)                                          \
    asm volatile("ldmatrix.sync.aligned.m8n8.x4.trans.shared.b16 {%0,%1,%2,%3}, [%4];" \
        : "=r"(r0), "=r"(r1), "=r"(r2), "=r"(r3) : "r"(addr))

__device__ __forceinline__ void cpa16(uint32_t s, const void* g) {
    asm volatile("cp.async.cg.shared.global [%0], [%1], 16;" :: "r"(s), "l"(g));
}
__device__ __forceinline__ void cpa_commit() {
    asm volatile("cp.async.commit_group;");
}

// fp16 tile swizzles: chunk = 16B unit
// 64B-pitch rows (32 halfs) for hgemm
__device__ __forceinline__ uint32_t hswz(int row, int chunk) {
    return (uint32_t)(row * 64 + (((chunk + (row >> 1)) & 3) << 4));
}
// 128B-pitch rows (64 halfs) for attention tiles
#define ASWZ(row, c8) ((uint32_t)(((row) << 7) | ((((c8) ^ ((row) & 7))) << 4)))
// 1024B-pitch rows (512 halfs) for the P-probability smem tile
#define PSWZ(row, k8) ((uint32_t)(((row) << 10) | \
    (((((k8) & ~7) | (((k8) & 7) ^ ((row) & 7)))) << 4)))

// ---------------------------------------------------------------------------
// Weight conversion fp32 -> fp16 (once per launch, ~40us)
// ---------------------------------------------------------------------------
__global__ __launch_bounds__(256) void cvtw_kernel(
    const float* __restrict__ ipw, const float* __restrict__ opw,
    const float* __restrict__ f1w, const float* __restrict__ f2w,
    __half* __restrict__ w16) {
    size_t i = ((size_t)blockIdx.x * 256 + threadIdx.x) * 4;
    const float* src; size_t off;
    if (i < 2359296)      { src = ipw; off = i; }
    else if (i < 3145728) { src = opw; off = i - 2359296; }
    else if (i < 6291456) { src = f1w; off = i - 3145728; }
    else                  { src = f2w; off = i - 6291456; }
    float4 v = *reinterpret_cast<const float4*>(src + off);
    __half2* dst = reinterpret_cast<__half2*>(w16 + i);
    dst[0] = __floats2half2_rn(v.x, v.y);
    dst[1] = __floats2half2_rn(v.z, v.w);
}

// ---------------------------------------------------------------------------
// Embedding: x fp32 + fp16 twin
// ---------------------------------------------------------------------------
__global__ __launch_bounds__(256) void embed_kernel(
    const int* __restrict__ ids, const float* __restrict__ emb,
    const float* __restrict__ pos, float* __restrict__ x, __half* __restrict__ x16) {
    int idx = blockIdx.x * blockDim.x + threadIdx.x;
    int token = idx >> 7;
    int c = idx & 127;
    float4 e = reinterpret_cast<const float4*>(emb)[(size_t)ids[token] * 128 + c];
    float4 p = reinterpret_cast<const float4*>(pos)[(size_t)(token & (TS - 1)) * 128 + c];
    float4 o;
    o.x = e.x + p.x; o.y = e.y + p.y; o.z = e.z + p.z; o.w = e.w + p.w;
    reinterpret_cast<float4*>(x)[idx] = o;
    __half2* h = reinterpret_cast<__half2*>(x16) + idx * 2;
    h[0] = __floats2half2_rn(o.x, o.y);
    h[1] = __floats2half2_rn(o.z, o.w);
}

// ---------------------------------------------------------------------------
// FP16 tensor-core GEMM (proven): C16 = A @ W^T + bias, opt GELU, fp16 out.
// Block 128x128, 128 thr, warp tile 64x64, 4-stage ring.
// ---------------------------------------------------------------------------
#define HSTG 16384
#define HG_SMEM (4 * HSTG)

template <int ACT>
__global__ __launch_bounds__(128, 2) void hgemm_kernel(
    const __half* __restrict__ A, const __half* __restrict__ W,
    const float* __restrict__ bias, __half* __restrict__ C16, int N, int K) {
    extern __shared__ char smraw[];
    uint32_t base;
    asm("{ .reg .u64 t; cvta.to.shared.u64 t, %1; cvt.u32.u64 %0, t; }"
        : "=r"(base) : "l"(smraw));

    const int t = threadIdx.x;
    const int lane = t & 31;
    const int warp = t >> 5;
    const int wr = (warp >> 1) * 64;
    const int wc = (warp & 1) * 64;
    const int qr = lane >> 2;
    const int qc = lane & 3;

    const int m0 = blockIdx.y * 128;
    const int n0 = blockIdx.x * 128;
    const int KT = K >> 5;

    const int arow = lane & 15;
    const int achk = lane >> 4;
    const int brow = lane & 7;
    const int bchk = (lane >> 3) & 1;

    float acc[4][8][4];
#pragma unroll
    for (int i = 0; i < 4; i++)
#pragma unroll
        for (int j = 0; j < 8; j++)
#pragma unroll
            for (int r = 0; r < 4; r++) acc[i][j][r] = 0.f;

#pragma unroll
    for (int s = 0; s < 3; s++) {
        uint32_t sb = base + s * HSTG;
#pragma unroll
        for (int i = 0; i < 4; i++) {
            int idx = t + 128 * i;
            int row = idx >> 2, c = idx & 3;
            cpa16(sb + hswz(row, c), A + (size_t)(m0 + row) * K + s * 32 + c * 8);
            cpa16(sb + 8192 + hswz(row, c), W + (size_t)(n0 + row) * K + s * 32 + c * 8);
        }
        cpa_commit();
    }

    for (int kt = 0; kt < KT; kt++) {
        int pend = KT - 1 - kt; if (pend > 2) pend = 2;
        if (pend == 2)      asm volatile("cp.async.wait_group 2;");
        else if (pend == 1) asm volatile("cp.async.wait_group 1;");
        else                asm volatile("cp.async.wait_group 0;");
        __syncthreads();

        if (kt + 3 < KT) {
            int j = kt + 3;
            uint32_t sb = base + (j & 3) * HSTG;
#pragma unroll
            for (int i = 0; i < 4; i++) {
                int idx = t + 128 * i;
                int row = idx >> 2, c = idx & 3;
                cpa16(sb + hswz(row, c), A + (size_t)(m0 + row) * K + j * 32 + c * 8);
                cpa16(sb + 8192 + hswz(row, c), W + (size_t)(n0 + row) * K + j * 32 + c * 8);
            }
            cpa_commit();
        } else {
            cpa_commit();
        }

        const uint32_t sb = base + (kt & 3) * HSTG;
#pragma unroll
        for (int s2 = 0; s2 < 2; s2++) {
            uint32_t a[4][4], bw[8][2];
#pragma unroll
            for (int mi = 0; mi < 4; mi++) {
                uint32_t ad = sb + hswz(wr + mi * 16 + arow, 2 * s2 + achk);
                LDSM4(a[mi][0], a[mi][1], a[mi][2], a[mi][3], ad);
            }
#pragma unroll
            for (int ni = 0; ni < 8; ni++) {
                uint32_t bd = sb + 8192 + hswz(wc + ni * 8 + brow, 2 * s2 + bchk);
                LDSM2(bw[ni][0], bw[ni][1], bd);
            }
#pragma unroll
            for (int mi = 0; mi < 4; mi++)
#pragma unroll
                for (int ni = 0; ni < 8; ni++) MMA_F16(acc[mi][ni], a[mi], bw[ni]);
        }
    }

#pragma unroll
    for (int mi = 0; mi < 4; mi++) {
#pragma unroll
        for (int ni = 0; ni < 8; ni++) {
            int col = n0 + wc + ni * 8 + qc * 2;
            float b0 = bias[col], b1 = bias[col + 1];
#pragma unroll
            for (int half = 0; half < 2; half++) {
                int row = m0 + wr + mi * 16 + qr + half * 8;
                float v0 = acc[mi][ni][half * 2 + 0] + b0;
                float v1 = acc[mi][ni][half * 2 + 1] + b1;
                if (ACT == 1) {
                    v0 = 0.5f * v0 * (1.f + erff(v0 * 0.70710678118654752f));
                    v1 = 0.5f * v1 * (1.f + erff(v1 * 0.70710678118654752f));
                }
                *reinterpret_cast<__half2*>(C16 + (size_t)row * N + col) =
                    __floats2half2_rn(v0, v1);
            }
        }
    }
}

// ---------------------------------------------------------------------------
// Fully fused attention v2 (proven round-12): scores + softmax + AV,
// K/V fully smem-resident. Block: 32 q-rows x 512 keys for one (b,h).
// ---------------------------------------------------------------------------
#define AF_SMEM 101504

__global__ __launch_bounds__(256, 2) void attn_fused16_kernel(
    const __half* __restrict__ qkv16, const int* __restrict__ mask,
    float* __restrict__ attn, __half* __restrict__ att16) {
    extern __shared__ char smraw[];
    uint32_t base;
    asm("{ .reg .u64 t; cvta.to.shared.u64 t, %1; cvt.u32.u64 %0, t; }"
        : "=r"(base) : "l"(smraw));
    const uint32_t pbase = base + 65536;          // Q (phase 1) then P
    float* biasS = reinterpret_cast<float*>(smraw + 98304);
    float* red   = reinterpret_cast<float*>(smraw + 100352);

    const int t = threadIdx.x, lane = t & 31, warp = t >> 5;
    const int qr = lane >> 2, qc = lane & 3;
    const int bh = blockIdx.y, b = bh >> 3, h = bh & 7;
    const int m0 = blockIdx.x * 32;
    const __half* qb = qkv16 + (size_t)b * TS * QKVW + h * THD;
    const __half* kb = qb + TE;
    const __half* vb = qb + 2 * TE;

    for (int i = t; i < 512; i += 256)
        biasS[i] = (mask[b * TS + i] == 0) ? -1e30f : 0.f;

    // prologue: Q + K keys 0..255 -> group A; K keys 256..511 -> group B
    {
        int row = t >> 3, c8 = t & 7;
        cpa16(pbase + ASWZ(row, c8), qb + (size_t)(m0 + row) * QKVW + c8 * 8);
#pragma unroll
        for (int i = 0; i < 8; i++) {
            int u = t + 256 * i;
            int kr = u >> 3, kc = u & 7;
            cpa16(base + ASWZ(kr, kc), kb + (size_t)kr * QKVW + kc * 8);
        }
    }
    cpa_commit();
#pragma unroll
    for (int i = 0; i < 8; i++) {
        int u = t + 256 * i;
        int kr = 256 + (u >> 3), kc = u & 7;
        cpa16(base + ASWZ(kr, kc), kb + (size_t)kr * QKVW + kc * 8);
    }
    cpa_commit();

    float acc[8][2][4];
#pragma unroll
    for (int c = 0; c < 8; c++)
#pragma unroll
        for (int mi = 0; mi < 2; mi++)
#pragma unroll
            for (int r = 0; r < 4; r++) acc[c][mi][r] = 0.f;

    const int arow = lane & 15, achk = lane >> 4;
    const int kchk_off = lane >> 4;
    const int kk_half  = (lane >> 3) & 1;
    const int krow8    = lane & 7;

    // ---- Phase 1: QK^T (s-outer, chunk-inner) ----
    asm volatile("cp.async.wait_group 1;");
    __syncthreads();
#pragma unroll
    for (int hf = 0; hf < 2; hf++) {
        if (hf == 1) {
            asm volatile("cp.async.wait_group 0;");
            __syncthreads();
        }
#pragma unroll
        for (int s = 0; s < 4; s++) {
            uint32_t qf[2][4];
#pragma unroll
            for (int mi = 0; mi < 2; mi++)
                LDSM4(qf[mi][0], qf[mi][1], qf[mi][2], qf[mi][3],
                      pbase + ASWZ(mi * 16 + arow, 2 * s + achk));
#pragma unroll
            for (int cc = 0; cc < 2; cc++) {
                const int c = hf * 4 + cc * 2;
                uint32_t k4[4];
                LDSM4(k4[0], k4[1], k4[2], k4[3],
                      base + ASWZ((c + kchk_off) * 64 + warp * 8 + krow8,
                                  2 * s + kk_half));
#pragma unroll
                for (int mi = 0; mi < 2; mi++) {
                    MMA_F16(acc[c][mi], qf[mi], (k4 + 0));
                    MMA_F16(acc[c + 1][mi], qf[mi], (k4 + 2));
                }
            }
        }
    }
    __syncthreads();   // all K reads done; V may overwrite

    // Issue V loads (overlap with softmax)
#pragma unroll
    for (int i = 0; i < 8; i++) {
        int u = t + 256 * i;
        int vr = u >> 3, vc = u & 7;
        cpa16(base + ASWZ(vr, vc), vb + (size_t)vr * QKVW + vc * 8);
    }
    cpa_commit();
#pragma unroll
    for (int i = 0; i < 8; i++) {
        int u = t + 256 * i;
        int vr = 256 + (u >> 3), vc = u & 7;
        cpa16(base + ASWZ(vr, vc), vb + (size_t)vr * QKVW + vc * 8);
    }
    cpa_commit();

    // ---- softmax over 512 keys per row (32 rows) ----
    float bm[2][2], bs[2][2];
    const float scale = 0.125f;
#pragma unroll
    for (int mi = 0; mi < 2; mi++) {
#pragma unroll
        for (int h2 = 0; h2 < 2; h2++) {
            float m = -3.4e38f;
#pragma unroll
            for (int c = 0; c < 8; c++) {
                int col = c * 64 + warp * 8 + qc * 2;
                float v0 = acc[c][mi][2 * h2 + 0] * scale + biasS[col];
                float v1 = acc[c][mi][2 * h2 + 1] * scale + biasS[col + 1];
                acc[c][mi][2 * h2 + 0] = v0;
                acc[c][mi][2 * h2 + 1] = v1;
                m = fmaxf(m, fmaxf(v0, v1));
            }
            m = fmaxf(m, __shfl_xor_sync(0xFFFFFFFFu, m, 1));
            m = fmaxf(m, __shfl_xor_sync(0xFFFFFFFFu, m, 2));
            bm[mi][h2] = m;
        }
    }
    if (qc == 0) {
#pragma unroll
        for (int mi = 0; mi < 2; mi++)
#pragma unroll
            for (int h2 = 0; h2 < 2; h2++)
                red[(mi * 16 + qr + h2 * 8) * 9 + warp] = bm[mi][h2];
    }
    __syncthreads();
#pragma unroll
    for (int mi = 0; mi < 2; mi++)
#pragma unroll
        for (int h2 = 0; h2 < 2; h2++) {
            int row = mi * 16 + qr + h2 * 8;
            float m = red[row * 9 + 0];
#pragma unroll
            for (int w2 = 1; w2 < 8; w2++) m = fmaxf(m, red[row * 9 + w2]);
            bm[mi][h2] = m;
        }
    __syncthreads();
#pragma unroll
    for (int mi = 0; mi < 2; mi++) {
#pragma unroll
        for (int h2 = 0; h2 < 2; h2++) {
            float m = bm[mi][h2];
            float s = 0.f;
#pragma unroll
            for (int c = 0; c < 8; c++) {
                float e0 = __expf(acc[c][mi][2 * h2 + 0] - m);
                float e1 = __expf(acc[c][mi][2 * h2 + 1] - m);
                acc[c][mi][2 * h2 + 0] = e0;
                acc[c][mi][2 * h2 + 1] = e1;
                s += e0 + e1;
            }
            s += __shfl_xor_sync(0xFFFFFFFFu, s, 1);
            s += __shfl_xor_sync(0xFFFFFFFFu, s, 2);
            bs[mi][h2] = s;
        }
    }
    if (qc == 0) {
#pragma unroll
        for (int mi = 0; mi < 2; mi++)
#pragma unroll
            for (int h2 = 0; h2 < 2; h2++)
                red[(mi * 16 + qr + h2 * 8) * 9 + warp] = bs[mi][h2];
    }
    __syncthreads();
    // normalize; write fp32 probs (streaming) + fp16 P into SMEM
#pragma unroll
    for (int mi = 0; mi < 2; mi++)
#pragma unroll
        for (int h2 = 0; h2 < 2; h2++) {
            int row = mi * 16 + qr + h2 * 8;
            float s = 0.f;
#pragma unroll
            for (int w2 = 0; w2 < 8; w2++) s += red[row * 9 + w2];
            float inv = 1.f / s;
            float* orow = attn + ((size_t)bh * TS + m0 + row) * TS;
#pragma unroll
            for (int c = 0; c < 8; c++) {
                int col = c * 64 + warp * 8 + qc * 2;
                float2 o;
                o.x = acc[c][mi][2 * h2 + 0] * inv;
                o.y = acc[c][mi][2 * h2 + 1] * inv;
                __stcs(reinterpret_cast<float2*>(orow + col), o);
                __half2 hv = __floats2half2_rn(o.x, o.y);
                uint32_t u = *reinterpret_cast<uint32_t*>(&hv);
                asm volatile("st.shared.b32 [%0], %1;"
                             :: "r"(pbase + PSWZ(row, c * 8 + warp) + qc * 4), "r"(u)
                             : "memory");
            }
        }

    // ---- Phase 2: O = P @ V; warp w owns head dims [w*8, w*8+8) ----
    float oacc[2][4];
#pragma unroll
    for (int mi = 0; mi < 2; mi++)
#pragma unroll
        for (int r = 0; r < 4; r++) oacc[mi][r] = 0.f;

    asm volatile("cp.async.wait_group 1;");
    __syncthreads();   // V keys 0..255 + all P stores visible
#pragma unroll
    for (int hf = 0; hf < 2; hf++) {
        if (hf == 1) {
            asm volatile("cp.async.wait_group 0;");
            __syncthreads();
        }
#pragma unroll
        for (int ks2 = 0; ks2 < 8; ks2++) {
            const int ks = hf * 16 + ks2 * 2;
            uint32_t bw4[4];
            LDSM4T(bw4[0], bw4[1], bw4[2], bw4[3],
                   base + ASWZ(ks * 16 + lane, warp));
#pragma unroll
            for (int k2 = 0; k2 < 2; k2++) {
                uint32_t af[2][4];
#pragma unroll
                for (int mi = 0; mi < 2; mi++)
                    LDSM4(af[mi][0], af[mi][1], af[mi][2], af[mi][3],
                          pbase + PSWZ(mi * 16 + arow, (ks + k2) * 2 + achk));
#pragma unroll
                for (int mi = 0; mi < 2; mi++)
                    MMA_F16(oacc[mi], af[mi], (bw4 + 2 * k2));
            }
        }
    }

    // epilogue: write att16 (concat layout)
#pragma unroll
    for (int mi = 0; mi < 2; mi++) {
#pragma unroll
        for (int h2 = 0; h2 < 2; h2++) {
            int row = m0 + mi * 16 + qr + h2 * 8;
            int col = h * THD + warp * 8 + qc * 2;
            *reinterpret_cast<__half2*>(att16 + ((size_t)b * TS + row) * TE + col) =
                __floats2half2_rn(oacc[mi][2 * h2 + 0], oacc[mi][2 * h2 + 1]);
        }
    }
}

// ---------------------------------------------------------------------------
// Fused residual + LayerNorm; y input fp16, writes fp32 x and fp16 twin.
// ---------------------------------------------------------------------------
__global__ __launch_bounds__(128) void add_ln_kernel(
    float* __restrict__ x, const __half* __restrict__ y16,
    const float* __restrict__ g, const float* __restrict__ bb,
    __half* __restrict__ x16) {
    const size_t row = blockIdx.x;
    const int t = threadIdx.x;
    float4 xv = reinterpret_cast<float4*>(x + row * TE)[t];
    const __half2* yp = reinterpret_cast<const __half2*>(y16 + row * TE) + t * 2;
    float2 y0 = __half22float2(yp[0]);
    float2 y1 = __half22float2(yp[1]);
    float4 s;
    s.x = xv.x + y0.x; s.y = xv.y + y0.y; s.z = xv.z + y1.x; s.w = xv.w + y1.y;
    float sum = s.x + s.y + s.z + s.w;
    float sq = s.x * s.x + s.y * s.y + s.z * s.z + s.w * s.w;
#pragma unroll
    for (int o = 16; o; o >>= 1) {
        sum += __shfl_xor_sync(0xFFFFFFFFu, sum, o);
        sq  += __shfl_xor_sync(0xFFFFFFFFu, sq, o);
    }
    __shared__ float s1[4], s2[4];
    if ((t & 31) == 0) { s1[t >> 5] = sum; s2[t >> 5] = sq; }
    __syncthreads();
    sum = s1[0] + s1[1] + s1[2] + s1[3];
    sq  = s2[0] + s2[1] + s2[2] + s2[3];
    const float mean = sum * (1.f / TE);
    const float var = sq * (1.f / TE) - mean * mean;
    const float rstd = rsqrtf(var + 1e-5f);
    float4 gv = reinterpret_cast<const float4*>(g)[t];
    float4 bv = reinterpret_cast<const float4*>(bb)[t];
    float4 o;
    o.x = (s.x - mean) * rstd * gv.x + bv.x;
    o.y = (s.y - mean) * rstd * gv.y + bv.y;
    o.z = (s.z - mean) * rstd * gv.z + bv.z;
    o.w = (s.w - mean) * rstd * gv.w + bv.w;
    reinterpret_cast<float4*>(x + row * TE)[t] = o;
    __half2* hx = reinterpret_cast<__half2*>(x16 + row * TE) + t * 2;
    hx[0] = __floats2half2_rn(o.x, o.y);
    hx[1] = __floats2half2_rn(o.z, o.w);
}

// ---------------------------------------------------------------------------
// CLS head
// ---------------------------------------------------------------------------
__global__ void cls_kernel(const float* __restrict__ x, const float* __restrict__ w,
                           const float* __restrict__ cb, float* __restrict__ out) {
    int t = threadIdx.x;
    if (t >= TB * 2) return;
    int b = t >> 1, c = t & 1;
    const float* xr = x + (size_t)b * TS * TE;
    const float* wr = w + c * TE;
    float s = cb[c];
    for (int e = 0; e < TE; e++) s = fmaf(xr[e], wr[e], s);
    out[b * 2 + c] = s;
}

// ---------------------------------------------------------------------------
extern "C" void kernel_launch(void* const* d_in, const int* in_sizes, int n_in,
                              void* d_out, int out_size) {
    const int*   ids  = (const int*)d_in[0];
    const int*   mask = (const int*)d_in[1];
    const float* emb  = (const float*)d_in[2];
    const float* pos  = (const float*)d_in[3];
    const float* ipw  = (const float*)d_in[4];
    const float* ipb  = (const float*)d_in[5];
    const float* opw  = (const float*)d_in[6];
    const float* opb  = (const float*)d_in[7];
    const float* l1g  = (const float*)d_in[8];
    const float* l1b  = (const float*)d_in[9];
    const float* l2g  = (const float*)d_in[10];
    const float* l2b  = (const float*)d_in[11];
    const float* f1w  = (const float*)d_in[12];
    const float* f1b  = (const float*)d_in[13];
    const float* f2w  = (const float*)d_in[14];
    const float* f2b  = (const float*)d_in[15];
    const float* cw   = (const float*)d_in[16];
    const float* cb   = (const float*)d_in[17];
    float* out = (float*)d_out;
    float* attn_base = out + TB * 2;

    float *x;
    __half *y16, *qkv16, *x16, *att16, *h16, *w16;
    cudaGetSymbolAddress((void**)&x,      g_x);
    cudaGetSymbolAddress((void**)&y16,    g_y16);
    cudaGetSymbolAddress((void**)&qkv16,  g_qkv16);
    cudaGetSymbolAddress((void**)&x16,    g_x16);
    cudaGetSymbolAddress((void**)&att16,  g_att16);
    cudaGetSymbolAddress((void**)&h16,    g_h16);
    cudaGetSymbolAddress((void**)&w16,    g_w16);

    cudaFuncSetAttribute(hgemm_kernel<0>, cudaFuncAttributeMaxDynamicSharedMemorySize, HG_SMEM);
    cudaFuncSetAttribute(hgemm_kernel<1>, cudaFuncAttributeMaxDynamicSharedMemorySize, HG_SMEM);
    cudaFuncSetAttribute(attn_fused16_kernel, cudaFuncAttributeMaxDynamicSharedMemorySize, AF_SMEM);

    cvtw_kernel<<<W16_TOTAL / 4 / 256, 256>>>(ipw, opw, f1w, f2w, w16);
    embed_kernel<<<(TT * 128) / 256, 256>>>(ids, emb, pos, x, x16);

    for (int l = 0; l < TL; l++) {
        hgemm_kernel<0><<<dim3(QKVW / 128, TT / 128), 128, HG_SMEM>>>(
            x16, w16 + W16_IPW(l), ipb + l * QKVW, qkv16, QKVW, TE);

        float* attn_l = attn_base + (size_t)l * TB * TNH * TS * TS;
        attn_fused16_kernel<<<dim3(16, TB * TNH), 256, AF_SMEM>>>(
            qkv16, mask, attn_l, att16);

        hgemm_kernel<0><<<dim3(TE / 128, TT / 128), 128, HG_SMEM>>>(
            att16, w16 + W16_OPW(l), opb + l * TE, y16, TE, TE);
        add_ln_kernel<<<TT, 128>>>(x, y16, l1g + l * TE, l1b + l * TE, x16);

        hgemm_kernel<1><<<dim3(4 * TE / 128, TT / 128), 128, HG_SMEM>>>(
            x16, w16 + W16_F1W(l), f1b + l * 4 * TE, h16, 4 * TE, TE);
        hgemm_kernel<0><<<dim3(TE / 128, TT / 128), 128, HG_SMEM>>>(
            h16, w16 + W16_F2W(l), f2b + l * TE, y16, TE, 4 * TE);
        add_ln_kernel<<<TT, 128>>>(x, y16, l2g + l * TE, l2b + l * TE, x16);
    }

    cls_kernel<<<1, 64>>>(x, cw, cb, out);
}

// round 14
// speedup vs baseline: 2.4050x; 1.0126x over previous
#include <cuda_runtime.h>
#include <cuda_fp16.h>
#include <cstdint>
#include <math.h>

// Problem constants
#define TB 32      // batch
#define TS 512     // seq len
#define TE 512     // d_model
#define THD 64     // head dim
#define TNH 8      // heads
#define TL 3       // layers
#define TT (TB*TS) // tokens = 16384
#define QKVW 1536  // 3*E

// Scratch (device globals; allocation-free contract)
__device__ __half g_y16[(size_t)TT * TE];      // gemm out fp16         16 MB
__device__ __half g_qkv16[(size_t)TT * QKVW];  // qkv fp16              48 MB
__device__ __half g_x16[(size_t)TT * TE];      // hidden fp16 residual  16 MB
__device__ __half g_att16[(size_t)TT * TE];    // attn concat fp16      16 MB
__device__ __half g_h16[(size_t)TT * 4 * TE];  // ffn hidden fp16       64 MB
#define W16_TOTAL 9437184
__device__ __half g_w16[W16_TOTAL];            // all weights fp16      18 MB
#define W16_IPW(l) ((size_t)(l) * 786432)
#define W16_OPW(l) (2359296 + (size_t)(l) * 262144)
#define W16_F1W(l) (3145728 + (size_t)(l) * 1048576)
#define W16_F2W(l) (6291456 + (size_t)(l) * 1048576)

#define MMA_F16(d, a, b)                                                      \
    asm volatile(                                                             \
        "mma.sync.aligned.m16n8k16.row.col.f32.f16.f16.f32 "                  \
        "{%0,%1,%2,%3}, {%4,%5,%6,%7}, {%8,%9}, {%0,%1,%2,%3};"               \
        : "+f"(d[0]), "+f"(d[1]), "+f"(d[2]), "+f"(d[3])                      \
        : "r"(a[0]), "r"(a[1]), "r"(a[2]), "r"(a[3]), "r"(b[0]), "r"(b[1]))

#define LDSM4(r0, r1, r2, r3, addr)                                           \
    asm volatile("ldmatrix.sync.aligned.m8n8.x4.shared.b16 {%0,%1,%2,%3}, [%4];" \
        : "=r"(r0), "=r"(r1), "=r"(r2), "=r"(r3) : "r"(addr))

#define LDSM2(r0, r1, addr)                                                   \
    asm volatile("ldmatrix.sync.aligned.m8n8.x2.shared.b16 {%0,%1}, [%2];"    \
        : "=r"(r0), "=r"(r1) : "r"(addr))

#define LDSM4T(r0, r1, r2, r3, addr)                                          \
    asm volatile("ldmatrix.sync.aligned.m8n8.x4.trans.shared.b16 {%0,%1,%2,%3}, [%4];" \
        : "=r"(r0), "=r"(r1), "=r"(r2), "=r"(r3) : "r"(addr))

__device__ __forceinline__ void cpa16(uint32_t s, const void* g) {
    asm volatile("cp.async.cg.shared.global [%0], [%1], 16;" :: "r"(s), "l"(g));
}
__device__ __forceinline__ void cpa_commit() {
    asm volatile("cp.async.commit_group;");
}

// fp16 tile swizzles: chunk = 16B unit
// 64B-pitch rows (32 halfs) for hgemm
__device__ __forceinline__ uint32_t hswz(int row, int chunk) {
    return (uint32_t)(row * 64 + (((chunk + (row >> 1)) & 3) << 4));
}
// 128B-pitch rows (64 halfs) for attention tiles
#define ASWZ(row, c8) ((uint32_t)(((row) << 7) | ((((c8) ^ ((row) & 7))) << 4)))
// 1024B-pitch rows (512 halfs) for the P-probability smem tile
#define PSWZ(row, k8) ((uint32_t)(((row) << 10) | \
    (((((k8) & ~7) | (((k8) & 7) ^ ((row) & 7)))) << 4)))

// ---------------------------------------------------------------------------
// Weight conversion fp32 -> fp16 (once per launch, ~40us)
// ---------------------------------------------------------------------------
__global__ __launch_bounds__(256) void cvtw_kernel(
    const float* __restrict__ ipw, const float* __restrict__ opw,
    const float* __restrict__ f1w, const float* __restrict__ f2w,
    __half* __restrict__ w16) {
    size_t i = ((size_t)blockIdx.x * 256 + threadIdx.x) * 4;
    const float* src; size_t off;
    if (i < 2359296)      { src = ipw; off = i; }
    else if (i < 3145728) { src = opw; off = i - 2359296; }
    else if (i < 6291456) { src = f1w; off = i - 3145728; }
    else                  { src = f2w; off = i - 6291456; }
    float4 v = *reinterpret_cast<const float4*>(src + off);
    __half2* dst = reinterpret_cast<__half2*>(w16 + i);
    dst[0] = __floats2half2_rn(v.x, v.y);
    dst[1] = __floats2half2_rn(v.z, v.w);
}

// ---------------------------------------------------------------------------
// Embedding: x16 = fp16(emb[ids] + pos)
// ---------------------------------------------------------------------------
__global__ __launch_bounds__(256) void embed_kernel(
    const int* __restrict__ ids, const float* __restrict__ emb,
    const float* __restrict__ pos, __half* __restrict__ x16) {
    int idx = blockIdx.x * blockDim.x + threadIdx.x;
    int token = idx >> 7;
    int c = idx & 127;
    float4 e = reinterpret_cast<const float4*>(emb)[(size_t)ids[token] * 128 + c];
    float4 p = reinterpret_cast<const float4*>(pos)[(size_t)(token & (TS - 1)) * 128 + c];
    __half2* h = reinterpret_cast<__half2*>(x16) + idx * 2;
    h[0] = __floats2half2_rn(e.x + p.x, e.y + p.y);
    h[1] = __floats2half2_rn(e.z + p.z, e.w + p.w);
}

// ---------------------------------------------------------------------------
// FP16 tensor-core GEMM (proven): C16 = A @ W^T + bias, opt GELU, fp16 out.
// Block 128x128, 128 thr, warp tile 64x64, 4-stage ring.
// ---------------------------------------------------------------------------
#define HSTG 16384
#define HG_SMEM (4 * HSTG)

template <int ACT>
__global__ __launch_bounds__(128, 2) void hgemm_kernel(
    const __half* __restrict__ A, const __half* __restrict__ W,
    const float* __restrict__ bias, __half* __restrict__ C16, int N, int K) {
    extern __shared__ char smraw[];
    uint32_t base;
    asm("{ .reg .u64 t; cvta.to.shared.u64 t, %1; cvt.u32.u64 %0, t; }"
        : "=r"(base) : "l"(smraw));

    const int t = threadIdx.x;
    const int lane = t & 31;
    const int warp = t >> 5;
    const int wr = (warp >> 1) * 64;
    const int wc = (warp & 1) * 64;
    const int qr = lane >> 2;
    const int qc = lane & 3;

    const int m0 = blockIdx.y * 128;
    const int n0 = blockIdx.x * 128;
    const int KT = K >> 5;

    const int arow = lane & 15;
    const int achk = lane >> 4;
    const int brow = lane & 7;
    const int bchk = (lane >> 3) & 1;

    float acc[4][8][4];
#pragma unroll
    for (int i = 0; i < 4; i++)
#pragma unroll
        for (int j = 0; j < 8; j++)
#pragma unroll
            for (int r = 0; r < 4; r++) acc[i][j][r] = 0.f;

#pragma unroll
    for (int s = 0; s < 3; s++) {
        uint32_t sb = base + s * HSTG;
#pragma unroll
        for (int i = 0; i < 4; i++) {
            int idx = t + 128 * i;
            int row = idx >> 2, c = idx & 3;
            cpa16(sb + hswz(row, c), A + (size_t)(m0 + row) * K + s * 32 + c * 8);
            cpa16(sb + 8192 + hswz(row, c), W + (size_t)(n0 + row) * K + s * 32 + c * 8);
        }
        cpa_commit();
    }

    for (int kt = 0; kt < KT; kt++) {
        int pend = KT - 1 - kt; if (pend > 2) pend = 2;
        if (pend == 2)      asm volatile("cp.async.wait_group 2;");
        else if (pend == 1) asm volatile("cp.async.wait_group 1;");
        else                asm volatile("cp.async.wait_group 0;");
        __syncthreads();

        if (kt + 3 < KT) {
            int j = kt + 3;
            uint32_t sb = base + (j & 3) * HSTG;
#pragma unroll
            for (int i = 0; i < 4; i++) {
                int idx = t + 128 * i;
                int row = idx >> 2, c = idx & 3;
                cpa16(sb + hswz(row, c), A + (size_t)(m0 + row) * K + j * 32 + c * 8);
                cpa16(sb + 8192 + hswz(row, c), W + (size_t)(n0 + row) * K + j * 32 + c * 8);
            }
            cpa_commit();
        } else {
            cpa_commit();
        }

        const uint32_t sb = base + (kt & 3) * HSTG;
#pragma unroll
        for (int s2 = 0; s2 < 2; s2++) {
            uint32_t a[4][4], bw[8][2];
#pragma unroll
            for (int mi = 0; mi < 4; mi++) {
                uint32_t ad = sb + hswz(wr + mi * 16 + arow, 2 * s2 + achk);
                LDSM4(a[mi][0], a[mi][1], a[mi][2], a[mi][3], ad);
            }
#pragma unroll
            for (int ni = 0; ni < 8; ni++) {
                uint32_t bd = sb + 8192 + hswz(wc + ni * 8 + brow, 2 * s2 + bchk);
                LDSM2(bw[ni][0], bw[ni][1], bd);
            }
#pragma unroll
            for (int mi = 0; mi < 4; mi++)
#pragma unroll
                for (int ni = 0; ni < 8; ni++) MMA_F16(acc[mi][ni], a[mi], bw[ni]);
        }
    }

#pragma unroll
    for (int mi = 0; mi < 4; mi++) {
#pragma unroll
        for (int ni = 0; ni < 8; ni++) {
            int col = n0 + wc + ni * 8 + qc * 2;
            float b0 = bias[col], b1 = bias[col + 1];
#pragma unroll
            for (int half = 0; half < 2; half++) {
                int row = m0 + wr + mi * 16 + qr + half * 8;
                float v0 = acc[mi][ni][half * 2 + 0] + b0;
                float v1 = acc[mi][ni][half * 2 + 1] + b1;
                if (ACT == 1) {
                    v0 = 0.5f * v0 * (1.f + erff(v0 * 0.70710678118654752f));
                    v1 = 0.5f * v1 * (1.f + erff(v1 * 0.70710678118654752f));
                }
                *reinterpret_cast<__half2*>(C16 + (size_t)row * N + col) =
                    __floats2half2_rn(v0, v1);
            }
        }
    }
}

// ---------------------------------------------------------------------------
// Fully fused attention v2 (proven round-12): scores + softmax + AV,
// K/V fully smem-resident. Block: 32 q-rows x 512 keys for one (b,h).
// ---------------------------------------------------------------------------
#define AF_SMEM 101504

__global__ __launch_bounds__(256, 2) void attn_fused16_kernel(
    const __half* __restrict__ qkv16, const int* __restrict__ mask,
    float* __restrict__ attn, __half* __restrict__ att16) {
    extern __shared__ char smraw[];
    uint32_t base;
    asm("{ .reg .u64 t; cvta.to.shared.u64 t, %1; cvt.u32.u64 %0, t; }"
        : "=r"(base) : "l"(smraw));
    const uint32_t pbase = base + 65536;          // Q (phase 1) then P
    float* biasS = reinterpret_cast<float*>(smraw + 98304);
    float* red   = reinterpret_cast<float*>(smraw + 100352);

    const int t = threadIdx.x, lane = t & 31, warp = t >> 5;
    const int qr = lane >> 2, qc = lane & 3;
    const int bh = blockIdx.y, b = bh >> 3, h = bh & 7;
    const int m0 = blockIdx.x * 32;
    const __half* qb = qkv16 + (size_t)b * TS * QKVW + h * THD;
    const __half* kb = qb + TE;
    const __half* vb = qb + 2 * TE;

    for (int i = t; i < 512; i += 256)
        biasS[i] = (mask[b * TS + i] == 0) ? -1e30f : 0.f;

    // prologue: Q + K keys 0..255 -> group A; K keys 256..511 -> group B
    {
        int row = t >> 3, c8 = t & 7;
        cpa16(pbase + ASWZ(row, c8), qb + (size_t)(m0 + row) * QKVW + c8 * 8);
#pragma unroll
        for (int i = 0; i < 8; i++) {
            int u = t + 256 * i;
            int kr = u >> 3, kc = u & 7;
            cpa16(base + ASWZ(kr, kc), kb + (size_t)kr * QKVW + kc * 8);
        }
    }
    cpa_commit();
#pragma unroll
    for (int i = 0; i < 8; i++) {
        int u = t + 256 * i;
        int kr = 256 + (u >> 3), kc = u & 7;
        cpa16(base + ASWZ(kr, kc), kb + (size_t)kr * QKVW + kc * 8);
    }
    cpa_commit();

    float acc[8][2][4];
#pragma unroll
    for (int c = 0; c < 8; c++)
#pragma unroll
        for (int mi = 0; mi < 2; mi++)
#pragma unroll
            for (int r = 0; r < 4; r++) acc[c][mi][r] = 0.f;

    const int arow = lane & 15, achk = lane >> 4;
    const int kchk_off = lane >> 4;
    const int kk_half  = (lane >> 3) & 1;
    const int krow8    = lane & 7;

    // ---- Phase 1: QK^T (s-outer, chunk-inner) ----
    asm volatile("cp.async.wait_group 1;");
    __syncthreads();
#pragma unroll
    for (int hf = 0; hf < 2; hf++) {
        if (hf == 1) {
            asm volatile("cp.async.wait_group 0;");
            __syncthreads();
        }
#pragma unroll
        for (int s = 0; s < 4; s++) {
            uint32_t qf[2][4];
#pragma unroll
            for (int mi = 0; mi < 2; mi++)
                LDSM4(qf[mi][0], qf[mi][1], qf[mi][2], qf[mi][3],
                      pbase + ASWZ(mi * 16 + arow, 2 * s + achk));
#pragma unroll
            for (int cc = 0; cc < 2; cc++) {
                const int c = hf * 4 + cc * 2;
                uint32_t k4[4];
                LDSM4(k4[0], k4[1], k4[2], k4[3],
                      base + ASWZ((c + kchk_off) * 64 + warp * 8 + krow8,
                                  2 * s + kk_half));
#pragma unroll
                for (int mi = 0; mi < 2; mi++) {
                    MMA_F16(acc[c][mi], qf[mi], (k4 + 0));
                    MMA_F16(acc[c + 1][mi], qf[mi], (k4 + 2));
                }
            }
        }
    }
    __syncthreads();   // all K reads done; V may overwrite

    // Issue V loads (overlap with softmax)
#pragma unroll
    for (int i = 0; i < 8; i++) {
        int u = t + 256 * i;
        int vr = u >> 3, vc = u & 7;
        cpa16(base + ASWZ(vr, vc), vb + (size_t)vr * QKVW + vc * 8);
    }
    cpa_commit();
#pragma unroll
    for (int i = 0; i < 8; i++) {
        int u = t + 256 * i;
        int vr = 256 + (u >> 3), vc = u & 7;
        cpa16(base + ASWZ(vr, vc), vb + (size_t)vr * QKVW + vc * 8);
    }
    cpa_commit();

    // ---- softmax over 512 keys per row (32 rows) ----
    float bm[2][2], bs[2][2];
    const float scale = 0.125f;
#pragma unroll
    for (int mi = 0; mi < 2; mi++) {
#pragma unroll
        for (int h2 = 0; h2 < 2; h2++) {
            float m = -3.4e38f;
#pragma unroll
            for (int c = 0; c < 8; c++) {
                int col = c * 64 + warp * 8 + qc * 2;
                float v0 = acc[c][mi][2 * h2 + 0] * scale + biasS[col];
                float v1 = acc[c][mi][2 * h2 + 1] * scale + biasS[col + 1];
                acc[c][mi][2 * h2 + 0] = v0;
                acc[c][mi][2 * h2 + 1] = v1;
                m = fmaxf(m, fmaxf(v0, v1));
            }
            m = fmaxf(m, __shfl_xor_sync(0xFFFFFFFFu, m, 1));
            m = fmaxf(m, __shfl_xor_sync(0xFFFFFFFFu, m, 2));
            bm[mi][h2] = m;
        }
    }
    if (qc == 0) {
#pragma unroll
        for (int mi = 0; mi < 2; mi++)
#pragma unroll
            for (int h2 = 0; h2 < 2; h2++)
                red[(mi * 16 + qr + h2 * 8) * 9 + warp] = bm[mi][h2];
    }
    __syncthreads();
#pragma unroll
    for (int mi = 0; mi < 2; mi++)
#pragma unroll
        for (int h2 = 0; h2 < 2; h2++) {
            int row = mi * 16 + qr + h2 * 8;
            float m = red[row * 9 + 0];
#pragma unroll
            for (int w2 = 1; w2 < 8; w2++) m = fmaxf(m, red[row * 9 + w2]);
            bm[mi][h2] = m;
        }
    __syncthreads();
#pragma unroll
    for (int mi = 0; mi < 2; mi++) {
#pragma unroll
        for (int h2 = 0; h2 < 2; h2++) {
            float m = bm[mi][h2];
            float s = 0.f;
#pragma unroll
            for (int c = 0; c < 8; c++) {
                float e0 = __expf(acc[c][mi][2 * h2 + 0] - m);
                float e1 = __expf(acc[c][mi][2 * h2 + 1] - m);
                acc[c][mi][2 * h2 + 0] = e0;
                acc[c][mi][2 * h2 + 1] = e1;
                s += e0 + e1;
            }
            s += __shfl_xor_sync(0xFFFFFFFFu, s, 1);
            s += __shfl_xor_sync(0xFFFFFFFFu, s, 2);
            bs[mi][h2] = s;
        }
    }
    if (qc == 0) {
#pragma unroll
        for (int mi = 0; mi < 2; mi++)
#pragma unroll
            for (int h2 = 0; h2 < 2; h2++)
                red[(mi * 16 + qr + h2 * 8) * 9 + warp] = bs[mi][h2];
    }
    __syncthreads();
    // normalize; write fp32 probs (streaming) + fp16 P into SMEM
#pragma unroll
    for (int mi = 0; mi < 2; mi++)
#pragma unroll
        for (int h2 = 0; h2 < 2; h2++) {
            int row = mi * 16 + qr + h2 * 8;
            float s = 0.f;
#pragma unroll
            for (int w2 = 0; w2 < 8; w2++) s += red[row * 9 + w2];
            float inv = 1.f / s;
            float* orow = attn + ((size_t)bh * TS + m0 + row) * TS;
#pragma unroll
            for (int c = 0; c < 8; c++) {
                int col = c * 64 + warp * 8 + qc * 2;
                float2 o;
                o.x = acc[c][mi][2 * h2 + 0] * inv;
                o.y = acc[c][mi][2 * h2 + 1] * inv;
                __stcs(reinterpret_cast<float2*>(orow + col), o);
                __half2 hv = __floats2half2_rn(o.x, o.y);
                uint32_t u = *reinterpret_cast<uint32_t*>(&hv);
                asm volatile("st.shared.b32 [%0], %1;"
                             :: "r"(pbase + PSWZ(row, c * 8 + warp) + qc * 4), "r"(u)
                             : "memory");
            }
        }

    // ---- Phase 2: O = P @ V; warp w owns head dims [w*8, w*8+8) ----
    float oacc[2][4];
#pragma unroll
    for (int mi = 0; mi < 2; mi++)
#pragma unroll
        for (int r = 0; r < 4; r++) oacc[mi][r] = 0.f;

    asm volatile("cp.async.wait_group 1;");
    __syncthreads();   // V keys 0..255 + all P stores visible
#pragma unroll
    for (int hf = 0; hf < 2; hf++) {
        if (hf == 1) {
            asm volatile("cp.async.wait_group 0;");
            __syncthreads();
        }
#pragma unroll
        for (int ks2 = 0; ks2 < 8; ks2++) {
            const int ks = hf * 16 + ks2 * 2;
            uint32_t bw4[4];
            LDSM4T(bw4[0], bw4[1], bw4[2], bw4[3],
                   base + ASWZ(ks * 16 + lane, warp));
#pragma unroll
            for (int k2 = 0; k2 < 2; k2++) {
                uint32_t af[2][4];
#pragma unroll
                for (int mi = 0; mi < 2; mi++)
                    LDSM4(af[mi][0], af[mi][1], af[mi][2], af[mi][3],
                          pbase + PSWZ(mi * 16 + arow, (ks + k2) * 2 + achk));
#pragma unroll
                for (int mi = 0; mi < 2; mi++)
                    MMA_F16(oacc[mi], af[mi], (bw4 + 2 * k2));
            }
        }
    }

    // epilogue: write att16 (concat layout)
#pragma unroll
    for (int mi = 0; mi < 2; mi++) {
#pragma unroll
        for (int h2 = 0; h2 < 2; h2++) {
            int row = m0 + mi * 16 + qr + h2 * 8;
            int col = h * THD + warp * 8 + qc * 2;
            *reinterpret_cast<__half2*>(att16 + ((size_t)b * TS + row) * TE + col) =
                __floats2half2_rn(oacc[mi][2 * h2 + 0], oacc[mi][2 * h2 + 1]);
        }
    }
}

// ---------------------------------------------------------------------------
// Fused residual + LayerNorm, fp16 residual stream:
// x16 = fp16(LN(x16 + y16) * g + b). 1 block/token, 128 thr.
// Sums computed in fp32.
// ---------------------------------------------------------------------------
__global__ __launch_bounds__(128) void add_ln_kernel(
    __half* __restrict__ x16, const __half* __restrict__ y16,
    const float* __restrict__ g, const float* __restrict__ bb) {
    const size_t row = blockIdx.x;
    const int t = threadIdx.x;
    const __half2* xp = reinterpret_cast<const __half2*>(x16 + row * TE) + t * 2;
    const __half2* yp = reinterpret_cast<const __half2*>(y16 + row * TE) + t * 2;
    float2 x0 = __half22float2(xp[0]);
    float2 x1 = __half22float2(xp[1]);
    float2 y0 = __half22float2(yp[0]);
    float2 y1 = __half22float2(yp[1]);
    float4 s;
    s.x = x0.x + y0.x; s.y = x0.y + y0.y; s.z = x1.x + y1.x; s.w = x1.y + y1.y;
    float sum = s.x + s.y + s.z + s.w;
    float sq = s.x * s.x + s.y * s.y + s.z * s.z + s.w * s.w;
#pragma unroll
    for (int o = 16; o; o >>= 1) {
        sum += __shfl_xor_sync(0xFFFFFFFFu, sum, o);
        sq  += __shfl_xor_sync(0xFFFFFFFFu, sq, o);
    }
    __shared__ float s1[4], s2[4];
    if ((t & 31) == 0) { s1[t >> 5] = sum; s2[t >> 5] = sq; }
    __syncthreads();
    sum = s1[0] + s1[1] + s1[2] + s1[3];
    sq  = s2[0] + s2[1] + s2[2] + s2[3];
    const float mean = sum * (1.f / TE);
    const float var = sq * (1.f / TE) - mean * mean;
    const float rstd = rsqrtf(var + 1e-5f);
    float4 gv = reinterpret_cast<const float4*>(g)[t];
    float4 bv = reinterpret_cast<const float4*>(bb)[t];
    __half2* hx = reinterpret_cast<__half2*>(x16 + row * TE) + t * 2;
    hx[0] = __floats2half2_rn((s.x - mean) * rstd * gv.x + bv.x,
                              (s.y - mean) * rstd * gv.y + bv.y);
    hx[1] = __floats2half2_rn((s.z - mean) * rstd * gv.z + bv.z,
                              (s.w - mean) * rstd * gv.w + bv.w);
}

// ---------------------------------------------------------------------------
// CLS head: fp16 hidden, fp32 accumulate.
// ---------------------------------------------------------------------------
__global__ void cls_kernel(const __half* __restrict__ x16, const float* __restrict__ w,
                           const float* __restrict__ cb, float* __restrict__ out) {
    int t = threadIdx.x;
    if (t >= TB * 2) return;
    int b = t >> 1, c = t & 1;
    const __half* xr = x16 + (size_t)b * TS * TE;
    const float* wr = w + c * TE;
    float s = cb[c];
    for (int e = 0; e < TE; e++) s = fmaf(__half2float(xr[e]), wr[e], s);
    out[b * 2 + c] = s;
}

// ---------------------------------------------------------------------------
extern "C" void kernel_launch(void* const* d_in, const int* in_sizes, int n_in,
                              void* d_out, int out_size) {
    const int*   ids  = (const int*)d_in[0];
    const int*   mask = (const int*)d_in[1];
    const float* emb  = (const float*)d_in[2];
    const float* pos  = (const float*)d_in[3];
    const float* ipw  = (const float*)d_in[4];
    const float* ipb  = (const float*)d_in[5];
    const float* opw  = (const float*)d_in[6];
    const float* opb  = (const float*)d_in[7];
    const float* l1g  = (const float*)d_in[8];
    const float* l1b  = (const float*)d_in[9];
    const float* l2g  = (const float*)d_in[10];
    const float* l2b  = (const float*)d_in[11];
    const float* f1w  = (const float*)d_in[12];
    const float* f1b  = (const float*)d_in[13];
    const float* f2w  = (const float*)d_in[14];
    const float* f2b  = (const float*)d_in[15];
    const float* cw   = (const float*)d_in[16];
    const float* cb   = (const float*)d_in[17];
    float* out = (float*)d_out;
    float* attn_base = out + TB * 2;

    __half *y16, *qkv16, *x16, *att16, *h16, *w16;
    cudaGetSymbolAddress((void**)&y16,    g_y16);
    cudaGetSymbolAddress((void**)&qkv16,  g_qkv16);
    cudaGetSymbolAddress((void**)&x16,    g_x16);
    cudaGetSymbolAddress((void**)&att16,  g_att16);
    cudaGetSymbolAddress((void**)&h16,    g_h16);
    cudaGetSymbolAddress((void**)&w16,    g_w16);

    cudaFuncSetAttribute(hgemm_kernel<0>, cudaFuncAttributeMaxDynamicSharedMemorySize, HG_SMEM);
    cudaFuncSetAttribute(hgemm_kernel<1>, cudaFuncAttributeMaxDynamicSharedMemorySize, HG_SMEM);
    cudaFuncSetAttribute(attn_fused16_kernel, cudaFuncAttributeMaxDynamicSharedMemorySize, AF_SMEM);

    cvtw_kernel<<<W16_TOTAL / 4 / 256, 256>>>(ipw, opw, f1w, f2w, w16);
    embed_kernel<<<(TT * 128) / 256, 256>>>(ids, emb, pos, x16);

    for (int l = 0; l < TL; l++) {
        hgemm_kernel<0><<<dim3(QKVW / 128, TT / 128), 128, HG_SMEM>>>(
            x16, w16 + W16_IPW(l), ipb + l * QKVW, qkv16, QKVW, TE);

        float* attn_l = attn_base + (size_t)l * TB * TNH * TS * TS;
        attn_fused16_kernel<<<dim3(16, TB * TNH), 256, AF_SMEM>>>(
            qkv16, mask, attn_l, att16);

        hgemm_kernel<0><<<dim3(TE / 128, TT / 128), 128, HG_SMEM>>>(
            att16, w16 + W16_OPW(l), opb + l * TE, y16, TE, TE);
        add_ln_kernel<<<TT, 128>>>(x16, y16, l1g + l * TE, l1b + l * TE);

        hgemm_kernel<1><<<dim3(4 * TE / 128, TT / 128), 128, HG_SMEM>>>(
            x16, w16 + W16_F1W(l), f1b + l * 4 * TE, h16, 4 * TE, TE);
        hgemm_kernel<0><<<dim3(TE / 128, TT / 128), 128, HG_SMEM>>>(
            h16, w16 + W16_F2W(l), f2b + l * TE, y16, TE, 4 * TE);
        add_ln_kernel<<<TT, 128>>>(x16, y16, l2g + l * TE, l2b + l * TE);
    }

    cls_kernel<<<1, 64>>>(x16, cw, cb, out);
}

// round 15
// speedup vs baseline: 2.5060x; 1.0420x over previous
#include <cuda_runtime.h>
#include <cuda_fp16.h>
#include <cstdint>
#include <math.h>

// Problem constants
#define TB 32      // batch
#define TS 512     // seq len
#define TE 512     // d_model
#define THD 64     // head dim
#define TNH 8      // heads
#define TL 3       // layers
#define TT (TB*TS) // tokens = 16384
#define QKVW 1536  // 3*E

// Scratch (device globals; allocation-free contract)
__device__ __half g_y16[(size_t)TT * TE];      // gemm out fp16         16 MB
__device__ __half g_qkv16[(size_t)TT * QKVW];  // qkv fp16              48 MB
__device__ __half g_x16[(size_t)TT * TE];      // hidden fp16 residual  16 MB
__device__ __half g_att16[(size_t)TT * TE];    // attn concat fp16      16 MB
__device__ __half g_h16[(size_t)TT * 4 * TE];  // ffn hidden fp16       64 MB
#define W16_TOTAL 9437184
__device__ __half g_w16[W16_TOTAL];            // all weights fp16      18 MB
#define W16_IPW(l) ((size_t)(l) * 786432)
#define W16_OPW(l) (2359296 + (size_t)(l) * 262144)
#define W16_F1W(l) (3145728 + (size_t)(l) * 1048576)
#define W16_F2W(l) (6291456 + (size_t)(l) * 1048576)

#define MMA_F16(d, a, b)                                                      \
    asm volatile(                                                             \
        "mma.sync.aligned.m16n8k16.row.col.f32.f16.f16.f32 "                  \
        "{%0,%1,%2,%3}, {%4,%5,%6,%7}, {%8,%9}, {%0,%1,%2,%3};"               \
        : "+f"(d[0]), "+f"(d[1]), "+f"(d[2]), "+f"(d[3])                      \
        : "r"(a[0]), "r"(a[1]), "r"(a[2]), "r"(a[3]), "r"(b[0]), "r"(b[1]))

#define LDSM4(r0, r1, r2, r3, addr)                                           \
    asm volatile("ldmatrix.sync.aligned.m8n8.x4.shared.b16 {%0,%1,%2,%3}, [%4];" \
        : "=r"(r0), "=r"(r1), "=r"(r2), "=r"(r3) : "r"(addr))

#define LDSM4T(r0, r1, r2, r3, addr)                                          \
    asm volatile("ldmatrix.sync.aligned.m8n8.x4.trans.shared.b16 {%0,%1,%2,%3}, [%4];" \
        : "=r"(r0), "=r"(r1), "=r"(r2), "=r"(r3) : "r"(addr))

__device__ __forceinline__ void cpa16(uint32_t s, const void* g) {
    asm volatile("cp.async.cg.shared.global [%0], [%1], 16;" :: "r"(s), "l"(g));
}
__device__ __forceinline__ void cpa_commit() {
    asm volatile("cp.async.commit_group;");
}

// fp16 tile swizzles: chunk = 16B unit
// 64B-pitch rows (32 halfs) for hgemm
__device__ __forceinline__ uint32_t hswz(int row, int chunk) {
    return (uint32_t)(row * 64 + (((chunk + (row >> 1)) & 3) << 4));
}
// 128B-pitch rows (64 halfs) for attention tiles
#define ASWZ(row, c8) ((uint32_t)(((row) << 7) | ((((c8) ^ ((row) & 7))) << 4)))
// 1024B-pitch rows (512 halfs) for the P-probability smem tile
#define PSWZ(row, k8) ((uint32_t)(((row) << 10) | \
    (((((k8) & ~7) | (((k8) & 7) ^ ((row) & 7)))) << 4)))

// ---------------------------------------------------------------------------
// Weight conversion fp32 -> fp16 (once per launch, ~40us)
// ---------------------------------------------------------------------------
__global__ __launch_bounds__(256) void cvtw_kernel(
    const float* __restrict__ ipw, const float* __restrict__ opw,
    const float* __restrict__ f1w, const float* __restrict__ f2w,
    __half* __restrict__ w16) {
    size_t i = ((size_t)blockIdx.x * 256 + threadIdx.x) * 4;
    const float* src; size_t off;
    if (i < 2359296)      { src = ipw; off = i; }
    else if (i < 3145728) { src = opw; off = i - 2359296; }
    else if (i < 6291456) { src = f1w; off = i - 3145728; }
    else                  { src = f2w; off = i - 6291456; }
    float4 v = *reinterpret_cast<const float4*>(src + off);
    __half2* dst = reinterpret_cast<__half2*>(w16 + i);
    dst[0] = __floats2half2_rn(v.x, v.y);
    dst[1] = __floats2half2_rn(v.z, v.w);
}

// ---------------------------------------------------------------------------
// Embedding: x16 = fp16(emb[ids] + pos)
// ---------------------------------------------------------------------------
__global__ __launch_bounds__(256) void embed_kernel(
    const int* __restrict__ ids, const float* __restrict__ emb,
    const float* __restrict__ pos, __half* __restrict__ x16) {
    int idx = blockIdx.x * blockDim.x + threadIdx.x;
    int token = idx >> 7;
    int c = idx & 127;
    float4 e = reinterpret_cast<const float4*>(emb)[(size_t)ids[token] * 128 + c];
    float4 p = reinterpret_cast<const float4*>(pos)[(size_t)(token & (TS - 1)) * 128 + c];
    __half2* h = reinterpret_cast<__half2*>(x16) + idx * 2;
    h[0] = __floats2half2_rn(e.x + p.x, e.y + p.y);
    h[1] = __floats2half2_rn(e.z + p.z, e.w + p.w);
}

// ---------------------------------------------------------------------------
// FP16 tensor-core GEMM: C16 = A @ W^T + bias, opt GELU, fp16 out.
// Block 128x128, 128 thr, warp tile 64x64, 4-stage ring.
// B fragments loaded via paired LDSM4 (2 n-tiles x 2 k-chunks per op).
// ---------------------------------------------------------------------------
#define HSTG 16384
#define HG_SMEM (4 * HSTG)

template <int ACT>
__global__ __launch_bounds__(128, 2) void hgemm_kernel(
    const __half* __restrict__ A, const __half* __restrict__ W,
    const float* __restrict__ bias, __half* __restrict__ C16, int N, int K) {
    extern __shared__ char smraw[];
    uint32_t base;
    asm("{ .reg .u64 t; cvta.to.shared.u64 t, %1; cvt.u32.u64 %0, t; }"
        : "=r"(base) : "l"(smraw));

    const int t = threadIdx.x;
    const int lane = t & 31;
    const int warp = t >> 5;
    const int wr = (warp >> 1) * 64;
    const int wc = (warp & 1) * 64;
    const int qr = lane >> 2;
    const int qc = lane & 3;

    const int m0 = blockIdx.y * 128;
    const int n0 = blockIdx.x * 128;
    const int KT = K >> 5;

    const int arow = lane & 15;
    const int achk = lane >> 4;
    // paired-B LDSM4 addressing: lanes 0-7 (ni,k0), 8-15 (ni,k1),
    // 16-23 (ni+1,k0), 24-31 (ni+1,k1)
    const int bn2 = ((lane >> 4) << 3) + (lane & 7);  // row offset within ni pair
    const int bch = (lane >> 3) & 1;                  // k-chunk select

    float acc[4][8][4];
#pragma unroll
    for (int i = 0; i < 4; i++)
#pragma unroll
        for (int j = 0; j < 8; j++)
#pragma unroll
            for (int r = 0; r < 4; r++) acc[i][j][r] = 0.f;

#pragma unroll
    for (int s = 0; s < 3; s++) {
        uint32_t sb = base + s * HSTG;
#pragma unroll
        for (int i = 0; i < 4; i++) {
            int idx = t + 128 * i;
            int row = idx >> 2, c = idx & 3;
            cpa16(sb + hswz(row, c), A + (size_t)(m0 + row) * K + s * 32 + c * 8);
            cpa16(sb + 8192 + hswz(row, c), W + (size_t)(n0 + row) * K + s * 32 + c * 8);
        }
        cpa_commit();
    }

    for (int kt = 0; kt < KT; kt++) {
        int pend = KT - 1 - kt; if (pend > 2) pend = 2;
        if (pend == 2)      asm volatile("cp.async.wait_group 2;");
        else if (pend == 1) asm volatile("cp.async.wait_group 1;");
        else                asm volatile("cp.async.wait_group 0;");
        __syncthreads();

        if (kt + 3 < KT) {
            int j = kt + 3;
            uint32_t sb = base + (j & 3) * HSTG;
#pragma unroll
            for (int i = 0; i < 4; i++) {
                int idx = t + 128 * i;
                int row = idx >> 2, c = idx & 3;
                cpa16(sb + hswz(row, c), A + (size_t)(m0 + row) * K + j * 32 + c * 8);
                cpa16(sb + 8192 + hswz(row, c), W + (size_t)(n0 + row) * K + j * 32 + c * 8);
            }
            cpa_commit();
        } else {
            cpa_commit();
        }

        const uint32_t sb = base + (kt & 3) * HSTG;
#pragma unroll
        for (int s2 = 0; s2 < 2; s2++) {
            uint32_t a[4][4], bw[8][2];
#pragma unroll
            for (int mi = 0; mi < 4; mi++) {
                uint32_t ad = sb + hswz(wr + mi * 16 + arow, 2 * s2 + achk);
                LDSM4(a[mi][0], a[mi][1], a[mi][2], a[mi][3], ad);
            }
#pragma unroll
            for (int np = 0; np < 4; np++) {
                uint32_t bd = sb + 8192 + hswz(wc + np * 16 + bn2, 2 * s2 + bch);
                LDSM4(bw[2 * np][0], bw[2 * np][1],
                      bw[2 * np + 1][0], bw[2 * np + 1][1], bd);
            }
#pragma unroll
            for (int mi = 0; mi < 4; mi++)
#pragma unroll
                for (int ni = 0; ni < 8; ni++) MMA_F16(acc[mi][ni], a[mi], bw[ni]);
        }
    }

#pragma unroll
    for (int mi = 0; mi < 4; mi++) {
#pragma unroll
        for (int ni = 0; ni < 8; ni++) {
            int col = n0 + wc + ni * 8 + qc * 2;
            float b0 = bias[col], b1 = bias[col + 1];
#pragma unroll
            for (int half = 0; half < 2; half++) {
                int row = m0 + wr + mi * 16 + qr + half * 8;
                float v0 = acc[mi][ni][half * 2 + 0] + b0;
                float v1 = acc[mi][ni][half * 2 + 1] + b1;
                if (ACT == 1) {
                    v0 = 0.5f * v0 * (1.f + erff(v0 * 0.70710678118654752f));
                    v1 = 0.5f * v1 * (1.f + erff(v1 * 0.70710678118654752f));
                }
                *reinterpret_cast<__half2*>(C16 + (size_t)row * N + col) =
                    __floats2half2_rn(v0, v1);
            }
        }
    }
}

// ---------------------------------------------------------------------------
// Fully fused attention v2 (proven round-12): scores + softmax + AV,
// K/V fully smem-resident. Block: 32 q-rows x 512 keys for one (b,h).
// ---------------------------------------------------------------------------
#define AF_SMEM 101504

__global__ __launch_bounds__(256, 2) void attn_fused16_kernel(
    const __half* __restrict__ qkv16, const int* __restrict__ mask,
    float* __restrict__ attn, __half* __restrict__ att16) {
    extern __shared__ char smraw[];
    uint32_t base;
    asm("{ .reg .u64 t; cvta.to.shared.u64 t, %1; cvt.u32.u64 %0, t; }"
        : "=r"(base) : "l"(smraw));
    const uint32_t pbase = base + 65536;          // Q (phase 1) then P
    float* biasS = reinterpret_cast<float*>(smraw + 98304);
    float* red   = reinterpret_cast<float*>(smraw + 100352);

    const int t = threadIdx.x, lane = t & 31, warp = t >> 5;
    const int qr = lane >> 2, qc = lane & 3;
    const int bh = blockIdx.y, b = bh >> 3, h = bh & 7;
    const int m0 = blockIdx.x * 32;
    const __half* qb = qkv16 + (size_t)b * TS * QKVW + h * THD;
    const __half* kb = qb + TE;
    const __half* vb = qb + 2 * TE;

    for (int i = t; i < 512; i += 256)
        biasS[i] = (mask[b * TS + i] == 0) ? -1e30f : 0.f;

    // prologue: Q + K keys 0..255 -> group A; K keys 256..511 -> group B
    {
        int row = t >> 3, c8 = t & 7;
        cpa16(pbase + ASWZ(row, c8), qb + (size_t)(m0 + row) * QKVW + c8 * 8);
#pragma unroll
        for (int i = 0; i < 8; i++) {
            int u = t + 256 * i;
            int kr = u >> 3, kc = u & 7;
            cpa16(base + ASWZ(kr, kc), kb + (size_t)kr * QKVW + kc * 8);
        }
    }
    cpa_commit();
#pragma unroll
    for (int i = 0; i < 8; i++) {
        int u = t + 256 * i;
        int kr = 256 + (u >> 3), kc = u & 7;
        cpa16(base + ASWZ(kr, kc), kb + (size_t)kr * QKVW + kc * 8);
    }
    cpa_commit();

    float acc[8][2][4];
#pragma unroll
    for (int c = 0; c < 8; c++)
#pragma unroll
        for (int mi = 0; mi < 2; mi++)
#pragma unroll
            for (int r = 0; r < 4; r++) acc[c][mi][r] = 0.f;

    const int arow = lane & 15, achk = lane >> 4;
    const int kchk_off = lane >> 4;
    const int kk_half  = (lane >> 3) & 1;
    const int krow8    = lane & 7;

    // ---- Phase 1: QK^T (s-outer, chunk-inner) ----
    asm volatile("cp.async.wait_group 1;");
    __syncthreads();
#pragma unroll
    for (int hf = 0; hf < 2; hf++) {
        if (hf == 1) {
            asm volatile("cp.async.wait_group 0;");
            __syncthreads();
        }
#pragma unroll
        for (int s = 0; s < 4; s++) {
            uint32_t qf[2][4];
#pragma unroll
            for (int mi = 0; mi < 2; mi++)
                LDSM4(qf[mi][0], qf[mi][1], qf[mi][2], qf[mi][3],
                      pbase + ASWZ(mi * 16 + arow, 2 * s + achk));
#pragma unroll
            for (int cc = 0; cc < 2; cc++) {
                const int c = hf * 4 + cc * 2;
                uint32_t k4[4];
                LDSM4(k4[0], k4[1], k4[2], k4[3],
                      base + ASWZ((c + kchk_off) * 64 + warp * 8 + krow8,
                                  2 * s + kk_half));
#pragma unroll
                for (int mi = 0; mi < 2; mi++) {
                    MMA_F16(acc[c][mi], qf[mi], (k4 + 0));
                    MMA_F16(acc[c + 1][mi], qf[mi], (k4 + 2));
                }
            }
        }
    }
    __syncthreads();   // all K reads done; V may overwrite

    // Issue V loads (overlap with softmax)
#pragma unroll
    for (int i = 0; i < 8; i++) {
        int u = t + 256 * i;
        int vr = u >> 3, vc = u & 7;
        cpa16(base + ASWZ(vr, vc), vb + (size_t)vr * QKVW + vc * 8);
    }
    cpa_commit();
#pragma unroll
    for (int i = 0; i < 8; i++) {
        int u = t + 256 * i;
        int vr = 256 + (u >> 3), vc = u & 7;
        cpa16(base + ASWZ(vr, vc), vb + (size_t)vr * QKVW + vc * 8);
    }
    cpa_commit();

    // ---- softmax over 512 keys per row (32 rows) ----
    float bm[2][2], bs[2][2];
    const float scale = 0.125f;
#pragma unroll
    for (int mi = 0; mi < 2; mi++) {
#pragma unroll
        for (int h2 = 0; h2 < 2; h2++) {
            float m = -3.4e38f;
#pragma unroll
            for (int c = 0; c < 8; c++) {
                int col = c * 64 + warp * 8 + qc * 2;
                float v0 = acc[c][mi][2 * h2 + 0] * scale + biasS[col];
                float v1 = acc[c][mi][2 * h2 + 1] * scale + biasS[col + 1];
                acc[c][mi][2 * h2 + 0] = v0;
                acc[c][mi][2 * h2 + 1] = v1;
                m = fmaxf(m, fmaxf(v0, v1));
            }
            m = fmaxf(m, __shfl_xor_sync(0xFFFFFFFFu, m, 1));
            m = fmaxf(m, __shfl_xor_sync(0xFFFFFFFFu, m, 2));
            bm[mi][h2] = m;
        }
    }
    if (qc == 0) {
#pragma unroll
        for (int mi = 0; mi < 2; mi++)
#pragma unroll
            for (int h2 = 0; h2 < 2; h2++)
                red[(mi * 16 + qr + h2 * 8) * 9 + warp] = bm[mi][h2];
    }
    __syncthreads();
#pragma unroll
    for (int mi = 0; mi < 2; mi++)
#pragma unroll
        for (int h2 = 0; h2 < 2; h2++) {
            int row = mi * 16 + qr + h2 * 8;
            float m = red[row * 9 + 0];
#pragma unroll
            for (int w2 = 1; w2 < 8; w2++) m = fmaxf(m, red[row * 9 + w2]);
            bm[mi][h2] = m;
        }
    __syncthreads();
#pragma unroll
    for (int mi = 0; mi < 2; mi++) {
#pragma unroll
        for (int h2 = 0; h2 < 2; h2++) {
            float m = bm[mi][h2];
            float s = 0.f;
#pragma unroll
            for (int c = 0; c < 8; c++) {
                float e0 = __expf(acc[c][mi][2 * h2 + 0] - m);
                float e1 = __expf(acc[c][mi][2 * h2 + 1] - m);
                acc[c][mi][2 * h2 + 0] = e0;
                acc[c][mi][2 * h2 + 1] = e1;
                s += e0 + e1;
            }
            s += __shfl_xor_sync(0xFFFFFFFFu, s, 1);
            s += __shfl_xor_sync(0xFFFFFFFFu, s, 2);
            bs[mi][h2] = s;
        }
    }
    if (qc == 0) {
#pragma unroll
        for (int mi = 0; mi < 2; mi++)
#pragma unroll
            for (int h2 = 0; h2 < 2; h2++)
                red[(mi * 16 + qr + h2 * 8) * 9 + warp] = bs[mi][h2];
    }
    __syncthreads();
    // normalize; write fp32 probs (streaming) + fp16 P into SMEM
#pragma unroll
    for (int mi = 0; mi < 2; mi++)
#pragma unroll
        for (int h2 = 0; h2 < 2; h2++) {
            int row = mi * 16 + qr + h2 * 8;
            float s = 0.f;
#pragma unroll
            for (int w2 = 0; w2 < 8; w2++) s += red[row * 9 + w2];
            float inv = 1.f / s;
            float* orow = attn + ((size_t)bh * TS + m0 + row) * TS;
#pragma unroll
            for (int c = 0; c < 8; c++) {
                int col = c * 64 + warp * 8 + qc * 2;
                float2 o;
                o.x = acc[c][mi][2 * h2 + 0] * inv;
                o.y = acc[c][mi][2 * h2 + 1] * inv;
                __stcs(reinterpret_cast<float2*>(orow + col), o);
                __half2 hv = __floats2half2_rn(o.x, o.y);
                uint32_t u = *reinterpret_cast<uint32_t*>(&hv);
                asm volatile("st.shared.b32 [%0], %1;"
                             :: "r"(pbase + PSWZ(row, c * 8 + warp) + qc * 4), "r"(u)
                             : "memory");
            }
        }

    // ---- Phase 2: O = P @ V; warp w owns head dims [w*8, w*8+8) ----
    float oacc[2][4];
#pragma unroll
    for (int mi = 0; mi < 2; mi++)
#pragma unroll
        for (int r = 0; r < 4; r++) oacc[mi][r] = 0.f;

    asm volatile("cp.async.wait_group 1;");
    __syncthreads();   // V keys 0..255 + all P stores visible
#pragma unroll
    for (int hf = 0; hf < 2; hf++) {
        if (hf == 1) {
            asm volatile("cp.async.wait_group 0;");
            __syncthreads();
        }
#pragma unroll
        for (int ks2 = 0; ks2 < 8; ks2++) {
            const int ks = hf * 16 + ks2 * 2;
            uint32_t bw4[4];
            LDSM4T(bw4[0], bw4[1], bw4[2], bw4[3],
                   base + ASWZ(ks * 16 + lane, warp));
#pragma unroll
            for (int k2 = 0; k2 < 2; k2++) {
                uint32_t af[2][4];
#pragma unroll
                for (int mi = 0; mi < 2; mi++)
                    LDSM4(af[mi][0], af[mi][1], af[mi][2], af[mi][3],
                          pbase + PSWZ(mi * 16 + arow, (ks + k2) * 2 + achk));
#pragma unroll
                for (int mi = 0; mi < 2; mi++)
                    MMA_F16(oacc[mi], af[mi], (bw4 + 2 * k2));
            }
        }
    }

    // epilogue: write att16 (concat layout)
#pragma unroll
    for (int mi = 0; mi < 2; mi++) {
#pragma unroll
        for (int h2 = 0; h2 < 2; h2++) {
            int row = m0 + mi * 16 + qr + h2 * 8;
            int col = h * THD + warp * 8 + qc * 2;
            *reinterpret_cast<__half2*>(att16 + ((size_t)b * TS + row) * TE + col) =
                __floats2half2_rn(oacc[mi][2 * h2 + 0], oacc[mi][2 * h2 + 1]);
        }
    }
}

// ---------------------------------------------------------------------------
// Fused residual + LayerNorm, fp16 residual stream:
// x16 = fp16(LN(x16 + y16) * g + b). 1 block/token, 128 thr. fp32 sums.
// ---------------------------------------------------------------------------
__global__ __launch_bounds__(128) void add_ln_kernel(
    __half* __restrict__ x16, const __half* __restrict__ y16,
    const float* __restrict__ g, const float* __restrict__ bb) {
    const size_t row = blockIdx.x;
    const int t = threadIdx.x;
    const __half2* xp = reinterpret_cast<const __half2*>(x16 + row * TE) + t * 2;
    const __half2* yp = reinterpret_cast<const __half2*>(y16 + row * TE) + t * 2;
    float2 x0 = __half22float2(xp[0]);
    float2 x1 = __half22float2(xp[1]);
    float2 y0 = __half22float2(yp[0]);
    float2 y1 = __half22float2(yp[1]);
    float4 s;
    s.x = x0.x + y0.x; s.y = x0.y + y0.y; s.z = x1.x + y1.x; s.w = x1.y + y1.y;
    float sum = s.x + s.y + s.z + s.w;
    float sq = s.x * s.x + s.y * s.y + s.z * s.z + s.w * s.w;
#pragma unroll
    for (int o = 16; o; o >>= 1) {
        sum += __shfl_xor_sync(0xFFFFFFFFu, sum, o);
        sq  += __shfl_xor_sync(0xFFFFFFFFu, sq, o);
    }
    __shared__ float s1[4], s2[4];
    if ((t & 31) == 0) { s1[t >> 5] = sum; s2[t >> 5] = sq; }
    __syncthreads();
    sum = s1[0] + s1[1] + s1[2] + s1[3];
    sq  = s2[0] + s2[1] + s2[2] + s2[3];
    const float mean = sum * (1.f / TE);
    const float var = sq * (1.f / TE) - mean * mean;
    const float rstd = rsqrtf(var + 1e-5f);
    float4 gv = reinterpret_cast<const float4*>(g)[t];
    float4 bv = reinterpret_cast<const float4*>(bb)[t];
    __half2* hx = reinterpret_cast<__half2*>(x16 + row * TE) + t * 2;
    hx[0] = __floats2half2_rn((s.x - mean) * rstd * gv.x + bv.x,
                              (s.y - mean) * rstd * gv.y + bv.y);
    hx[1] = __floats2half2_rn((s.z - mean) * rstd * gv.z + bv.z,
                              (s.w - mean) * rstd * gv.w + bv.w);
}

// ---------------------------------------------------------------------------
// CLS head: fp16 hidden, fp32 accumulate.
// ---------------------------------------------------------------------------
__global__ void cls_kernel(const __half* __restrict__ x16, const float* __restrict__ w,
                           const float* __restrict__ cb, float* __restrict__ out) {
    int t = threadIdx.x;
    if (t >= TB * 2) return;
    int b = t >> 1, c = t & 1;
    const __half* xr = x16 + (size_t)b * TS * TE;
    const float* wr = w + c * TE;
    float s = cb[c];
    for (int e = 0; e < TE; e++) s = fmaf(__half2float(xr[e]), wr[e], s);
    out[b * 2 + c] = s;
}

// ---------------------------------------------------------------------------
extern "C" void kernel_launch(void* const* d_in, const int* in_sizes, int n_in,
                              void* d_out, int out_size) {
    const int*   ids  = (const int*)d_in[0];
    const int*   mask = (const int*)d_in[1];
    const float* emb  = (const float*)d_in[2];
    const float* pos  = (const float*)d_in[3];
    const float* ipw  = (const float*)d_in[4];
    const float* ipb  = (const float*)d_in[5];
    const float* opw  = (const float*)d_in[6];
    const float* opb  = (const float*)d_in[7];
    const float* l1g  = (const float*)d_in[8];
    const float* l1b  = (const float*)d_in[9];
    const float* l2g  = (const float*)d_in[10];
    const float* l2b  = (const float*)d_in[11];
    const float* f1w  = (const float*)d_in[12];
    const float* f1b  = (const float*)d_in[13];
    const float* f2w  = (const float*)d_in[14];
    const float* f2b  = (const float*)d_in[15];
    const float* cw   = (const float*)d_in[16];
    const float* cb   = (const float*)d_in[17];
    float* out = (float*)d_out;
    float* attn_base = out + TB * 2;

    __half *y16, *qkv16, *x16, *att16, *h16, *w16;
    cudaGetSymbolAddress((void**)&y16,    g_y16);
    cudaGetSymbolAddress((void**)&qkv16,  g_qkv16);
    cudaGetSymbolAddress((void**)&x16,    g_x16);
    cudaGetSymbolAddress((void**)&att16,  g_att16);
    cudaGetSymbolAddress((void**)&h16,    g_h16);
    cudaGetSymbolAddress((void**)&w16,    g_w16);

    cudaFuncSetAttribute(hgemm_kernel<0>, cudaFuncAttributeMaxDynamicSharedMemorySize, HG_SMEM);
    cudaFuncSetAttribute(hgemm_kernel<1>, cudaFuncAttributeMaxDynamicSharedMemorySize, HG_SMEM);
    cudaFuncSetAttribute(attn_fused16_kernel, cudaFuncAttributeMaxDynamicSharedMemorySize, AF_SMEM);

    cvtw_kernel<<<W16_TOTAL / 4 / 256, 256>>>(ipw, opw, f1w, f2w, w16);
    embed_kernel<<<(TT * 128) / 256, 256>>>(ids, emb, pos, x16);

    for (int l = 0; l < TL; l++) {
        hgemm_kernel<0><<<dim3(QKVW / 128, TT / 128), 128, HG_SMEM>>>(
            x16, w16 + W16_IPW(l), ipb + l * QKVW, qkv16, QKVW, TE);

        float* attn_l = attn_base + (size_t)l * TB * TNH * TS * TS;
        attn_fused16_kernel<<<dim3(16, TB * TNH), 256, AF_SMEM>>>(
            qkv16, mask, attn_l, att16);

        hgemm_kernel<0><<<dim3(TE / 128, TT / 128), 128, HG_SMEM>>>(
            att16, w16 + W16_OPW(l), opb + l * TE, y16, TE, TE);
        add_ln_kernel<<<TT, 128>>>(x16, y16, l1g + l * TE, l1b + l * TE);

        hgemm_kernel<1><<<dim3(4 * TE / 128, TT / 128), 128, HG_SMEM>>>(
            x16, w16 + W16_F1W(l), f1b + l * 4 * TE, h16, 4 * TE, TE);
        hgemm_kernel<0><<<dim3(TE / 128, TT / 128), 128, HG_SMEM>>>(
            h16, w16 + W16_F2W(l), f2b + l * TE, y16, TE, 4 * TE);
        add_ln_kernel<<<TT, 128>>>(x16, y16, l2g + l * TE, l2b + l * TE);
    }

    cls_kernel<<<1, 64>>>(x16, cw, cb, out);
}

// round 16
// speedup vs baseline: 2.5803x; 1.0296x over previous
#include <cuda_runtime.h>
#include <cuda_fp16.h>
#include <cstdint>
#include <math.h>

// Problem constants
#define TB 32      // batch
#define TS 512     // seq len
#define TE 512     // d_model
#define THD 64     // head dim
#define TNH 8      // heads
#define TL 3       // layers
#define TT (TB*TS) // tokens = 16384
#define QKVW 1536  // 3*E

// Scratch (device globals; allocation-free contract)
__device__ __half g_y16[(size_t)TT * TE];      // gemm out fp16         16 MB
__device__ __half g_qkv16[(size_t)TT * QKVW];  // qkv fp16              48 MB
__device__ __half g_x16[(size_t)TT * TE];      // hidden fp16 residual  16 MB
__device__ __half g_att16[(size_t)TT * TE];    // attn concat fp16      16 MB
__device__ __half g_h16[(size_t)TT * 4 * TE];  // ffn hidden fp16       64 MB
#define W16_TOTAL 9437184
__device__ __half g_w16[W16_TOTAL];            // all weights fp16      18 MB
#define W16_IPW(l) ((size_t)(l) * 786432)
#define W16_OPW(l) (2359296 + (size_t)(l) * 262144)
#define W16_F1W(l) (3145728 + (size_t)(l) * 1048576)
#define W16_F2W(l) (6291456 + (size_t)(l) * 1048576)

#define MMA_F16(d, a, b)                                                      \
    asm volatile(                                                             \
        "mma.sync.aligned.m16n8k16.row.col.f32.f16.f16.f32 "                  \
        "{%0,%1,%2,%3}, {%4,%5,%6,%7}, {%8,%9}, {%0,%1,%2,%3};"               \
        : "+f"(d[0]), "+f"(d[1]), "+f"(d[2]), "+f"(d[3])                      \
        : "r"(a[0]), "r"(a[1]), "r"(a[2]), "r"(a[3]), "r"(b[0]), "r"(b[1]))

#define LDSM4(r0, r1, r2, r3, addr)                                           \
    asm volatile("ldmatrix.sync.aligned.m8n8.x4.shared.b16 {%0,%1,%2,%3}, [%4];" \
        : "=r"(r0), "=r"(r1), "=r"(r2), "=r"(r3) : "r"(addr))

#define LDSM4T(r0, r1, r2, r3, addr)                                          \
    asm volatile("ldmatrix.sync.aligned.m8n8.x4.trans.shared.b16 {%0,%1,%2,%3}, [%4];" \
        : "=r"(r0), "=r"(r1), "=r"(r2), "=r"(r3) : "r"(addr))

__device__ __forceinline__ void cpa16(uint32_t s, const void* g) {
    asm volatile("cp.async.cg.shared.global [%0], [%1], 16;" :: "r"(s), "l"(g));
}
__device__ __forceinline__ void cpa_commit() {
    asm volatile("cp.async.commit_group;");
}

// fp16 tile swizzles: chunk = 16B unit
// 128B-pitch rows (64 halfs) — used by hgemm tiles and attention tiles
#define ASWZ(row, c8) ((uint32_t)(((row) << 7) | ((((c8) ^ ((row) & 7))) << 4)))
// 1024B-pitch rows (512 halfs) for the P-probability smem tile
#define PSWZ(row, k8) ((uint32_t)(((row) << 10) | \
    (((((k8) & ~7) | (((k8) & 7) ^ ((row) & 7)))) << 4)))

// ---------------------------------------------------------------------------
// Weight conversion fp32 -> fp16 (once per launch)
// ---------------------------------------------------------------------------
__global__ __launch_bounds__(256) void cvtw_kernel(
    const float* __restrict__ ipw, const float* __restrict__ opw,
    const float* __restrict__ f1w, const float* __restrict__ f2w,
    __half* __restrict__ w16) {
    size_t i = ((size_t)blockIdx.x * 256 + threadIdx.x) * 4;
    const float* src; size_t off;
    if (i < 2359296)      { src = ipw; off = i; }
    else if (i < 3145728) { src = opw; off = i - 2359296; }
    else if (i < 6291456) { src = f1w; off = i - 3145728; }
    else                  { src = f2w; off = i - 6291456; }
    float4 v = *reinterpret_cast<const float4*>(src + off);
    __half2* dst = reinterpret_cast<__half2*>(w16 + i);
    dst[0] = __floats2half2_rn(v.x, v.y);
    dst[1] = __floats2half2_rn(v.z, v.w);
}

// ---------------------------------------------------------------------------
// Embedding: x16 = fp16(emb[ids] + pos)
// ---------------------------------------------------------------------------
__global__ __launch_bounds__(256) void embed_kernel(
    const int* __restrict__ ids, const float* __restrict__ emb,
    const float* __restrict__ pos, __half* __restrict__ x16) {
    int idx = blockIdx.x * blockDim.x + threadIdx.x;
    int token = idx >> 7;
    int c = idx & 127;
    float4 e = reinterpret_cast<const float4*>(emb)[(size_t)ids[token] * 128 + c];
    float4 p = reinterpret_cast<const float4*>(pos)[(size_t)(token & (TS - 1)) * 128 + c];
    __half2* h = reinterpret_cast<__half2*>(x16) + idx * 2;
    h[0] = __floats2half2_rn(e.x + p.x, e.y + p.y);
    h[1] = __floats2half2_rn(e.z + p.z, e.w + p.w);
}

// ---------------------------------------------------------------------------
// FP16 tensor-core GEMM v3: C16 = A @ W^T + bias, opt GELU, fp16 out.
// Block 128x128, 128 thr, warp tile 64x64. k-tile 64 (128B ASWZ rows),
// 3-stage cp.async ring (32KB/stage); paired-B LDSM4.
// ---------------------------------------------------------------------------
#define HSTG 32768
#define HG_SMEM (3 * HSTG)

template <int ACT>
__global__ __launch_bounds__(128, 2) void hgemm_kernel(
    const __half* __restrict__ A, const __half* __restrict__ W,
    const float* __restrict__ bias, __half* __restrict__ C16, int N, int K) {
    extern __shared__ char smraw[];
    uint32_t base;
    asm("{ .reg .u64 t; cvta.to.shared.u64 t, %1; cvt.u32.u64 %0, t; }"
        : "=r"(base) : "l"(smraw));

    const int t = threadIdx.x;
    const int lane = t & 31;
    const int warp = t >> 5;
    const int wr = (warp >> 1) * 64;
    const int wc = (warp & 1) * 64;
    const int qr = lane >> 2;
    const int qc = lane & 3;

    const int m0 = blockIdx.y * 128;
    const int n0 = blockIdx.x * 128;
    const int KT = K >> 6;

    const int arow = lane & 15;
    const int achk = lane >> 4;
    // paired-B LDSM4: lanes 0-7 (ni,k0), 8-15 (ni,k1), 16-23 (ni+1,k0), 24-31 (ni+1,k1)
    const int bn2 = ((lane >> 4) << 3) + (lane & 7);
    const int bch = (lane >> 3) & 1;

    float acc[4][8][4];
#pragma unroll
    for (int i = 0; i < 4; i++)
#pragma unroll
        for (int j = 0; j < 8; j++)
#pragma unroll
            for (int r = 0; r < 4; r++) acc[i][j][r] = 0.f;

    // prologue: stages 0,1
#pragma unroll
    for (int s = 0; s < 2; s++) {
        uint32_t sb = base + s * HSTG;
#pragma unroll
        for (int i = 0; i < 8; i++) {
            int idx = t + 128 * i;
            int row = idx >> 3, c8 = idx & 7;
            cpa16(sb + ASWZ(row, c8), A + (size_t)(m0 + row) * K + s * 64 + c8 * 8);
            cpa16(sb + 16384 + ASWZ(row, c8), W + (size_t)(n0 + row) * K + s * 64 + c8 * 8);
        }
        cpa_commit();
    }

    for (int kt = 0; kt < KT; kt++) {
        if (kt + 1 < KT) asm volatile("cp.async.wait_group 1;");
        else             asm volatile("cp.async.wait_group 0;");
        __syncthreads();

        if (kt + 2 < KT) {
            int j = kt + 2;
            uint32_t sb = base + (j % 3) * HSTG;
#pragma unroll
            for (int i = 0; i < 8; i++) {
                int idx = t + 128 * i;
                int row = idx >> 3, c8 = idx & 7;
                cpa16(sb + ASWZ(row, c8), A + (size_t)(m0 + row) * K + j * 64 + c8 * 8);
                cpa16(sb + 16384 + ASWZ(row, c8), W + (size_t)(n0 + row) * K + j * 64 + c8 * 8);
            }
            cpa_commit();
        } else {
            cpa_commit();
        }

        const uint32_t sb = base + (kt % 3) * HSTG;
#pragma unroll
        for (int s2 = 0; s2 < 4; s2++) {
            uint32_t a[4][4], bw[8][2];
#pragma unroll
            for (int mi = 0; mi < 4; mi++) {
                uint32_t ad = sb + ASWZ(wr + mi * 16 + arow, 2 * s2 + achk);
                LDSM4(a[mi][0], a[mi][1], a[mi][2], a[mi][3], ad);
            }
#pragma unroll
            for (int np = 0; np < 4; np++) {
                uint32_t bd = sb + 16384 + ASWZ(wc + np * 16 + bn2, 2 * s2 + bch);
                LDSM4(bw[2 * np][0], bw[2 * np][1],
                      bw[2 * np + 1][0], bw[2 * np + 1][1], bd);
            }
#pragma unroll
            for (int mi = 0; mi < 4; mi++)
#pragma unroll
                for (int ni = 0; ni < 8; ni++) MMA_F16(acc[mi][ni], a[mi], bw[ni]);
        }
    }

#pragma unroll
    for (int mi = 0; mi < 4; mi++) {
#pragma unroll
        for (int ni = 0; ni < 8; ni++) {
            int col = n0 + wc + ni * 8 + qc * 2;
            float b0 = bias[col], b1 = bias[col + 1];
#pragma unroll
            for (int half = 0; half < 2; half++) {
                int row = m0 + wr + mi * 16 + qr + half * 8;
                float v0 = acc[mi][ni][half * 2 + 0] + b0;
                float v1 = acc[mi][ni][half * 2 + 1] + b1;
                if (ACT == 1) {
                    v0 = 0.5f * v0 * (1.f + erff(v0 * 0.70710678118654752f));
                    v1 = 0.5f * v1 * (1.f + erff(v1 * 0.70710678118654752f));
                }
                *reinterpret_cast<__half2*>(C16 + (size_t)row * N + col) =
                    __floats2half2_rn(v0, v1);
            }
        }
    }
}

// ---------------------------------------------------------------------------
// Fully fused attention v2 (proven round-12): scores + softmax + AV,
// K/V fully smem-resident. Block: 32 q-rows x 512 keys for one (b,h).
// ---------------------------------------------------------------------------
#define AF_SMEM 101504

__global__ __launch_bounds__(256, 2) void attn_fused16_kernel(
    const __half* __restrict__ qkv16, const int* __restrict__ mask,
    float* __restrict__ attn, __half* __restrict__ att16) {
    extern __shared__ char smraw[];
    uint32_t base;
    asm("{ .reg .u64 t; cvta.to.shared.u64 t, %1; cvt.u32.u64 %0, t; }"
        : "=r"(base) : "l"(smraw));
    const uint32_t pbase = base + 65536;          // Q (phase 1) then P
    float* biasS = reinterpret_cast<float*>(smraw + 98304);
    float* red   = reinterpret_cast<float*>(smraw + 100352);

    const int t = threadIdx.x, lane = t & 31, warp = t >> 5;
    const int qr = lane >> 2, qc = lane & 3;
    const int bh = blockIdx.y, b = bh >> 3, h = bh & 7;
    const int m0 = blockIdx.x * 32;
    const __half* qb = qkv16 + (size_t)b * TS * QKVW + h * THD;
    const __half* kb = qb + TE;
    const __half* vb = qb + 2 * TE;

    for (int i = t; i < 512; i += 256)
        biasS[i] = (mask[b * TS + i] == 0) ? -1e30f : 0.f;

    // prologue: Q + K keys 0..255 -> group A; K keys 256..511 -> group B
    {
        int row = t >> 3, c8 = t & 7;
        cpa16(pbase + ASWZ(row, c8), qb + (size_t)(m0 + row) * QKVW + c8 * 8);
#pragma unroll
        for (int i = 0; i < 8; i++) {
            int u = t + 256 * i;
            int kr = u >> 3, kc = u & 7;
            cpa16(base + ASWZ(kr, kc), kb + (size_t)kr * QKVW + kc * 8);
        }
    }
    cpa_commit();
#pragma unroll
    for (int i = 0; i < 8; i++) {
        int u = t + 256 * i;
        int kr = 256 + (u >> 3), kc = u & 7;
        cpa16(base + ASWZ(kr, kc), kb + (size_t)kr * QKVW + kc * 8);
    }
    cpa_commit();

    float acc[8][2][4];
#pragma unroll
    for (int c = 0; c < 8; c++)
#pragma unroll
        for (int mi = 0; mi < 2; mi++)
#pragma unroll
            for (int r = 0; r < 4; r++) acc[c][mi][r] = 0.f;

    const int arow = lane & 15, achk = lane >> 4;
    const int kchk_off = lane >> 4;
    const int kk_half  = (lane >> 3) & 1;
    const int krow8    = lane & 7;

    // ---- Phase 1: QK^T (s-outer, chunk-inner) ----
    asm volatile("cp.async.wait_group 1;");
    __syncthreads();
#pragma unroll
    for (int hf = 0; hf < 2; hf++) {
        if (hf == 1) {
            asm volatile("cp.async.wait_group 0;");
            __syncthreads();
        }
#pragma unroll
        for (int s = 0; s < 4; s++) {
            uint32_t qf[2][4];
#pragma unroll
            for (int mi = 0; mi < 2; mi++)
                LDSM4(qf[mi][0], qf[mi][1], qf[mi][2], qf[mi][3],
                      pbase + ASWZ(mi * 16 + arow, 2 * s + achk));
#pragma unroll
            for (int cc = 0; cc < 2; cc++) {
                const int c = hf * 4 + cc * 2;
                uint32_t k4[4];
                LDSM4(k4[0], k4[1], k4[2], k4[3],
                      base + ASWZ((c + kchk_off) * 64 + warp * 8 + krow8,
                                  2 * s + kk_half));
#pragma unroll
                for (int mi = 0; mi < 2; mi++) {
                    MMA_F16(acc[c][mi], qf[mi], (k4 + 0));
                    MMA_F16(acc[c + 1][mi], qf[mi], (k4 + 2));
                }
            }
        }
    }
    __syncthreads();   // all K reads done; V may overwrite

    // Issue V loads (overlap with softmax)
#pragma unroll
    for (int i = 0; i < 8; i++) {
        int u = t + 256 * i;
        int vr = u >> 3, vc = u & 7;
        cpa16(base + ASWZ(vr, vc), vb + (size_t)vr * QKVW + vc * 8);
    }
    cpa_commit();
#pragma unroll
    for (int i = 0; i < 8; i++) {
        int u = t + 256 * i;
        int vr = 256 + (u >> 3), vc = u & 7;
        cpa16(base + ASWZ(vr, vc), vb + (size_t)vr * QKVW + vc * 8);
    }
    cpa_commit();

    // ---- softmax over 512 keys per row (32 rows) ----
    float bm[2][2], bs[2][2];
    const float scale = 0.125f;
#pragma unroll
    for (int mi = 0; mi < 2; mi++) {
#pragma unroll
        for (int h2 = 0; h2 < 2; h2++) {
            float m = -3.4e38f;
#pragma unroll
            for (int c = 0; c < 8; c++) {
                int col = c * 64 + warp * 8 + qc * 2;
                float v0 = acc[c][mi][2 * h2 + 0] * scale + biasS[col];
                float v1 = acc[c][mi][2 * h2 + 1] * scale + biasS[col + 1];
                acc[c][mi][2 * h2 + 0] = v0;
                acc[c][mi][2 * h2 + 1] = v1;
                m = fmaxf(m, fmaxf(v0, v1));
            }
            m = fmaxf(m, __shfl_xor_sync(0xFFFFFFFFu, m, 1));
            m = fmaxf(m, __shfl_xor_sync(0xFFFFFFFFu, m, 2));
            bm[mi][h2] = m;
        }
    }
    if (qc == 0) {
#pragma unroll
        for (int mi = 0; mi < 2; mi++)
#pragma unroll
            for (int h2 = 0; h2 < 2; h2++)
                red[(mi * 16 + qr + h2 * 8) * 9 + warp] = bm[mi][h2];
    }
    __syncthreads();
#pragma unroll
    for (int mi = 0; mi < 2; mi++)
#pragma unroll
        for (int h2 = 0; h2 < 2; h2++) {
            int row = mi * 16 + qr + h2 * 8;
            float m = red[row * 9 + 0];
#pragma unroll
            for (int w2 = 1; w2 < 8; w2++) m = fmaxf(m, red[row * 9 + w2]);
            bm[mi][h2] = m;
        }
    __syncthreads();
#pragma unroll
    for (int mi = 0; mi < 2; mi++) {
#pragma unroll
        for (int h2 = 0; h2 < 2; h2++) {
            float m = bm[mi][h2];
            float s = 0.f;
#pragma unroll
            for (int c = 0; c < 8; c++) {
                float e0 = __expf(acc[c][mi][2 * h2 + 0] - m);
                float e1 = __expf(acc[c][mi][2 * h2 + 1] - m);
                acc[c][mi][2 * h2 + 0] = e0;
                acc[c][mi][2 * h2 + 1] = e1;
                s += e0 + e1;
            }
            s += __shfl_xor_sync(0xFFFFFFFFu, s, 1);
            s += __shfl_xor_sync(0xFFFFFFFFu, s, 2);
            bs[mi][h2] = s;
        }
    }
    if (qc == 0) {
#pragma unroll
        for (int mi = 0; mi < 2; mi++)
#pragma unroll
            for (int h2 = 0; h2 < 2; h2++)
                red[(mi * 16 + qr + h2 * 8) * 9 + warp] = bs[mi][h2];
    }
    __syncthreads();
    // normalize; write fp32 probs (streaming) + fp16 P into SMEM
#pragma unroll
    for (int mi = 0; mi < 2; mi++)
#pragma unroll
        for (int h2 = 0; h2 < 2; h2++) {
            int row = mi * 16 + qr + h2 * 8;
            float s = 0.f;
#pragma unroll
            for (int w2 = 0; w2 < 8; w2++) s += red[row * 9 + w2];
            float inv = 1.f / s;
            float* orow = attn + ((size_t)bh * TS + m0 + row) * TS;
#pragma unroll
            for (int c = 0; c < 8; c++) {
                int col = c * 64 + warp * 8 + qc * 2;
                float2 o;
                o.x = acc[c][mi][2 * h2 + 0] * inv;
                o.y = acc[c][mi][2 * h2 + 1] * inv;
                __stcs(reinterpret_cast<float2*>(orow + col), o);
                __half2 hv = __floats2half2_rn(o.x, o.y);
                uint32_t u = *reinterpret_cast<uint32_t*>(&hv);
                asm volatile("st.shared.b32 [%0], %1;"
                             :: "r"(pbase + PSWZ(row, c * 8 + warp) + qc * 4), "r"(u)
                             : "memory");
            }
        }

    // ---- Phase 2: O = P @ V; warp w owns head dims [w*8, w*8+8) ----
    float oacc[2][4];
#pragma unroll
    for (int mi = 0; mi < 2; mi++)
#pragma unroll
        for (int r = 0; r < 4; r++) oacc[mi][r] = 0.f;

    asm volatile("cp.async.wait_group 1;");
    __syncthreads();   // V keys 0..255 + all P stores visible
#pragma unroll
    for (int hf = 0; hf < 2; hf++) {
        if (hf == 1) {
            asm volatile("cp.async.wait_group 0;");
            __syncthreads();
        }
#pragma unroll
        for (int ks2 = 0; ks2 < 8; ks2++) {
            const int ks = hf * 16 + ks2 * 2;
            uint32_t bw4[4];
            LDSM4T(bw4[0], bw4[1], bw4[2], bw4[3],
                   base + ASWZ(ks * 16 + lane, warp));
#pragma unroll
            for (int k2 = 0; k2 < 2; k2++) {
                uint32_t af[2][4];
#pragma unroll
                for (int mi = 0; mi < 2; mi++)
                    LDSM4(af[mi][0], af[mi][1], af[mi][2], af[mi][3],
                          pbase + PSWZ(mi * 16 + arow, (ks + k2) * 2 + achk));
#pragma unroll
                for (int mi = 0; mi < 2; mi++)
                    MMA_F16(oacc[mi], af[mi], (bw4 + 2 * k2));
            }
        }
    }

    // epilogue: write att16 (concat layout)
#pragma unroll
    for (int mi = 0; mi < 2; mi++) {
#pragma unroll
        for (int h2 = 0; h2 < 2; h2++) {
            int row = m0 + mi * 16 + qr + h2 * 8;
            int col = h * THD + warp * 8 + qc * 2;
            *reinterpret_cast<__half2*>(att16 + ((size_t)b * TS + row) * TE + col) =
                __floats2half2_rn(oacc[mi][2 * h2 + 0], oacc[mi][2 * h2 + 1]);
        }
    }
}

// ---------------------------------------------------------------------------
// Fused residual + LayerNorm, fp16 residual stream:
// x16 = fp16(LN(x16 + y16) * g + b). 1 block/token, 128 thr. fp32 sums.
// ---------------------------------------------------------------------------
__global__ __launch_bounds__(128) void add_ln_kernel(
    __half* __restrict__ x16, const __half* __restrict__ y16,
    const float* __restrict__ g, const float* __restrict__ bb) {
    const size_t row = blockIdx.x;
    const int t = threadIdx.x;
    const __half2* xp = reinterpret_cast<const __half2*>(x16 + row * TE) + t * 2;
    const __half2* yp = reinterpret_cast<const __half2*>(y16 + row * TE) + t * 2;
    float2 x0 = __half22float2(xp[0]);
    float2 x1 = __half22float2(xp[1]);
    float2 y0 = __half22float2(yp[0]);
    float2 y1 = __half22float2(yp[1]);
    float4 s;
    s.x = x0.x + y0.x; s.y = x0.y + y0.y; s.z = x1.x + y1.x; s.w = x1.y + y1.y;
    float sum = s.x + s.y + s.z + s.w;
    float sq = s.x * s.x + s.y * s.y + s.z * s.z + s.w * s.w;
#pragma unroll
    for (int o = 16; o; o >>= 1) {
        sum += __shfl_xor_sync(0xFFFFFFFFu, sum, o);
        sq  += __shfl_xor_sync(0xFFFFFFFFu, sq, o);
    }
    __shared__ float s1[4], s2[4];
    if ((t & 31) == 0) { s1[t >> 5] = sum; s2[t >> 5] = sq; }
    __syncthreads();
    sum = s1[0] + s1[1] + s1[2] + s1[3];
    sq  = s2[0] + s2[1] + s2[2] + s2[3];
    const float mean = sum * (1.f / TE);
    const float var = sq * (1.f / TE) - mean * mean;
    const float rstd = rsqrtf(var + 1e-5f);
    float4 gv = reinterpret_cast<const float4*>(g)[t];
    float4 bv = reinterpret_cast<const float4*>(bb)[t];
    __half2* hx = reinterpret_cast<__half2*>(x16 + row * TE) + t * 2;
    hx[0] = __floats2half2_rn((s.x - mean) * rstd * gv.x + bv.x,
                              (s.y - mean) * rstd * gv.y + bv.y);
    hx[1] = __floats2half2_rn((s.z - mean) * rstd * gv.z + bv.z,
                              (s.w - mean) * rstd * gv.w + bv.w);
}

// ---------------------------------------------------------------------------
// CLS head: fp16 hidden, fp32 accumulate.
// ---------------------------------------------------------------------------
__global__ void cls_kernel(const __half* __restrict__ x16, const float* __restrict__ w,
                           const float* __restrict__ cb, float* __restrict__ out) {
    int t = threadIdx.x;
    if (t >= TB * 2) return;
    int b = t >> 1, c = t & 1;
    const __half* xr = x16 + (size_t)b * TS * TE;
    const float* wr = w + c * TE;
    float s = cb[c];
    for (int e = 0; e < TE; e++) s = fmaf(__half2float(xr[e]), wr[e], s);
    out[b * 2 + c] = s;
}

// ---------------------------------------------------------------------------
extern "C" void kernel_launch(void* const* d_in, const int* in_sizes, int n_in,
                              void* d_out, int out_size) {
    const int*   ids  = (const int*)d_in[0];
    const int*   mask = (const int*)d_in[1];
    const float* emb  = (const float*)d_in[2];
    const float* pos  = (const float*)d_in[3];
    const float* ipw  = (const float*)d_in[4];
    const float* ipb  = (const float*)d_in[5];
    const float* opw  = (const float*)d_in[6];
    const float* opb  = (const float*)d_in[7];
    const float* l1g  = (const float*)d_in[8];
    const float* l1b  = (const float*)d_in[9];
    const float* l2g  = (const float*)d_in[10];
    const float* l2b  = (const float*)d_in[11];
    const float* f1w  = (const float*)d_in[12];
    const float* f1b  = (const float*)d_in[13];
    const float* f2w  = (const float*)d_in[14];
    const float* f2b  = (const float*)d_in[15];
    const float* cw   = (const float*)d_in[16];
    const float* cb   = (const float*)d_in[17];
    float* out = (float*)d_out;
    float* attn_base = out + TB * 2;

    __half *y16, *qkv16, *x16, *att16, *h16, *w16;
    cudaGetSymbolAddress((void**)&y16,    g_y16);
    cudaGetSymbolAddress((void**)&qkv16,  g_qkv16);
    cudaGetSymbolAddress((void**)&x16,    g_x16);
    cudaGetSymbolAddress((void**)&att16,  g_att16);
    cudaGetSymbolAddress((void**)&h16,    g_h16);
    cudaGetSymbolAddress((void**)&w16,    g_w16);

    cudaFuncSetAttribute(hgemm_kernel<0>, cudaFuncAttributeMaxDynamicSharedMemorySize, HG_SMEM);
    cudaFuncSetAttribute(hgemm_kernel<1>, cudaFuncAttributeMaxDynamicSharedMemorySize, HG_SMEM);
    cudaFuncSetAttribute(attn_fused16_kernel, cudaFuncAttributeMaxDynamicSharedMemorySize, AF_SMEM);

    cvtw_kernel<<<W16_TOTAL / 4 / 256, 256>>>(ipw, opw, f1w, f2w, w16);
    embed_kernel<<<(TT * 128) / 256, 256>>>(ids, emb, pos, x16);

    for (int l = 0; l < TL; l++) {
        hgemm_kernel<0><<<dim3(QKVW / 128, TT / 128), 128, HG_SMEM>>>(
            x16, w16 + W16_IPW(l), ipb + l * QKVW, qkv16, QKVW, TE);

        float* attn_l = attn_base + (size_t)l * TB * TNH * TS * TS;
        attn_fused16_kernel<<<dim3(16, TB * TNH), 256, AF_SMEM>>>(
            qkv16, mask, attn_l, att16);

        hgemm_kernel<0><<<dim3(TE / 128, TT / 128), 128, HG_SMEM>>>(
            att16, w16 + W16_OPW(l), opb + l * TE, y16, TE, TE);
        add_ln_kernel<<<TT, 128>>>(x16, y16, l1g + l * TE, l1b + l * TE);

        hgemm_kernel<1><<<dim3(4 * TE / 128, TT / 128), 128, HG_SMEM>>>(
            x16, w16 + W16_F1W(l), f1b + l * 4 * TE, h16, 4 * TE, TE);
        hgemm_kernel<0><<<dim3(TE / 128, TT / 128), 128, HG_SMEM>>>(
            h16, w16 + W16_F2W(l), f2b + l * TE, y16, TE, 4 * TE);
        add_ln_kernel<<<TT, 128>>>(x16, y16, l2g + l * TE, l2b + l * TE);
    }

    cls_kernel<<<1, 64>>>(x16, cw, cb, out);
}

// round 17
// speedup vs baseline: 2.6583x; 1.0302x over previous
#include <cuda_runtime.h>
#include <cuda_fp16.h>
#include <cstdint>
#include <math.h>

// Problem constants
#define TB 32      // batch
#define TS 512     // seq len
#define TE 512     // d_model
#define THD 64     // head dim
#define TNH 8      // heads
#define TL 3       // layers
#define TT (TB*TS) // tokens = 16384
#define QKVW 1536  // 3*E

// Scratch (device globals; allocation-free contract)
__device__ __half g_y16[(size_t)TT * TE];      // gemm out fp16         16 MB
__device__ __half g_qkv16[(size_t)TT * QKVW];  // qkv fp16              48 MB
__device__ __half g_x16[(size_t)TT * TE];      // hidden fp16 residual  16 MB
__device__ __half g_att16[(size_t)TT * TE];    // attn concat fp16      16 MB
__device__ __half g_h16[(size_t)TT * 4 * TE];  // ffn hidden fp16       64 MB
#define W16_TOTAL 9437184
__device__ __half g_w16[W16_TOTAL];            // all weights fp16      18 MB
#define W16_IPW(l) ((size_t)(l) * 786432)
#define W16_OPW(l) (2359296 + (size_t)(l) * 262144)
#define W16_F1W(l) (3145728 + (size_t)(l) * 1048576)
#define W16_F2W(l) (6291456 + (size_t)(l) * 1048576)

#define MMA_F16(d, a, b)                                                      \
    asm volatile(                                                             \
        "mma.sync.aligned.m16n8k16.row.col.f32.f16.f16.f32 "                  \
        "{%0,%1,%2,%3}, {%4,%5,%6,%7}, {%8,%9}, {%0,%1,%2,%3};"               \
        : "+f"(d[0]), "+f"(d[1]), "+f"(d[2]), "+f"(d[3])                      \
        : "r"(a[0]), "r"(a[1]), "r"(a[2]), "r"(a[3]), "r"(b[0]), "r"(b[1]))

#define LDSM4(r0, r1, r2, r3, addr)                                           \
    asm volatile("ldmatrix.sync.aligned.m8n8.x4.shared.b16 {%0,%1,%2,%3}, [%4];" \
        : "=r"(r0), "=r"(r1), "=r"(r2), "=r"(r3) : "r"(addr))

#define LDSM4T(r0, r1, r2, r3, addr)                                          \
    asm volatile("ldmatrix.sync.aligned.m8n8.x4.trans.shared.b16 {%0,%1,%2,%3}, [%4];" \
        : "=r"(r0), "=r"(r1), "=r"(r2), "=r"(r3) : "r"(addr))

__device__ __forceinline__ void cpa16(uint32_t s, const void* g) {
    asm volatile("cp.async.cg.shared.global [%0], [%1], 16;" :: "r"(s), "l"(g));
}
__device__ __forceinline__ void cpa_commit() {
    asm volatile("cp.async.commit_group;");
}

// fp16 tile swizzles: chunk = 16B unit
// 128B-pitch rows (64 halfs) — used by hgemm tiles and attention tiles
#define ASWZ(row, c8) ((uint32_t)(((row) << 7) | ((((c8) ^ ((row) & 7))) << 4)))
// 1024B-pitch rows (512 halfs) for the P-probability smem tile
#define PSWZ(row, k8) ((uint32_t)(((row) << 10) | \
    (((((k8) & ~7) | (((k8) & 7) ^ ((row) & 7)))) << 4)))

#define NPERSIST 296   // 148 SMs x 2 blocks

// ---------------------------------------------------------------------------
// Weight conversion fp32 -> fp16 (once per launch)
// ---------------------------------------------------------------------------
__global__ __launch_bounds__(256) void cvtw_kernel(
    const float* __restrict__ ipw, const float* __restrict__ opw,
    const float* __restrict__ f1w, const float* __restrict__ f2w,
    __half* __restrict__ w16) {
    size_t i = ((size_t)blockIdx.x * 256 + threadIdx.x) * 4;
    const float* src; size_t off;
    if (i < 2359296)      { src = ipw; off = i; }
    else if (i < 3145728) { src = opw; off = i - 2359296; }
    else if (i < 6291456) { src = f1w; off = i - 3145728; }
    else                  { src = f2w; off = i - 6291456; }
    float4 v = *reinterpret_cast<const float4*>(src + off);
    __half2* dst = reinterpret_cast<__half2*>(w16 + i);
    dst[0] = __floats2half2_rn(v.x, v.y);
    dst[1] = __floats2half2_rn(v.z, v.w);
}

// ---------------------------------------------------------------------------
// Embedding: x16 = fp16(emb[ids] + pos)
// ---------------------------------------------------------------------------
__global__ __launch_bounds__(256) void embed_kernel(
    const int* __restrict__ ids, const float* __restrict__ emb,
    const float* __restrict__ pos, __half* __restrict__ x16) {
    int idx = blockIdx.x * blockDim.x + threadIdx.x;
    int token = idx >> 7;
    int c = idx & 127;
    float4 e = reinterpret_cast<const float4*>(emb)[(size_t)ids[token] * 128 + c];
    float4 p = reinterpret_cast<const float4*>(pos)[(size_t)(token & (TS - 1)) * 128 + c];
    __half2* h = reinterpret_cast<__half2*>(x16) + idx * 2;
    h[0] = __floats2half2_rn(e.x + p.x, e.y + p.y);
    h[1] = __floats2half2_rn(e.z + p.z, e.w + p.w);
}

// ---------------------------------------------------------------------------
// FP16 tensor-core GEMM v4 (persistent): C16 = A @ W^T + bias, opt GELU.
// Grid = NPERSIST blocks; each loops over 128x128 tiles. Per tile: k-tile 64
// (128B ASWZ rows), 3-stage cp.async ring, paired-B LDSM4. M fixed = TT.
// ---------------------------------------------------------------------------
#define HSTG 32768
#define HG_SMEM (3 * HSTG)

template <int ACT>
__global__ __launch_bounds__(128, 2) void hgemm_kernel(
    const __half* __restrict__ A, const __half* __restrict__ W,
    const float* __restrict__ bias, __half* __restrict__ C16, int N, int K) {
    extern __shared__ char smraw[];
    uint32_t base;
    asm("{ .reg .u64 t; cvta.to.shared.u64 t, %1; cvt.u32.u64 %0, t; }"
        : "=r"(base) : "l"(smraw));

    const int t = threadIdx.x;
    const int lane = t & 31;
    const int warp = t >> 5;
    const int wr = (warp >> 1) * 64;
    const int wc = (warp & 1) * 64;
    const int qr = lane >> 2;
    const int qc = lane & 3;

    const int KT = K >> 6;
    const int ntN = N >> 7;
    const int nTiles = (TT >> 7) * ntN;

    const int arow = lane & 15;
    const int achk = lane >> 4;
    const int bn2 = ((lane >> 4) << 3) + (lane & 7);
    const int bch = (lane >> 3) & 1;

    for (int tile = blockIdx.x; tile < nTiles; tile += NPERSIST) {
        const int m0 = (tile / ntN) * 128;
        const int n0 = (tile % ntN) * 128;

        float acc[4][8][4];
#pragma unroll
        for (int i = 0; i < 4; i++)
#pragma unroll
            for (int j = 0; j < 8; j++)
#pragma unroll
                for (int r = 0; r < 4; r++) acc[i][j][r] = 0.f;

        __syncthreads();   // prior tile's fragment reads done before refill
#pragma unroll
        for (int s = 0; s < 2; s++) {
            uint32_t sb = base + s * HSTG;
#pragma unroll
            for (int i = 0; i < 8; i++) {
                int idx = t + 128 * i;
                int row = idx >> 3, c8 = idx & 7;
                cpa16(sb + ASWZ(row, c8), A + (size_t)(m0 + row) * K + s * 64 + c8 * 8);
                cpa16(sb + 16384 + ASWZ(row, c8), W + (size_t)(n0 + row) * K + s * 64 + c8 * 8);
            }
            cpa_commit();
        }

        for (int kt = 0; kt < KT; kt++) {
            if (kt + 1 < KT) asm volatile("cp.async.wait_group 1;");
            else             asm volatile("cp.async.wait_group 0;");
            __syncthreads();

            if (kt + 2 < KT) {
                int j = kt + 2;
                uint32_t sb = base + (j % 3) * HSTG;
#pragma unroll
                for (int i = 0; i < 8; i++) {
                    int idx = t + 128 * i;
                    int row = idx >> 3, c8 = idx & 7;
                    cpa16(sb + ASWZ(row, c8), A + (size_t)(m0 + row) * K + j * 64 + c8 * 8);
                    cpa16(sb + 16384 + ASWZ(row, c8), W + (size_t)(n0 + row) * K + j * 64 + c8 * 8);
                }
                cpa_commit();
            } else {
                cpa_commit();
            }

            const uint32_t sb = base + (kt % 3) * HSTG;
#pragma unroll
            for (int s2 = 0; s2 < 4; s2++) {
                uint32_t a[4][4], bw[8][2];
#pragma unroll
                for (int mi = 0; mi < 4; mi++) {
                    uint32_t ad = sb + ASWZ(wr + mi * 16 + arow, 2 * s2 + achk);
                    LDSM4(a[mi][0], a[mi][1], a[mi][2], a[mi][3], ad);
                }
#pragma unroll
                for (int np = 0; np < 4; np++) {
                    uint32_t bd = sb + 16384 + ASWZ(wc + np * 16 + bn2, 2 * s2 + bch);
                    LDSM4(bw[2 * np][0], bw[2 * np][1],
                          bw[2 * np + 1][0], bw[2 * np + 1][1], bd);
                }
#pragma unroll
                for (int mi = 0; mi < 4; mi++)
#pragma unroll
                    for (int ni = 0; ni < 8; ni++) MMA_F16(acc[mi][ni], a[mi], bw[ni]);
            }
        }

#pragma unroll
        for (int mi = 0; mi < 4; mi++) {
#pragma unroll
            for (int ni = 0; ni < 8; ni++) {
                int col = n0 + wc + ni * 8 + qc * 2;
                float b0 = bias[col], b1 = bias[col + 1];
#pragma unroll
                for (int half = 0; half < 2; half++) {
                    int row = m0 + wr + mi * 16 + qr + half * 8;
                    float v0 = acc[mi][ni][half * 2 + 0] + b0;
                    float v1 = acc[mi][ni][half * 2 + 1] + b1;
                    if (ACT == 1) {
                        v0 = 0.5f * v0 * (1.f + erff(v0 * 0.70710678118654752f));
                        v1 = 0.5f * v1 * (1.f + erff(v1 * 0.70710678118654752f));
                    }
                    *reinterpret_cast<__half2*>(C16 + (size_t)row * N + col) =
                        __floats2half2_rn(v0, v1);
                }
            }
        }
    }
}

// ---------------------------------------------------------------------------
// Fully fused attention v2 (proven round-12): scores + softmax + AV,
// K/V fully smem-resident. Block: 32 q-rows x 512 keys for one (b,h).
// ---------------------------------------------------------------------------
#define AF_SMEM 101504

__global__ __launch_bounds__(256, 2) void attn_fused16_kernel(
    const __half* __restrict__ qkv16, const int* __restrict__ mask,
    float* __restrict__ attn, __half* __restrict__ att16) {
    extern __shared__ char smraw[];
    uint32_t base;
    asm("{ .reg .u64 t; cvta.to.shared.u64 t, %1; cvt.u32.u64 %0, t; }"
        : "=r"(base) : "l"(smraw));
    const uint32_t pbase = base + 65536;          // Q (phase 1) then P
    float* biasS = reinterpret_cast<float*>(smraw + 98304);
    float* red   = reinterpret_cast<float*>(smraw + 100352);

    const int t = threadIdx.x, lane = t & 31, warp = t >> 5;
    const int qr = lane >> 2, qc = lane & 3;
    const int bh = blockIdx.y, b = bh >> 3, h = bh & 7;
    const int m0 = blockIdx.x * 32;
    const __half* qb = qkv16 + (size_t)b * TS * QKVW + h * THD;
    const __half* kb = qb + TE;
    const __half* vb = qb + 2 * TE;

    for (int i = t; i < 512; i += 256)
        biasS[i] = (mask[b * TS + i] == 0) ? -1e30f : 0.f;

    // prologue: Q + K keys 0..255 -> group A; K keys 256..511 -> group B
    {
        int row = t >> 3, c8 = t & 7;
        cpa16(pbase + ASWZ(row, c8), qb + (size_t)(m0 + row) * QKVW + c8 * 8);
#pragma unroll
        for (int i = 0; i < 8; i++) {
            int u = t + 256 * i;
            int kr = u >> 3, kc = u & 7;
            cpa16(base + ASWZ(kr, kc), kb + (size_t)kr * QKVW + kc * 8);
        }
    }
    cpa_commit();
#pragma unroll
    for (int i = 0; i < 8; i++) {
        int u = t + 256 * i;
        int kr = 256 + (u >> 3), kc = u & 7;
        cpa16(base + ASWZ(kr, kc), kb + (size_t)kr * QKVW + kc * 8);
    }
    cpa_commit();

    float acc[8][2][4];
#pragma unroll
    for (int c = 0; c < 8; c++)
#pragma unroll
        for (int mi = 0; mi < 2; mi++)
#pragma unroll
            for (int r = 0; r < 4; r++) acc[c][mi][r] = 0.f;

    const int arow = lane & 15, achk = lane >> 4;
    const int kchk_off = lane >> 4;
    const int kk_half  = (lane >> 3) & 1;
    const int krow8    = lane & 7;

    // ---- Phase 1: QK^T (s-outer, chunk-inner) ----
    asm volatile("cp.async.wait_group 1;");
    __syncthreads();
#pragma unroll
    for (int hf = 0; hf < 2; hf++) {
        if (hf == 1) {
            asm volatile("cp.async.wait_group 0;");
            __syncthreads();
        }
#pragma unroll
        for (int s = 0; s < 4; s++) {
            uint32_t qf[2][4];
#pragma unroll
            for (int mi = 0; mi < 2; mi++)
                LDSM4(qf[mi][0], qf[mi][1], qf[mi][2], qf[mi][3],
                      pbase + ASWZ(mi * 16 + arow, 2 * s + achk));
#pragma unroll
            for (int cc = 0; cc < 2; cc++) {
                const int c = hf * 4 + cc * 2;
                uint32_t k4[4];
                LDSM4(k4[0], k4[1], k4[2], k4[3],
                      base + ASWZ((c + kchk_off) * 64 + warp * 8 + krow8,
                                  2 * s + kk_half));
#pragma unroll
                for (int mi = 0; mi < 2; mi++) {
                    MMA_F16(acc[c][mi], qf[mi], (k4 + 0));
                    MMA_F16(acc[c + 1][mi], qf[mi], (k4 + 2));
                }
            }
        }
    }
    __syncthreads();   // all K reads done; V may overwrite

    // Issue V loads (overlap with softmax)
#pragma unroll
    for (int i = 0; i < 8; i++) {
        int u = t + 256 * i;
        int vr = u >> 3, vc = u & 7;
        cpa16(base + ASWZ(vr, vc), vb + (size_t)vr * QKVW + vc * 8);
    }
    cpa_commit();
#pragma unroll
    for (int i = 0; i < 8; i++) {
        int u = t + 256 * i;
        int vr = 256 + (u >> 3), vc = u & 7;
        cpa16(base + ASWZ(vr, vc), vb + (size_t)vr * QKVW + vc * 8);
    }
    cpa_commit();

    // ---- softmax over 512 keys per row (32 rows) ----
    float bm[2][2], bs[2][2];
    const float scale = 0.125f;
#pragma unroll
    for (int mi = 0; mi < 2; mi++) {
#pragma unroll
        for (int h2 = 0; h2 < 2; h2++) {
            float m = -3.4e38f;
#pragma unroll
            for (int c = 0; c < 8; c++) {
                int col = c * 64 + warp * 8 + qc * 2;
                float v0 = acc[c][mi][2 * h2 + 0] * scale + biasS[col];
                float v1 = acc[c][mi][2 * h2 + 1] * scale + biasS[col + 1];
                acc[c][mi][2 * h2 + 0] = v0;
                acc[c][mi][2 * h2 + 1] = v1;
                m = fmaxf(m, fmaxf(v0, v1));
            }
            m = fmaxf(m, __shfl_xor_sync(0xFFFFFFFFu, m, 1));
            m = fmaxf(m, __shfl_xor_sync(0xFFFFFFFFu, m, 2));
            bm[mi][h2] = m;
        }
    }
    if (qc == 0) {
#pragma unroll
        for (int mi = 0; mi < 2; mi++)
#pragma unroll
            for (int h2 = 0; h2 < 2; h2++)
                red[(mi * 16 + qr + h2 * 8) * 9 + warp] = bm[mi][h2];
    }
    __syncthreads();
#pragma unroll
    for (int mi = 0; mi < 2; mi++)
#pragma unroll
        for (int h2 = 0; h2 < 2; h2++) {
            int row = mi * 16 + qr + h2 * 8;
            float m = red[row * 9 + 0];
#pragma unroll
            for (int w2 = 1; w2 < 8; w2++) m = fmaxf(m, red[row * 9 + w2]);
            bm[mi][h2] = m;
        }
    __syncthreads();
#pragma unroll
    for (int mi = 0; mi < 2; mi++) {
#pragma unroll
        for (int h2 = 0; h2 < 2; h2++) {
            float m = bm[mi][h2];
            float s = 0.f;
#pragma unroll
            for (int c = 0; c < 8; c++) {
                float e0 = __expf(acc[c][mi][2 * h2 + 0] - m);
                float e1 = __expf(acc[c][mi][2 * h2 + 1] - m);
                acc[c][mi][2 * h2 + 0] = e0;
                acc[c][mi][2 * h2 + 1] = e1;
                s += e0 + e1;
            }
            s += __shfl_xor_sync(0xFFFFFFFFu, s, 1);
            s += __shfl_xor_sync(0xFFFFFFFFu, s, 2);
            bs[mi][h2] = s;
        }
    }
    if (qc == 0) {
#pragma unroll
        for (int mi = 0; mi < 2; mi++)
#pragma unroll
            for (int h2 = 0; h2 < 2; h2++)
                red[(mi * 16 + qr + h2 * 8) * 9 + warp] = bs[mi][h2];
    }
    __syncthreads();
    // normalize; write fp32 probs (streaming) + fp16 P into SMEM
#pragma unroll
    for (int mi = 0; mi < 2; mi++)
#pragma unroll
        for (int h2 = 0; h2 < 2; h2++) {
            int row = mi * 16 + qr + h2 * 8;
            float s = 0.f;
#pragma unroll
            for (int w2 = 0; w2 < 8; w2++) s += red[row * 9 + w2];
            float inv = 1.f / s;
            float* orow = attn + ((size_t)bh * TS + m0 + row) * TS;
#pragma unroll
            for (int c = 0; c < 8; c++) {
                int col = c * 64 + warp * 8 + qc * 2;
                float2 o;
                o.x = acc[c][mi][2 * h2 + 0] * inv;
                o.y = acc[c][mi][2 * h2 + 1] * inv;
                __stcs(reinterpret_cast<float2*>(orow + col), o);
                __half2 hv = __floats2half2_rn(o.x, o.y);
                uint32_t u = *reinterpret_cast<uint32_t*>(&hv);
                asm volatile("st.shared.b32 [%0], %1;"
                             :: "r"(pbase + PSWZ(row, c * 8 + warp) + qc * 4), "r"(u)
                             : "memory");
            }
        }

    // ---- Phase 2: O = P @ V; warp w owns head dims [w*8, w*8+8) ----
    float oacc[2][4];
#pragma unroll
    for (int mi = 0; mi < 2; mi++)
#pragma unroll
        for (int r = 0; r < 4; r++) oacc[mi][r] = 0.f;

    asm volatile("cp.async.wait_group 1;");
    __syncthreads();   // V keys 0..255 + all P stores visible
#pragma unroll
    for (int hf = 0; hf < 2; hf++) {
        if (hf == 1) {
            asm volatile("cp.async.wait_group 0;");
            __syncthreads();
        }
#pragma unroll
        for (int ks2 = 0; ks2 < 8; ks2++) {
            const int ks = hf * 16 + ks2 * 2;
            uint32_t bw4[4];
            LDSM4T(bw4[0], bw4[1], bw4[2], bw4[3],
                   base + ASWZ(ks * 16 + lane, warp));
#pragma unroll
            for (int k2 = 0; k2 < 2; k2++) {
                uint32_t af[2][4];
#pragma unroll
                for (int mi = 0; mi < 2; mi++)
                    LDSM4(af[mi][0], af[mi][1], af[mi][2], af[mi][3],
                          pbase + PSWZ(mi * 16 + arow, (ks + k2) * 2 + achk));
#pragma unroll
                for (int mi = 0; mi < 2; mi++)
                    MMA_F16(oacc[mi], af[mi], (bw4 + 2 * k2));
            }
        }
    }

    // epilogue: write att16 (concat layout)
#pragma unroll
    for (int mi = 0; mi < 2; mi++) {
#pragma unroll
        for (int h2 = 0; h2 < 2; h2++) {
            int row = m0 + mi * 16 + qr + h2 * 8;
            int col = h * THD + warp * 8 + qc * 2;
            *reinterpret_cast<__half2*>(att16 + ((size_t)b * TS + row) * TE + col) =
                __floats2half2_rn(oacc[mi][2 * h2 + 0], oacc[mi][2 * h2 + 1]);
        }
    }
}

// ---------------------------------------------------------------------------
// Fused residual + LayerNorm, fp16 residual stream:
// x16 = fp16(LN(x16 + y16) * g + b). 1 block/token, 128 thr. fp32 sums.
// ---------------------------------------------------------------------------
__global__ __launch_bounds__(128) void add_ln_kernel(
    __half* __restrict__ x16, const __half* __restrict__ y16,
    const float* __restrict__ g, const float* __restrict__ bb) {
    const size_t row = blockIdx.x;
    const int t = threadIdx.x;
    const __half2* xp = reinterpret_cast<const __half2*>(x16 + row * TE) + t * 2;
    const __half2* yp = reinterpret_cast<const __half2*>(y16 + row * TE) + t * 2;
    float2 x0 = __half22float2(xp[0]);
    float2 x1 = __half22float2(xp[1]);
    float2 y0 = __half22float2(yp[0]);
    float2 y1 = __half22float2(yp[1]);
    float4 s;
    s.x = x0.x + y0.x; s.y = x0.y + y0.y; s.z = x1.x + y1.x; s.w = x1.y + y1.y;
    float sum = s.x + s.y + s.z + s.w;
    float sq = s.x * s.x + s.y * s.y + s.z * s.z + s.w * s.w;
#pragma unroll
    for (int o = 16; o; o >>= 1) {
        sum += __shfl_xor_sync(0xFFFFFFFFu, sum, o);
        sq  += __shfl_xor_sync(0xFFFFFFFFu, sq, o);
    }
    __shared__ float s1[4], s2[4];
    if ((t & 31) == 0) { s1[t >> 5] = sum; s2[t >> 5] = sq; }
    __syncthreads();
    sum = s1[0] + s1[1] + s1[2] + s1[3];
    sq  = s2[0] + s2[1] + s2[2] + s2[3];
    const float mean = sum * (1.f / TE);
    const float var = sq * (1.f / TE) - mean * mean;
    const float rstd = rsqrtf(var + 1e-5f);
    float4 gv = reinterpret_cast<const float4*>(g)[t];
    float4 bv = reinterpret_cast<const float4*>(bb)[t];
    __half2* hx = reinterpret_cast<__half2*>(x16 + row * TE) + t * 2;
    hx[0] = __floats2half2_rn((s.x - mean) * rstd * gv.x + bv.x,
                              (s.y - mean) * rstd * gv.y + bv.y);
    hx[1] = __floats2half2_rn((s.z - mean) * rstd * gv.z + bv.z,
                              (s.w - mean) * rstd * gv.w + bv.w);
}

// ---------------------------------------------------------------------------
// CLS head: fp16 hidden, fp32 accumulate.
// ---------------------------------------------------------------------------
__global__ void cls_kernel(const __half* __restrict__ x16, const float* __restrict__ w,
                           const float* __restrict__ cb, float* __restrict__ out) {
    int t = threadIdx.x;
    if (t >= TB * 2) return;
    int b = t >> 1, c = t & 1;
    const __half* xr = x16 + (size_t)b * TS * TE;
    const float* wr = w + c * TE;
    float s = cb[c];
    for (int e = 0; e < TE; e++) s = fmaf(__half2float(xr[e]), wr[e], s);
    out[b * 2 + c] = s;
}

// ---------------------------------------------------------------------------
extern "C" void kernel_launch(void* const* d_in, const int* in_sizes, int n_in,
                              void* d_out, int out_size) {
    const int*   ids  = (const int*)d_in[0];
    const int*   mask = (const int*)d_in[1];
    const float* emb  = (const float*)d_in[2];
    const float* pos  = (const float*)d_in[3];
    const float* ipw  = (const float*)d_in[4];
    const float* ipb  = (const float*)d_in[5];
    const float* opw  = (const float*)d_in[6];
    const float* opb  = (const float*)d_in[7];
    const float* l1g  = (const float*)d_in[8];
    const float* l1b  = (const float*)d_in[9];
    const float* l2g  = (const float*)d_in[10];
    const float* l2b  = (const float*)d_in[11];
    const float* f1w  = (const float*)d_in[12];
    const float* f1b  = (const float*)d_in[13];
    const float* f2w  = (const float*)d_in[14];
    const float* f2b  = (const float*)d_in[15];
    const float* cw   = (const float*)d_in[16];
    const float* cb   = (const float*)d_in[17];
    float* out = (float*)d_out;
    float* attn_base = out + TB * 2;

    __half *y16, *qkv16, *x16, *att16, *h16, *w16;
    cudaGetSymbolAddress((void**)&y16,    g_y16);
    cudaGetSymbolAddress((void**)&qkv16,  g_qkv16);
    cudaGetSymbolAddress((void**)&x16,    g_x16);
    cudaGetSymbolAddress((void**)&att16,  g_att16);
    cudaGetSymbolAddress((void**)&h16,    g_h16);
    cudaGetSymbolAddress((void**)&w16,    g_w16);

    cudaFuncSetAttribute(hgemm_kernel<0>, cudaFuncAttributeMaxDynamicSharedMemorySize, HG_SMEM);
    cudaFuncSetAttribute(hgemm_kernel<1>, cudaFuncAttributeMaxDynamicSharedMemorySize, HG_SMEM);
    cudaFuncSetAttribute(attn_fused16_kernel, cudaFuncAttributeMaxDynamicSharedMemorySize, AF_SMEM);

    cvtw_kernel<<<W16_TOTAL / 4 / 256, 256>>>(ipw, opw, f1w, f2w, w16);
    embed_kernel<<<(TT * 128) / 256, 256>>>(ids, emb, pos, x16);

    for (int l = 0; l < TL; l++) {
        hgemm_kernel<0><<<NPERSIST, 128, HG_SMEM>>>(
            x16, w16 + W16_IPW(l), ipb + l * QKVW, qkv16, QKVW, TE);

        float* attn_l = attn_base + (size_t)l * TB * TNH * TS * TS;
        attn_fused16_kernel<<<dim3(16, TB * TNH), 256, AF_SMEM>>>(
            qkv16, mask, attn_l, att16);

        hgemm_kernel<0><<<NPERSIST, 128, HG_SMEM>>>(
            att16, w16 + W16_OPW(l), opb + l * TE, y16, TE, TE);
        add_ln_kernel<<<TT, 128>>>(x16, y16, l1g + l * TE, l1b + l * TE);

        hgemm_kernel<1><<<NPERSIST, 128, HG_SMEM>>>(
            x16, w16 + W16_F1W(l), f1b + l * 4 * TE, h16, 4 * TE, TE);
        hgemm_kernel<0><<<NPERSIST, 128, HG_SMEM>>>(
            h16, w16 + W16_F2W(l), f2b + l * TE, y16, TE, 4 * TE);
        add_ln_kernel<<<TT, 128>>>(x16, y16, l2g + l * TE, l2b + l * TE);
    }

    cls_kernel<<<1, 64>>>(x16, cw, cb, out);
}